// round 4
// baseline (speedup 1.0000x reference)
#include <cuda_runtime.h>
#include <math_constants.h>
#include <stdint.h>

#define BATCH 4
#define NPIX 4096   // 64*64

typedef unsigned long long ull;

// ---------------- scratch (device globals; no cudaMalloc allowed) ----------------
__device__ float g_pool[BATCH * 128 * NPIX];
__device__ float g_buf1[BATCH * 256 * NPIX];
__device__ float g_buf2[BATCH * 256 * NPIX];
__device__ float g_br  [4 * BATCH * 64 * NPIX];
__device__ float g_q   [4 * BATCH * 64 * NPIX];
__device__ float g_k   [4 * BATCH * 64 * NPIX];
__device__ float g_v   [4 * BATCH * 64 * NPIX];
__device__ float g_pos [64 * NPIX];
__device__ float g_p1  [256 * 256];      // per-(slot,channel) partial sums
__device__ float g_p2  [256 * 256];      // per-(slot,channel) partial sumsq
__device__ float g_An  [6 * 256];        // BN folded scale  (y = A*v + B)
__device__ float g_Bn  [6 * 256];        // BN folded shift

// ---------------- packed f32x2 helpers ----------------
__device__ __forceinline__ ull pk2(float v) {
    ull r; uint32_t u = __float_as_uint(v);
    asm("mov.b64 %0, {%1,%2};" : "=l"(r) : "r"(u), "r"(u));
    return r;
}
__device__ __forceinline__ void fma2(ull& d, ull a, ull b) {
    asm("fma.rn.f32x2 %0, %1, %2, %0;" : "+l"(d) : "l"(a), "l"(b));
}
__device__ __forceinline__ float lo2(ull v) { return __uint_as_float((uint32_t)v); }
__device__ __forceinline__ float hi2(ull v) { return __uint_as_float((uint32_t)(v >> 32)); }

__device__ __forceinline__ uint32_t f2tf32(float f) {
    uint32_t u;
    asm("cvt.rna.tf32.f32 %0, %1;" : "=r"(u) : "f"(f));
    return u;
}
__device__ __forceinline__ void mma8(float d[4], const uint32_t a[4],
                                     uint32_t b0, uint32_t b1) {
    asm volatile(
        "mma.sync.aligned.m16n8k8.row.col.f32.tf32.tf32.f32 "
        "{%0,%1,%2,%3},{%4,%5,%6,%7},{%8,%9},{%0,%1,%2,%3};"
        : "+f"(d[0]), "+f"(d[1]), "+f"(d[2]), "+f"(d[3])
        : "r"(a[0]), "r"(a[1]), "r"(a[2]), "r"(a[3]), "r"(b0), "r"(b1));
}
__device__ __forceinline__ int ilv(int klo) { return (klo & 3) * 2 + (klo >> 2); }

// ---------------- maxpool 2x2 ----------------
__global__ void maxpool_kernel(const float* __restrict__ x, float* __restrict__ out) {
    int idx = blockIdx.x * blockDim.x + threadIdx.x;
    if (idx >= BATCH * 128 * NPIX) return;
    int p  = idx & (NPIX - 1);
    int bc = idx >> 12;
    int y = p >> 6, xx = p & 63;
    const float* src = x + ((long)bc * 128 + 2 * y) * 128 + 2 * xx;
    out[idx] = fmaxf(fmaxf(src[0], src[1]), fmaxf(src[128], src[129]));
}

// ======== scalar-packed (f32x2) 3x3 dilated conv, pad = dil, no bias ========
// grid (64 y, Cout/64, batch), block 128. thread: 8 oc (4 pairs) x 4 px.
// Input BN (A,B) applied + ReLU on load when Abn != null.
// Emits deterministic per-CTA BN partials (sum, sumsq) when p1 != null.
#define HALO 12
__global__ void __launch_bounds__(128) conv3x3_f2_kernel(
    const float* __restrict__ in, const float* __restrict__ w,
    float* __restrict__ out, int Cin, int dil,
    const float* __restrict__ Abn, const float* __restrict__ Bbn,
    float* __restrict__ p1, float* __restrict__ p2)
{
    const int y   = blockIdx.x;
    const int ocg = blockIdx.y;
    const int b   = blockIdx.z;
    const int Cout = gridDim.y * 64;
    in  += (long)b * Cin  * NPIX;
    out += (long)b * Cout * NPIX;

    const int t = threadIdx.x, tpx = t & 15, tlo = t >> 4;
    const int px0 = tpx * 4;

    __shared__ float sIn[8 * 3 * 88];   // [ic][ky][HALO + 64 + halo], zero borders
    __shared__ float sW [72 * 64];      // [kk][oc]

    // zero halos once (staging only writes interior)
    for (int i = t; i < 8 * 3 * 88; i += 128) sIn[i] = 0.f;

    ull acc[4][4];
#pragma unroll
    for (int o2 = 0; o2 < 4; o2++)
#pragma unroll
        for (int p = 0; p < 4; p++) acc[o2][p] = 0ull;

    for (int ic0 = 0; ic0 < Cin; ic0 += 8) {
        __syncthreads();
        // stage input rows (with optional BN+ReLU on load)
        for (int i = t; i < 1536; i += 128) {
            int ic  = i / 192;
            int rem = i - ic * 192;
            int ky  = rem >> 6, xx = rem & 63;
            int ry  = y + (ky - 1) * dil;
            float v = 0.f;
            if (ry >= 0 && ry < 64) {
                v = in[(ic0 + ic) * NPIX + ry * 64 + xx];
                if (Abn) {
                    int c = ic0 + ic;
                    v = fmaxf(v * Abn[c] + Bbn[c], 0.f);
                }
            }
            sIn[(ic * 3 + ky) * 88 + HALO + xx] = v;
        }
        // stage weights [kk 72][oc 64]
        for (int i = t; i < 4608; i += 128) {
            int oc = i & 63, kk = i >> 6;
            sW[kk * 64 + oc] = w[((long)(ocg * 64 + oc) * Cin + ic0) * 9 + kk];
        }
        __syncthreads();

#pragma unroll 1
        for (int ic = 0; ic < 8; ic++) {
#pragma unroll
            for (int ky = 0; ky < 3; ky++) {
                const float* base = sIn + (ic * 3 + ky) * 88 + HALO + px0;
#pragma unroll
                for (int kx = 0; kx < 3; kx++) {
                    int off = (kx - 1) * dil;
                    ull b0 = pk2(base[off]);
                    ull b1 = pk2(base[off + 1]);
                    ull b2 = pk2(base[off + 2]);
                    ull b3 = pk2(base[off + 3]);
                    const ull* wp = (const ull*)(sW + (ic * 9 + ky * 3 + kx) * 64 + tlo * 8);
#pragma unroll
                    for (int o2 = 0; o2 < 4; o2++) {
                        ull wv = wp[o2];
                        fma2(acc[o2][0], wv, b0);
                        fma2(acc[o2][1], wv, b1);
                        fma2(acc[o2][2], wv, b2);
                        fma2(acc[o2][3], wv, b3);
                    }
                }
            }
        }
    }

    // ---- epilogue: store + BN partials ----
    float sums[8], sqs[8];
#pragma unroll
    for (int o = 0; o < 8; o++) { sums[o] = 0.f; sqs[o] = 0.f; }
#pragma unroll
    for (int o2 = 0; o2 < 4; o2++) {
        int oce = ocg * 64 + tlo * 8 + 2 * o2;
        float* ope = out + (long)oce * NPIX + y * 64 + px0;
        float* opo = ope + NPIX;
#pragma unroll
        for (int p = 0; p < 4; p++) {
            float vl = lo2(acc[o2][p]), vh = hi2(acc[o2][p]);
            ope[p] = vl; opo[p] = vh;
            sums[2 * o2]     += vl; sqs[2 * o2]     += vl * vl;
            sums[2 * o2 + 1] += vh; sqs[2 * o2 + 1] += vh * vh;
        }
    }
    if (p1) {
#pragma unroll
        for (int o = 0; o < 8; o++) {
            float a = sums[o], q = sqs[o];
#pragma unroll
            for (int off = 1; off < 16; off <<= 1) {
                a += __shfl_xor_sync(0xffffffffu, a, off);
                q += __shfl_xor_sync(0xffffffffu, q, off);
            }
            if (tpx == 0) {
                int c = ocg * 64 + tlo * 8 + o;
                int slot = b * 64 + y;
                p1[slot * Cout + c] = a;
                p2[slot * Cout + c] = q;
            }
        }
    }
}

// ---------------- BN finalize: partials -> (A = g*istd, B = be - mean*A) ----------------
__global__ void finalize_kernel(const float* __restrict__ p1, const float* __restrict__ p2,
                                const float* __restrict__ g, const float* __restrict__ be,
                                float* __restrict__ A, float* __restrict__ B, int C) {
    const int c = blockIdx.x, t = threadIdx.x;   // block 128
    float s = 0.f, q = 0.f;
    for (int slot = t; slot < 256; slot += 128) {
        s += p1[slot * C + c];
        q += p2[slot * C + c];
    }
    __shared__ float rs[4], rq[4];
#pragma unroll
    for (int off = 16; off; off >>= 1) {
        s += __shfl_down_sync(0xffffffffu, s, off);
        q += __shfl_down_sync(0xffffffffu, q, off);
    }
    int lane = t & 31, wp = t >> 5;
    if (!lane) { rs[wp] = s; rq[wp] = q; }
    __syncthreads();
    if (t == 0) {
        s = rs[0] + rs[1] + rs[2] + rs[3];
        q = rq[0] + rq[1] + rq[2] + rq[3];
        const float inv = 1.f / (float)(BATCH * NPIX);
        float mean = s * inv;
        float var  = q * inv - mean * mean;
        float a = g[c] * rsqrtf(var + 1e-5f);
        A[c] = a;
        B[c] = be[c] - mean * a;
    }
}

// ---------------- 1x1 conv Cout=64 with input-BN + stats (aspp1 branch) ----------------
__global__ void __launch_bounds__(256) conv1x1_bn_kernel(
    const float* __restrict__ in, const float* __restrict__ w,
    float* __restrict__ out, int Cin,
    const float* __restrict__ Abn, const float* __restrict__ Bbn,
    float* __restrict__ p1, float* __restrict__ p2)
{
    const int p0 = blockIdx.x * 64;
    const int b  = blockIdx.z;
    in  += (long)b * Cin * NPIX;
    out += (long)b * 64  * NPIX;
    const int t = threadIdx.x, tx = t & 15, ty = t >> 4;

    __shared__ float sW [16 * 68];
    __shared__ float sIn[16 * 64];

    float acc[4][4];
#pragma unroll
    for (int r = 0; r < 4; r++)
#pragma unroll
        for (int c = 0; c < 4; c++) acc[r][c] = 0.f;

    for (int ic0 = 0; ic0 < Cin; ic0 += 16) {
        __syncthreads();
        for (int idx = t; idx < 1024; idx += 256) {
            int ic = idx & 15, oc = idx >> 4;
            sW[ic * 68 + oc] = w[(long)oc * Cin + ic0 + ic];
        }
        for (int idx = t; idx < 1024; idx += 256) {
            int ic = idx >> 6, px = idx & 63;
            int c = ic0 + ic;
            float v = in[c * NPIX + p0 + px];
            sIn[idx] = fmaxf(v * Abn[c] + Bbn[c], 0.f);
        }
        __syncthreads();
#pragma unroll
        for (int ic = 0; ic < 16; ic++) {
            float4 a  = *(const float4*)(sW  + ic * 68 + ty * 4);
            float4 xv = *(const float4*)(sIn + ic * 64 + tx * 4);
            float av[4] = {a.x, a.y, a.z, a.w};
            float xa[4] = {xv.x, xv.y, xv.z, xv.w};
#pragma unroll
            for (int r = 0; r < 4; r++)
#pragma unroll
                for (int c = 0; c < 4; c++) acc[r][c] += av[r] * xa[c];
        }
    }
    float sums[4], sqs[4];
#pragma unroll
    for (int r = 0; r < 4; r++) {
        float s = 0.f, q = 0.f;
        float* op = out + (long)(ty * 4 + r) * NPIX + p0 + tx * 4;
#pragma unroll
        for (int c = 0; c < 4; c++) {
            float v = acc[r][c];
            op[c] = v; s += v; q += v * v;
        }
        sums[r] = s; sqs[r] = q;
    }
#pragma unroll
    for (int r = 0; r < 4; r++) {
        float a = sums[r], q = sqs[r];
#pragma unroll
        for (int off = 1; off < 16; off <<= 1) {
            a += __shfl_xor_sync(0xffffffffu, a, off);
            q += __shfl_xor_sync(0xffffffffu, q, off);
        }
        if (tx == 0) {
            int c = ty * 4 + r;
            int slot = b * 64 + blockIdx.x;
            p1[slot * 64 + c] = a;
            p2[slot * 64 + c] = q;
        }
    }
}

// ---------------- fused q/k/v 1x1 projections (input = raw branch + branch BN) ----------------
__global__ void __launch_bounds__(256) qkv_kernel(
    const float* __restrict__ brin,
    const float* __restrict__ wq, const float* __restrict__ bq,
    const float* __restrict__ wk, const float* __restrict__ bk,
    const float* __restrict__ wv, const float* __restrict__ bv,
    float* __restrict__ qo, float* __restrict__ ko, float* __restrict__ vo,
    const float* __restrict__ Abase, const float* __restrict__ Bbase)
{
    const int p0  = blockIdx.x * 64;
    const int img = blockIdx.z;
    const int br  = img >> 2;
    const long ib = (long)img * 64 * NPIX;
    const float* A  = Abase + (2 + br) * 256;
    const float* Bb = Bbase + (2 + br) * 256;
    const int t = threadIdx.x, tx = t & 15, ty = t >> 4;

    __shared__ float sW [3 * 16 * 64];
    __shared__ float sIn[16 * 64];

    float acc[3][4][4];
#pragma unroll
    for (int m = 0; m < 3; m++)
#pragma unroll
        for (int r = 0; r < 4; r++)
#pragma unroll
            for (int c = 0; c < 4; c++) acc[m][r][c] = 0.f;

    for (int ic0 = 0; ic0 < 64; ic0 += 16) {
        __syncthreads();
        for (int i = t; i < 1024; i += 256) {
            int ic = i >> 6, px = i & 63;
            int c = ic0 + ic;
            float v = brin[ib + (long)c * NPIX + p0 + px];
            sIn[i] = fmaxf(v * A[c] + Bb[c], 0.f);
        }
        for (int i = t; i < 3072; i += 256) {
            int m = i >> 10, r = i & 1023;
            int ic = r & 15, oc = r >> 4;
            const float* wm = (m == 0) ? wq : ((m == 1) ? wk : wv);
            sW[m * 1024 + ic * 64 + oc] = wm[oc * 64 + ic0 + ic];
        }
        __syncthreads();
#pragma unroll
        for (int ic = 0; ic < 16; ic++) {
            float4 xv = *(const float4*)(sIn + ic * 64 + tx * 4);
            float xa[4] = {xv.x, xv.y, xv.z, xv.w};
#pragma unroll
            for (int m = 0; m < 3; m++) {
                float4 a = *(const float4*)(sW + m * 1024 + ic * 64 + ty * 4);
                float av[4] = {a.x, a.y, a.z, a.w};
#pragma unroll
                for (int r = 0; r < 4; r++)
#pragma unroll
                    for (int c = 0; c < 4; c++) acc[m][r][c] += av[r] * xa[c];
            }
        }
    }
    float* outs[3] = {qo, ko, vo};
    const float* bs[3] = {bq, bk, bv};
#pragma unroll
    for (int m = 0; m < 3; m++) {
#pragma unroll
        for (int r = 0; r < 4; r++) {
            float bb = bs[m][ty * 4 + r];
            float* op = outs[m] + ib + (long)(ty * 4 + r) * NPIX + p0 + tx * 4;
            op[0] = acc[m][r][0] + bb; op[1] = acc[m][r][1] + bb;
            op[2] = acc[m][r][2] + bb; op[3] = acc[m][r][3] + bb;
        }
    }
}

// ---------------- pos[d][a*64+b] = rel_h[d][b] + rel_w[d][a] ----------------
__global__ void pos_kernel(const float* __restrict__ rh, const float* __restrict__ rw) {
    int idx = blockIdx.x * blockDim.x + threadIdx.x;
    if (idx >= 64 * NPIX) return;
    int d = idx >> 12, n = idx & 4095, a = n >> 6, bb = n & 63;
    g_pos[idx] = rh[d * 64 + bb] + rw[d * 64 + a];
}

// ================= tf32 tensor-core flash attention (unchanged) =================
#define FLASH2_SMEM ((8192 + 4096 + 8192) * 4)

__global__ void __launch_bounds__(256, 1) flash_mma_kernel(
    const float* __restrict__ qg, const float* __restrict__ kg,
    const float* __restrict__ vg, float* __restrict__ outg)
{
    extern __shared__ uint32_t smu[];
    uint32_t* sK = smu;
    uint32_t* sV = smu + 8192;
    uint32_t* sP = smu + 12288;

    const int i0 = blockIdx.x * 128;
    const int b  = blockIdx.y, br = blockIdx.z;
    const long base = (long)(br * BATCH + b) * 64 * NPIX;
    const float* q = qg + base;
    const float* k = kg + base;
    const float* v = vg + base;
    float* outp = outg + (long)(b * 256 + br * 64) * NPIX;

    const int t = threadIdx.x;
    const int lane = t & 31, w = t >> 5;
    const int g = lane >> 2, tq = lane & 3;

    uint32_t Qf[16][4];
    {
        int i_r = i0 + w * 16 + g;
#pragma unroll
        for (int ks = 0; ks < 16; ks++) {
            int kc = ks * 8 + tq;
            const float* s0 = (kc < 64)     ? (q + kc * NPIX)       : (g_pos + (kc - 64) * NPIX);
            const float* s1 = (kc + 4 < 64) ? (q + (kc + 4) * NPIX) : (g_pos + (kc - 60) * NPIX);
            Qf[ks][0] = f2tf32(s0[i_r]);
            Qf[ks][1] = f2tf32(s0[i_r + 8]);
            Qf[ks][2] = f2tf32(s1[i_r]);
            Qf[ks][3] = f2tf32(s1[i_r + 8]);
        }
    }

    float Oa[8][4];
#pragma unroll
    for (int nt = 0; nt < 8; nt++)
#pragma unroll
        for (int c = 0; c < 4; c++) Oa[nt][c] = 0.f;
    float m0 = -CUDART_INF_F, m1 = -CUDART_INF_F, l0 = 0.f, l1 = 0.f;

    const int p00 = ((2 * tq) & 3) * 2 + (tq >> 1);
    const int p01 = ((2 * tq + 1) & 3) * 2 + ((2 * tq + 1) >> 2);

    for (int j0 = 0; j0 < NPIX; j0 += 64) {
        __syncthreads();
        for (int e = t; e < 8192; e += 256) {
            int klo = e & 7, joff = (e >> 3) & 3;
            int rest = e >> 5;
            int ks = rest & 15, jhi = rest >> 4;
            int j = jhi * 4 + joff;
            int kk = ks * 8 + klo;
            float val = (kk < 64) ? k[kk * NPIX + j0 + j]
                                  : q[(kk - 64) * NPIX + j0 + j];
            sK[ks * 512 + j * 8 + ilv(klo)] = f2tf32(val);
        }
        for (int e = t; e < 4096; e += 256) {
            int jlo = e & 7, doff = (e >> 3) & 3;
            int rest = e >> 5;
            int ksv = rest & 7, dhi = rest >> 3;
            int dd = dhi * 4 + doff;
            int j = ksv * 8 + jlo;
            sV[ksv * 512 + dd * 8 + ilv(jlo)] = f2tf32(v[dd * NPIX + j0 + j]);
        }
        __syncthreads();

        float Sa[8][4];
#pragma unroll
        for (int nt = 0; nt < 8; nt++)
#pragma unroll
            for (int c = 0; c < 4; c++) Sa[nt][c] = 0.f;
#pragma unroll
        for (int ks = 0; ks < 16; ks++) {
#pragma unroll
            for (int nt = 0; nt < 8; nt++) {
                uint2 bb = *(const uint2*)&sK[ks * 512 + (nt * 8 + g) * 8 + 2 * tq];
                mma8(Sa[nt], Qf[ks], bb.x, bb.y);
            }
        }

        float mx0 = -CUDART_INF_F, mx1 = -CUDART_INF_F;
#pragma unroll
        for (int nt = 0; nt < 8; nt++) {
            mx0 = fmaxf(mx0, fmaxf(Sa[nt][0], Sa[nt][1]));
            mx1 = fmaxf(mx1, fmaxf(Sa[nt][2], Sa[nt][3]));
        }
        mx0 = fmaxf(mx0, __shfl_xor_sync(0xffffffffu, mx0, 1));
        mx0 = fmaxf(mx0, __shfl_xor_sync(0xffffffffu, mx0, 2));
        mx1 = fmaxf(mx1, __shfl_xor_sync(0xffffffffu, mx1, 1));
        mx1 = fmaxf(mx1, __shfl_xor_sync(0xffffffffu, mx1, 2));
        float mn0 = fmaxf(m0, mx0), mn1 = fmaxf(m1, mx1);
        float al0 = __expf(m0 - mn0), al1 = __expf(m1 - mn1);

        float su0 = 0.f, su1 = 0.f;
        const int pb = w * 1024 + g * 8;
#pragma unroll
        for (int nt = 0; nt < 8; nt++) {
            float e00 = __expf(Sa[nt][0] - mn0);
            float e01 = __expf(Sa[nt][1] - mn0);
            float e10 = __expf(Sa[nt][2] - mn1);
            float e11 = __expf(Sa[nt][3] - mn1);
            su0 += e00 + e01; su1 += e10 + e11;
            sP[pb + nt * 128 + p00]      = f2tf32(e00);
            sP[pb + nt * 128 + p01]      = f2tf32(e01);
            sP[pb + nt * 128 + 64 + p00] = f2tf32(e10);
            sP[pb + nt * 128 + 64 + p01] = f2tf32(e11);
        }
        su0 += __shfl_xor_sync(0xffffffffu, su0, 1);
        su0 += __shfl_xor_sync(0xffffffffu, su0, 2);
        su1 += __shfl_xor_sync(0xffffffffu, su1, 1);
        su1 += __shfl_xor_sync(0xffffffffu, su1, 2);
        l0 = l0 * al0 + su0; l1 = l1 * al1 + su1;
        m0 = mn0; m1 = mn1;
#pragma unroll
        for (int nt = 0; nt < 8; nt++) {
            Oa[nt][0] *= al0; Oa[nt][1] *= al0;
            Oa[nt][2] *= al1; Oa[nt][3] *= al1;
        }
        __syncwarp();

#pragma unroll
        for (int ks = 0; ks < 8; ks++) {
            const uint32_t* ap = &sP[w * 1024 + ks * 128 + g * 8 + 2 * tq];
            uint2 a02 = *(const uint2*)ap;
            uint2 a13 = *(const uint2*)(ap + 64);
            uint32_t a[4] = {a02.x, a13.x, a02.y, a13.y};
#pragma unroll
            for (int nt = 0; nt < 8; nt++) {
                uint2 bb = *(const uint2*)&sV[ks * 512 + (nt * 8 + g) * 8 + 2 * tq];
                mma8(Oa[nt], a, bb.x, bb.y);
            }
        }
    }

    float inv0 = 1.f / l0, inv1 = 1.f / l1;
    int pix = i0 + w * 16 + g;
#pragma unroll
    for (int nt = 0; nt < 8; nt++) {
        int d0 = nt * 8 + 2 * tq;
        outp[(long)d0 * NPIX + pix]           = Oa[nt][0] * inv0;
        outp[(long)(d0 + 1) * NPIX + pix]     = Oa[nt][1] * inv0;
        outp[(long)d0 * NPIX + pix + 8]       = Oa[nt][2] * inv1;
        outp[(long)(d0 + 1) * NPIX + pix + 8] = Oa[nt][3] * inv1;
    }
}

// ---------------- host orchestration ----------------
extern "C" void kernel_launch(void* const* d_in, const int* in_sizes, int n_in,
                              void* d_out, int out_size) {
    const float* x      = (const float*)d_in[0];
    const float* dc_w1  = (const float*)d_in[1];
    // d_in[2] = dc_b1 : conv bias cancels in train-mode BN
    const float* dc_g1  = (const float*)d_in[3];
    const float* dc_be1 = (const float*)d_in[4];
    const float* dc_w2  = (const float*)d_in[5];
    // d_in[6] = dc_b2 : cancels
    const float* dc_g2  = (const float*)d_in[7];
    const float* dc_be2 = (const float*)d_in[8];
    const float* aw[4]  = {(const float*)d_in[9],  (const float*)d_in[12],
                           (const float*)d_in[15], (const float*)d_in[18]};
    const float* ag[4]  = {(const float*)d_in[10], (const float*)d_in[13],
                           (const float*)d_in[16], (const float*)d_in[19]};
    const float* ab[4]  = {(const float*)d_in[11], (const float*)d_in[14],
                           (const float*)d_in[17], (const float*)d_in[20]};
    const float* wq = (const float*)d_in[21]; const float* bq = (const float*)d_in[22];
    const float* wk = (const float*)d_in[23]; const float* bk = (const float*)d_in[24];
    const float* wv = (const float*)d_in[25]; const float* bv = (const float*)d_in[26];
    const float* rel_h = (const float*)d_in[27];
    const float* rel_w = (const float*)d_in[28];

    float *pool, *buf1, *buf2, *brb, *qb, *kb, *vb, *p1, *p2, *An, *Bn;
    cudaGetSymbolAddress((void**)&pool, g_pool);
    cudaGetSymbolAddress((void**)&buf1, g_buf1);
    cudaGetSymbolAddress((void**)&buf2, g_buf2);
    cudaGetSymbolAddress((void**)&brb,  g_br);
    cudaGetSymbolAddress((void**)&qb,   g_q);
    cudaGetSymbolAddress((void**)&kb,   g_k);
    cudaGetSymbolAddress((void**)&vb,   g_v);
    cudaGetSymbolAddress((void**)&p1,   g_p1);
    cudaGetSymbolAddress((void**)&p2,   g_p2);
    cudaGetSymbolAddress((void**)&An,   g_An);
    cudaGetSymbolAddress((void**)&Bn,   g_Bn);

    const int dils[4] = {1, 3, 6, 9};

    // mpconv: pool -> conv1(+stats) -> fin(0) -> conv2(BN0 on load, +stats) -> fin(1)
    maxpool_kernel<<<(BATCH * 128 * NPIX + 255) / 256, 256>>>(x, pool);
    conv3x3_f2_kernel<<<dim3(64, 4, BATCH), 128>>>(pool, dc_w1, buf1, 128, 1,
                                                   nullptr, nullptr, p1, p2);
    finalize_kernel<<<256, 128>>>(p1, p2, dc_g1, dc_be1, An + 0, Bn + 0, 256);
    conv3x3_f2_kernel<<<dim3(64, 4, BATCH), 128>>>(buf1, dc_w2, buf2, 256, 1,
                                                   An + 0, Bn + 0, p1, p2);
    finalize_kernel<<<256, 128>>>(p1, p2, dc_g2, dc_be2, An + 256, Bn + 256, 256);

    // ASPP branches: conv (BN1 on load, +stats) -> fin(2+i)
    for (int i = 0; i < 4; i++) {
        float* bro = brb + (long)i * BATCH * 64 * NPIX;
        if (dils[i] == 1) {
            conv1x1_bn_kernel<<<dim3(64, 1, BATCH), 256>>>(
                buf2, aw[i], bro, 256, An + 256, Bn + 256, p1, p2);
        } else {
            conv3x3_f2_kernel<<<dim3(64, 1, BATCH), 128>>>(
                buf2, aw[i], bro, 256, dils[i], An + 256, Bn + 256, p1, p2);
        }
        finalize_kernel<<<64, 128>>>(p1, p2, ag[i], ab[i],
                                     An + (2 + i) * 256, Bn + (2 + i) * 256, 64);
    }

    // fused qkv (branch BN on load) + pos
    qkv_kernel<<<dim3(64, 1, 16), 256>>>(brb, wq, bq, wk, bk, wv, bv,
                                         qb, kb, vb, An, Bn);
    pos_kernel<<<(64 * NPIX + 255) / 256, 256>>>(rel_h, rel_w);

    // tensor-core flash attention -> concat output
    cudaFuncSetAttribute((const void*)flash_mma_kernel,
                         cudaFuncAttributeMaxDynamicSharedMemorySize, FLASH2_SMEM);
    flash_mma_kernel<<<dim3(32, BATCH, 4), 256, FLASH2_SMEM>>>(qb, kb, vb, (float*)d_out);
}

// round 5
// speedup vs baseline: 1.0533x; 1.0533x over previous
#include <cuda_runtime.h>
#include <math_constants.h>
#include <stdint.h>

#define BATCH 4
#define NPIX 4096   // 64*64

typedef unsigned long long ull;

// ---------------- scratch (device globals; no cudaMalloc allowed) ----------------
__device__ float g_pool[BATCH * 128 * NPIX];
__device__ float g_buf1[BATCH * 256 * NPIX];
__device__ float g_buf2[BATCH * 256 * NPIX];
__device__ float g_br  [4 * BATCH * 64 * NPIX];
__device__ float g_q   [4 * BATCH * 64 * NPIX];
__device__ float g_k   [4 * BATCH * 64 * NPIX];
__device__ float g_v   [4 * BATCH * 64 * NPIX];
__device__ float g_pos [64 * NPIX];
__device__ float g_p1  [256 * 256];
__device__ float g_p2  [256 * 256];
__device__ float g_An  [6 * 256];
__device__ float g_Bn  [6 * 256];

// ---------------- packed f32x2 helpers ----------------
__device__ __forceinline__ ull pk2(float v) {
    ull r; uint32_t u = __float_as_uint(v);
    asm("mov.b64 %0, {%1,%2};" : "=l"(r) : "r"(u), "r"(u));
    return r;
}
__device__ __forceinline__ void fma2(ull& d, ull a, ull b) {
    asm("fma.rn.f32x2 %0, %1, %2, %0;" : "+l"(d) : "l"(a), "l"(b));
}
__device__ __forceinline__ float lo2(ull v) { return __uint_as_float((uint32_t)v); }
__device__ __forceinline__ float hi2(ull v) { return __uint_as_float((uint32_t)(v >> 32)); }

__device__ __forceinline__ uint32_t f2tf32(float f) {
    uint32_t u;
    asm("cvt.rna.tf32.f32 %0, %1;" : "=r"(u) : "f"(f));
    return u;
}
__device__ __forceinline__ void mma8(float d[4], const uint32_t a[4],
                                     uint32_t b0, uint32_t b1) {
    asm volatile(
        "mma.sync.aligned.m16n8k8.row.col.f32.tf32.tf32.f32 "
        "{%0,%1,%2,%3},{%4,%5,%6,%7},{%8,%9},{%0,%1,%2,%3};"
        : "+f"(d[0]), "+f"(d[1]), "+f"(d[2]), "+f"(d[3])
        : "r"(a[0]), "r"(a[1]), "r"(a[2]), "r"(a[3]), "r"(b0), "r"(b1));
}
__device__ __forceinline__ int ilv(int klo) { return (klo & 3) * 2 + (klo >> 2); }

// ---------------- maxpool 2x2 ----------------
__global__ void maxpool_kernel(const float* __restrict__ x, float* __restrict__ out) {
    int idx = blockIdx.x * blockDim.x + threadIdx.x;
    if (idx >= BATCH * 128 * NPIX) return;
    int p  = idx & (NPIX - 1);
    int bc = idx >> 12;
    int y = p >> 6, xx = p & 63;
    const float* src = x + ((long)bc * 128 + 2 * y) * 128 + 2 * xx;
    out[idx] = fmaxf(fmaxf(src[0], src[1]), fmaxf(src[128], src[129]));
}

// ======== f32x2 3x3 dilated conv (pad = dil), templated, vector LDS ========
// CTA: OCT oc x 64 px (one y row, one image). block = 128 = (64/PX) * (OCT/8).
// thread: 8 oc (4 f32x2 pairs) x PX px. Input BN+ReLU on load if Abn != null.
// Emits per-CTA BN partials (sum, sumsq).
template<int DIL, int OCT, int PX>
__global__ void __launch_bounds__(128) conv3x3_f2_kernel(
    const float* __restrict__ in, const float* __restrict__ w,
    float* __restrict__ out, int Cin,
    const float* __restrict__ Abn, const float* __restrict__ Bbn,
    float* __restrict__ p1, float* __restrict__ p2)
{
    constexpr int NPXT = 64 / PX;
    const int y   = blockIdx.x;
    const int ocg = blockIdx.y;
    const int b   = blockIdx.z;
    const int Cout = gridDim.y * OCT;
    in  += (long)b * Cin  * NPIX;
    out += (long)b * Cout * NPIX;

    const int t = threadIdx.x;
    const int tpx = t % NPXT, tlo = t / NPXT;
    const int px0 = tpx * PX;

    __shared__ float sIn[8 * 3 * 88];   // [ic][ky][12 halo + 64 + 12 halo]
    __shared__ float sW [72 * OCT];     // [kk][oc]

    for (int i = t; i < 8 * 3 * 88; i += 128) sIn[i] = 0.f;

    ull acc[4][PX];
#pragma unroll
    for (int o2 = 0; o2 < 4; o2++)
#pragma unroll
        for (int p = 0; p < PX; p++) acc[o2][p] = 0ull;

    for (int ic0 = 0; ic0 < Cin; ic0 += 8) {
        __syncthreads();
        // ---- stage input rows (BN+ReLU on load when fused) ----
        for (int i = t; i < 1536; i += 128) {
            int ic  = i / 192;
            int rem = i - ic * 192;
            int ky  = rem >> 6, xx = rem & 63;
            int ry  = y + (ky - 1) * DIL;
            float v = 0.f;
            if (ry >= 0 && ry < 64) {
                v = in[(ic0 + ic) * NPIX + ry * 64 + xx];
                if (Abn) {
                    int c = ic0 + ic;
                    v = fmaxf(v * Abn[c] + Bbn[c], 0.f);
                }
            }
            sIn[(ic * 3 + ky) * 88 + 12 + xx] = v;
        }
        // ---- stage weights [kk 72][oc OCT], oc fastest (conflict-free STS) ----
        for (int i = t; i < 72 * OCT; i += 128) {
            int oc = i & (OCT - 1);
            int kk = i / OCT;
            sW[kk * OCT + oc] = w[((long)(ocg * OCT + oc) * Cin + ic0) * 9 + kk];
        }
        __syncthreads();

#pragma unroll 2
        for (int ic = 0; ic < 8; ic++) {
#pragma unroll
            for (int ky = 0; ky < 3; ky++) {
                const float* base = sIn + (ic * 3 + ky) * 88 + 12 + px0;
#pragma unroll
                for (int kx = 0; kx < 3; kx++) {
                    const int off = (kx - 1) * DIL;
                    const int fw  = (((off + 12) >> 2) << 2) - 12;  // floor4
                    const int sh  = off - fw;                        // 0..3
                    const int nw  = (sh + PX + 3) >> 2;
                    float vv[16];
#pragma unroll
                    for (int wi = 0; wi < nw; wi++)
                        *(float4*)(vv + 4 * wi) = *(const float4*)(base + fw + 4 * wi);
                    const ull* wp = (const ull*)(sW + (ic * 9 + ky * 3 + kx) * OCT + tlo * 8);
                    ull wv0 = wp[0], wv1 = wp[1], wv2 = wp[2], wv3 = wp[3];
#pragma unroll
                    for (int p = 0; p < PX; p++) {
                        ull bp = pk2(vv[sh + p]);
                        fma2(acc[0][p], wv0, bp);
                        fma2(acc[1][p], wv1, bp);
                        fma2(acc[2][p], wv2, bp);
                        fma2(acc[3][p], wv3, bp);
                    }
                }
            }
        }
    }

    // ---- epilogue: store + BN partials ----
    float sums[8], sqs[8];
#pragma unroll
    for (int o = 0; o < 8; o++) { sums[o] = 0.f; sqs[o] = 0.f; }
#pragma unroll
    for (int o2 = 0; o2 < 4; o2++) {
        int oce = ocg * OCT + tlo * 8 + 2 * o2;
        float* ope = out + (long)oce * NPIX + y * 64 + px0;
        float* opo = ope + NPIX;
#pragma unroll
        for (int p = 0; p < PX; p++) {
            float vl = lo2(acc[o2][p]), vh = hi2(acc[o2][p]);
            ope[p] = vl; opo[p] = vh;
            sums[2 * o2]     += vl; sqs[2 * o2]     += vl * vl;
            sums[2 * o2 + 1] += vh; sqs[2 * o2 + 1] += vh * vh;
        }
    }
#pragma unroll
    for (int o = 0; o < 8; o++) {
        float a = sums[o], q = sqs[o];
#pragma unroll
        for (int off = 1; off < NPXT; off <<= 1) {
            a += __shfl_xor_sync(0xffffffffu, a, off);
            q += __shfl_xor_sync(0xffffffffu, q, off);
        }
        if (tpx == 0) {
            int c = ocg * OCT + tlo * 8 + o;
            int slot = b * 64 + y;
            p1[slot * Cout + c] = a;
            p2[slot * Cout + c] = q;
        }
    }
}

// ---------------- BN finalize ----------------
__global__ void finalize_kernel(const float* __restrict__ p1, const float* __restrict__ p2,
                                const float* __restrict__ g, const float* __restrict__ be,
                                float* __restrict__ A, float* __restrict__ B, int C) {
    const int c = blockIdx.x, t = threadIdx.x;   // block 128
    float s = 0.f, q = 0.f;
    for (int slot = t; slot < 256; slot += 128) {
        s += p1[slot * C + c];
        q += p2[slot * C + c];
    }
    __shared__ float rs[4], rq[4];
#pragma unroll
    for (int off = 16; off; off >>= 1) {
        s += __shfl_down_sync(0xffffffffu, s, off);
        q += __shfl_down_sync(0xffffffffu, q, off);
    }
    int lane = t & 31, wp = t >> 5;
    if (!lane) { rs[wp] = s; rq[wp] = q; }
    __syncthreads();
    if (t == 0) {
        s = rs[0] + rs[1] + rs[2] + rs[3];
        q = rq[0] + rq[1] + rq[2] + rq[3];
        const float inv = 1.f / (float)(BATCH * NPIX);
        float mean = s * inv;
        float var  = q * inv - mean * mean;
        float a = g[c] * rsqrtf(var + 1e-5f);
        A[c] = a;
        B[c] = be[c] - mean * a;
    }
}

// ---------------- 1x1 conv Cout=64 with input-BN + stats ----------------
__global__ void __launch_bounds__(256) conv1x1_bn_kernel(
    const float* __restrict__ in, const float* __restrict__ w,
    float* __restrict__ out, int Cin,
    const float* __restrict__ Abn, const float* __restrict__ Bbn,
    float* __restrict__ p1, float* __restrict__ p2)
{
    const int p0 = blockIdx.x * 64;
    const int b  = blockIdx.z;
    in  += (long)b * Cin * NPIX;
    out += (long)b * 64  * NPIX;
    const int t = threadIdx.x, tx = t & 15, ty = t >> 4;

    __shared__ float sW [16 * 68];
    __shared__ float sIn[16 * 64];

    float acc[4][4];
#pragma unroll
    for (int r = 0; r < 4; r++)
#pragma unroll
        for (int c = 0; c < 4; c++) acc[r][c] = 0.f;

    for (int ic0 = 0; ic0 < Cin; ic0 += 16) {
        __syncthreads();
        for (int idx = t; idx < 1024; idx += 256) {
            int ic = idx & 15, oc = idx >> 4;
            sW[ic * 68 + oc] = w[(long)oc * Cin + ic0 + ic];
        }
        for (int idx = t; idx < 1024; idx += 256) {
            int ic = idx >> 6, px = idx & 63;
            int c = ic0 + ic;
            float v = in[c * NPIX + p0 + px];
            sIn[idx] = fmaxf(v * Abn[c] + Bbn[c], 0.f);
        }
        __syncthreads();
#pragma unroll
        for (int ic = 0; ic < 16; ic++) {
            float4 a  = *(const float4*)(sW  + ic * 68 + ty * 4);
            float4 xv = *(const float4*)(sIn + ic * 64 + tx * 4);
            float av[4] = {a.x, a.y, a.z, a.w};
            float xa[4] = {xv.x, xv.y, xv.z, xv.w};
#pragma unroll
            for (int r = 0; r < 4; r++)
#pragma unroll
                for (int c = 0; c < 4; c++) acc[r][c] += av[r] * xa[c];
        }
    }
    float sums[4], sqs[4];
#pragma unroll
    for (int r = 0; r < 4; r++) {
        float s = 0.f, q = 0.f;
        float* op = out + (long)(ty * 4 + r) * NPIX + p0 + tx * 4;
#pragma unroll
        for (int c = 0; c < 4; c++) {
            float v = acc[r][c];
            op[c] = v; s += v; q += v * v;
        }
        sums[r] = s; sqs[r] = q;
    }
#pragma unroll
    for (int r = 0; r < 4; r++) {
        float a = sums[r], q = sqs[r];
#pragma unroll
        for (int off = 1; off < 16; off <<= 1) {
            a += __shfl_xor_sync(0xffffffffu, a, off);
            q += __shfl_xor_sync(0xffffffffu, q, off);
        }
        if (tx == 0) {
            int c = ty * 4 + r;
            int slot = b * 64 + blockIdx.x;
            p1[slot * 64 + c] = a;
            p2[slot * 64 + c] = q;
        }
    }
}

// ---------------- fused q/k/v 1x1 projections (branch BN on load) ----------------
__global__ void __launch_bounds__(256) qkv_kernel(
    const float* __restrict__ brin,
    const float* __restrict__ wq, const float* __restrict__ bq,
    const float* __restrict__ wk, const float* __restrict__ bk,
    const float* __restrict__ wv, const float* __restrict__ bv,
    float* __restrict__ qo, float* __restrict__ ko, float* __restrict__ vo,
    const float* __restrict__ Abase, const float* __restrict__ Bbase)
{
    const int p0  = blockIdx.x * 64;
    const int img = blockIdx.z;
    const int br  = img >> 2;
    const long ib = (long)img * 64 * NPIX;
    const float* A  = Abase + (2 + br) * 256;
    const float* Bb = Bbase + (2 + br) * 256;
    const int t = threadIdx.x, tx = t & 15, ty = t >> 4;

    __shared__ float sW [3 * 16 * 64];
    __shared__ float sIn[16 * 64];

    float acc[3][4][4];
#pragma unroll
    for (int m = 0; m < 3; m++)
#pragma unroll
        for (int r = 0; r < 4; r++)
#pragma unroll
            for (int c = 0; c < 4; c++) acc[m][r][c] = 0.f;

    for (int ic0 = 0; ic0 < 64; ic0 += 16) {
        __syncthreads();
        for (int i = t; i < 1024; i += 256) {
            int ic = i >> 6, px = i & 63;
            int c = ic0 + ic;
            float v = brin[ib + (long)c * NPIX + p0 + px];
            sIn[i] = fmaxf(v * A[c] + Bb[c], 0.f);
        }
        for (int i = t; i < 3072; i += 256) {
            int m = i >> 10, r = i & 1023;
            int ic = r & 15, oc = r >> 4;
            const float* wm = (m == 0) ? wq : ((m == 1) ? wk : wv);
            sW[m * 1024 + ic * 64 + oc] = wm[oc * 64 + ic0 + ic];
        }
        __syncthreads();
#pragma unroll
        for (int ic = 0; ic < 16; ic++) {
            float4 xv = *(const float4*)(sIn + ic * 64 + tx * 4);
            float xa[4] = {xv.x, xv.y, xv.z, xv.w};
#pragma unroll
            for (int m = 0; m < 3; m++) {
                float4 a = *(const float4*)(sW + m * 1024 + ic * 64 + ty * 4);
                float av[4] = {a.x, a.y, a.z, a.w};
#pragma unroll
                for (int r = 0; r < 4; r++)
#pragma unroll
                    for (int c = 0; c < 4; c++) acc[m][r][c] += av[r] * xa[c];
            }
        }
    }
    float* outs[3] = {qo, ko, vo};
    const float* bs[3] = {bq, bk, bv};
#pragma unroll
    for (int m = 0; m < 3; m++) {
#pragma unroll
        for (int r = 0; r < 4; r++) {
            float bb = bs[m][ty * 4 + r];
            float* op = outs[m] + ib + (long)(ty * 4 + r) * NPIX + p0 + tx * 4;
            op[0] = acc[m][r][0] + bb; op[1] = acc[m][r][1] + bb;
            op[2] = acc[m][r][2] + bb; op[3] = acc[m][r][3] + bb;
        }
    }
}

// ---------------- pos table ----------------
__global__ void pos_kernel(const float* __restrict__ rh, const float* __restrict__ rw) {
    int idx = blockIdx.x * blockDim.x + threadIdx.x;
    if (idx >= 64 * NPIX) return;
    int d = idx >> 12, n = idx & 4095, a = n >> 6, bb = n & 63;
    g_pos[idx] = rh[d * 64 + bb] + rw[d * 64 + a];
}

// ================= tf32 tensor-core flash attention =================
#define FLASH2_SMEM ((8192 + 4096 + 8192) * 4)

__global__ void __launch_bounds__(256, 1) flash_mma_kernel(
    const float* __restrict__ qg, const float* __restrict__ kg,
    const float* __restrict__ vg, float* __restrict__ outg)
{
    extern __shared__ uint32_t smu[];
    uint32_t* sK = smu;
    uint32_t* sV = smu + 8192;
    uint32_t* sP = smu + 12288;

    const int i0 = blockIdx.x * 128;
    const int b  = blockIdx.y, br = blockIdx.z;
    const long base = (long)(br * BATCH + b) * 64 * NPIX;
    const float* q = qg + base;
    const float* k = kg + base;
    const float* v = vg + base;
    float* outp = outg + (long)(b * 256 + br * 64) * NPIX;

    const int t = threadIdx.x;
    const int lane = t & 31, w = t >> 5;
    const int g = lane >> 2, tq = lane & 3;

    uint32_t Qf[16][4];
    {
        int i_r = i0 + w * 16 + g;
#pragma unroll
        for (int ks = 0; ks < 16; ks++) {
            int kc = ks * 8 + tq;
            const float* s0 = (kc < 64)     ? (q + kc * NPIX)       : (g_pos + (kc - 64) * NPIX);
            const float* s1 = (kc + 4 < 64) ? (q + (kc + 4) * NPIX) : (g_pos + (kc - 60) * NPIX);
            Qf[ks][0] = f2tf32(s0[i_r]);
            Qf[ks][1] = f2tf32(s0[i_r + 8]);
            Qf[ks][2] = f2tf32(s1[i_r]);
            Qf[ks][3] = f2tf32(s1[i_r + 8]);
        }
    }

    float Oa[8][4];
#pragma unroll
    for (int nt = 0; nt < 8; nt++)
#pragma unroll
        for (int c = 0; c < 4; c++) Oa[nt][c] = 0.f;
    float m0 = -CUDART_INF_F, m1 = -CUDART_INF_F, l0 = 0.f, l1 = 0.f;

    const int p00 = ((2 * tq) & 3) * 2 + (tq >> 1);
    const int p01 = ((2 * tq + 1) & 3) * 2 + ((2 * tq + 1) >> 2);

    for (int j0 = 0; j0 < NPIX; j0 += 64) {
        __syncthreads();
        for (int e = t; e < 8192; e += 256) {
            int klo = e & 7, joff = (e >> 3) & 3;
            int rest = e >> 5;
            int ks = rest & 15, jhi = rest >> 4;
            int j = jhi * 4 + joff;
            int kk = ks * 8 + klo;
            float val = (kk < 64) ? k[kk * NPIX + j0 + j]
                                  : q[(kk - 64) * NPIX + j0 + j];
            sK[ks * 512 + j * 8 + ilv(klo)] = f2tf32(val);
        }
        for (int e = t; e < 4096; e += 256) {
            int jlo = e & 7, doff = (e >> 3) & 3;
            int rest = e >> 5;
            int ksv = rest & 7, dhi = rest >> 3;
            int dd = dhi * 4 + doff;
            int j = ksv * 8 + jlo;
            sV[ksv * 512 + dd * 8 + ilv(jlo)] = f2tf32(v[dd * NPIX + j0 + j]);
        }
        __syncthreads();

        float Sa[8][4];
#pragma unroll
        for (int nt = 0; nt < 8; nt++)
#pragma unroll
            for (int c = 0; c < 4; c++) Sa[nt][c] = 0.f;
#pragma unroll
        for (int ks = 0; ks < 16; ks++) {
#pragma unroll
            for (int nt = 0; nt < 8; nt++) {
                uint2 bb = *(const uint2*)&sK[ks * 512 + (nt * 8 + g) * 8 + 2 * tq];
                mma8(Sa[nt], Qf[ks], bb.x, bb.y);
            }
        }

        float mx0 = -CUDART_INF_F, mx1 = -CUDART_INF_F;
#pragma unroll
        for (int nt = 0; nt < 8; nt++) {
            mx0 = fmaxf(mx0, fmaxf(Sa[nt][0], Sa[nt][1]));
            mx1 = fmaxf(mx1, fmaxf(Sa[nt][2], Sa[nt][3]));
        }
        mx0 = fmaxf(mx0, __shfl_xor_sync(0xffffffffu, mx0, 1));
        mx0 = fmaxf(mx0, __shfl_xor_sync(0xffffffffu, mx0, 2));
        mx1 = fmaxf(mx1, __shfl_xor_sync(0xffffffffu, mx1, 1));
        mx1 = fmaxf(mx1, __shfl_xor_sync(0xffffffffu, mx1, 2));
        float mn0 = fmaxf(m0, mx0), mn1 = fmaxf(m1, mx1);
        float al0 = __expf(m0 - mn0), al1 = __expf(m1 - mn1);

        float su0 = 0.f, su1 = 0.f;
        const int pb = w * 1024 + g * 8;
#pragma unroll
        for (int nt = 0; nt < 8; nt++) {
            float e00 = __expf(Sa[nt][0] - mn0);
            float e01 = __expf(Sa[nt][1] - mn0);
            float e10 = __expf(Sa[nt][2] - mn1);
            float e11 = __expf(Sa[nt][3] - mn1);
            su0 += e00 + e01; su1 += e10 + e11;
            sP[pb + nt * 128 + p00]      = f2tf32(e00);
            sP[pb + nt * 128 + p01]      = f2tf32(e01);
            sP[pb + nt * 128 + 64 + p00] = f2tf32(e10);
            sP[pb + nt * 128 + 64 + p01] = f2tf32(e11);
        }
        su0 += __shfl_xor_sync(0xffffffffu, su0, 1);
        su0 += __shfl_xor_sync(0xffffffffu, su0, 2);
        su1 += __shfl_xor_sync(0xffffffffu, su1, 1);
        su1 += __shfl_xor_sync(0xffffffffu, su1, 2);
        l0 = l0 * al0 + su0; l1 = l1 * al1 + su1;
        m0 = mn0; m1 = mn1;
#pragma unroll
        for (int nt = 0; nt < 8; nt++) {
            Oa[nt][0] *= al0; Oa[nt][1] *= al0;
            Oa[nt][2] *= al1; Oa[nt][3] *= al1;
        }
        __syncwarp();

#pragma unroll
        for (int ks = 0; ks < 8; ks++) {
            const uint32_t* ap = &sP[w * 1024 + ks * 128 + g * 8 + 2 * tq];
            uint2 a02 = *(const uint2*)ap;
            uint2 a13 = *(const uint2*)(ap + 64);
            uint32_t a[4] = {a02.x, a13.x, a02.y, a13.y};
#pragma unroll
            for (int nt = 0; nt < 8; nt++) {
                uint2 bb = *(const uint2*)&sV[ks * 512 + (nt * 8 + g) * 8 + 2 * tq];
                mma8(Oa[nt], a, bb.x, bb.y);
            }
        }
    }

    float inv0 = 1.f / l0, inv1 = 1.f / l1;
    int pix = i0 + w * 16 + g;
#pragma unroll
    for (int nt = 0; nt < 8; nt++) {
        int d0 = nt * 8 + 2 * tq;
        outp[(long)d0 * NPIX + pix]           = Oa[nt][0] * inv0;
        outp[(long)(d0 + 1) * NPIX + pix]     = Oa[nt][1] * inv0;
        outp[(long)d0 * NPIX + pix + 8]       = Oa[nt][2] * inv1;
        outp[(long)(d0 + 1) * NPIX + pix + 8] = Oa[nt][3] * inv1;
    }
}

// ---------------- host orchestration ----------------
extern "C" void kernel_launch(void* const* d_in, const int* in_sizes, int n_in,
                              void* d_out, int out_size) {
    const float* x      = (const float*)d_in[0];
    const float* dc_w1  = (const float*)d_in[1];
    // d_in[2] = dc_b1 : conv bias cancels in train-mode BN
    const float* dc_g1  = (const float*)d_in[3];
    const float* dc_be1 = (const float*)d_in[4];
    const float* dc_w2  = (const float*)d_in[5];
    // d_in[6] = dc_b2 : cancels
    const float* dc_g2  = (const float*)d_in[7];
    const float* dc_be2 = (const float*)d_in[8];
    const float* aw[4]  = {(const float*)d_in[9],  (const float*)d_in[12],
                           (const float*)d_in[15], (const float*)d_in[18]};
    const float* ag[4]  = {(const float*)d_in[10], (const float*)d_in[13],
                           (const float*)d_in[16], (const float*)d_in[19]};
    const float* ab[4]  = {(const float*)d_in[11], (const float*)d_in[14],
                           (const float*)d_in[17], (const float*)d_in[20]};
    const float* wq = (const float*)d_in[21]; const float* bq = (const float*)d_in[22];
    const float* wk = (const float*)d_in[23]; const float* bk = (const float*)d_in[24];
    const float* wv = (const float*)d_in[25]; const float* bv = (const float*)d_in[26];
    const float* rel_h = (const float*)d_in[27];
    const float* rel_w = (const float*)d_in[28];

    float *pool, *buf1, *buf2, *brb, *qb, *kb, *vb, *p1, *p2, *An, *Bn;
    cudaGetSymbolAddress((void**)&pool, g_pool);
    cudaGetSymbolAddress((void**)&buf1, g_buf1);
    cudaGetSymbolAddress((void**)&buf2, g_buf2);
    cudaGetSymbolAddress((void**)&brb,  g_br);
    cudaGetSymbolAddress((void**)&qb,   g_q);
    cudaGetSymbolAddress((void**)&kb,   g_k);
    cudaGetSymbolAddress((void**)&vb,   g_v);
    cudaGetSymbolAddress((void**)&p1,   g_p1);
    cudaGetSymbolAddress((void**)&p2,   g_p2);
    cudaGetSymbolAddress((void**)&An,   g_An);
    cudaGetSymbolAddress((void**)&Bn,   g_Bn);

    // mpconv: pool -> conv1(+stats) -> fin -> conv2(BN on load, +stats) -> fin
    maxpool_kernel<<<(BATCH * 128 * NPIX + 255) / 256, 256>>>(x, pool);
    conv3x3_f2_kernel<1, 128, 8><<<dim3(64, 2, BATCH), 128>>>(
        pool, dc_w1, buf1, 128, nullptr, nullptr, p1, p2);
    finalize_kernel<<<256, 128>>>(p1, p2, dc_g1, dc_be1, An + 0, Bn + 0, 256);
    conv3x3_f2_kernel<1, 128, 8><<<dim3(64, 2, BATCH), 128>>>(
        buf1, dc_w2, buf2, 256, An + 0, Bn + 0, p1, p2);
    finalize_kernel<<<256, 128>>>(p1, p2, dc_g2, dc_be2, An + 256, Bn + 256, 256);

    // ASPP branches (BN1 on load, +stats) -> fin(2+i)
    for (int i = 0; i < 4; i++) {
        float* bro = brb + (long)i * BATCH * 64 * NPIX;
        if (i == 0) {
            conv1x1_bn_kernel<<<dim3(64, 1, BATCH), 256>>>(
                buf2, aw[0], bro, 256, An + 256, Bn + 256, p1, p2);
        } else if (i == 1) {
            conv3x3_f2_kernel<3, 64, 4><<<dim3(64, 1, BATCH), 128>>>(
                buf2, aw[1], bro, 256, An + 256, Bn + 256, p1, p2);
        } else if (i == 2) {
            conv3x3_f2_kernel<6, 64, 4><<<dim3(64, 1, BATCH), 128>>>(
                buf2, aw[2], bro, 256, An + 256, Bn + 256, p1, p2);
        } else {
            conv3x3_f2_kernel<9, 64, 4><<<dim3(64, 1, BATCH), 128>>>(
                buf2, aw[3], bro, 256, An + 256, Bn + 256, p1, p2);
        }
        finalize_kernel<<<64, 128>>>(p1, p2, ag[i], ab[i],
                                     An + (2 + i) * 256, Bn + (2 + i) * 256, 64);
    }

    // fused qkv (branch BN on load) + pos
    qkv_kernel<<<dim3(64, 1, 16), 256>>>(brb, wq, bq, wk, bk, wv, bv,
                                         qb, kb, vb, An, Bn);
    pos_kernel<<<(64 * NPIX + 255) / 256, 256>>>(rel_h, rel_w);

    // tensor-core flash attention -> concat output
    cudaFuncSetAttribute((const void*)flash_mma_kernel,
                         cudaFuncAttributeMaxDynamicSharedMemorySize, FLASH2_SMEM);
    flash_mma_kernel<<<dim3(32, BATCH, 4), 256, FLASH2_SMEM>>>(qb, kb, vb, (float*)d_out);
}

// round 7
// speedup vs baseline: 1.6466x; 1.5633x over previous
#include <cuda_runtime.h>
#include <math_constants.h>
#include <stdint.h>

#define BATCH 4
#define NPIX 4096   // 64*64

// ---------------- scratch (device globals; no cudaMalloc allowed) ----------------
__device__ float g_pool[BATCH * 128 * NPIX];
__device__ float g_buf1[BATCH * 256 * NPIX];
__device__ float g_buf2[BATCH * 256 * NPIX];
__device__ float g_br  [4 * BATCH * 64 * NPIX];
__device__ float g_q   [4 * BATCH * 64 * NPIX];
__device__ float g_k   [4 * BATCH * 64 * NPIX];
__device__ float g_v   [4 * BATCH * 64 * NPIX];
__device__ float g_pos [64 * NPIX];
__device__ float g_p1  [256 * 256];
__device__ float g_p2  [256 * 256];
__device__ float g_An  [6 * 256];
__device__ float g_Bn  [6 * 256];
__device__ float g_wt  [2654208];   // pre-swizzled tf32 hi/lo weights

__device__ __forceinline__ uint32_t f2tf32(float f) {
    uint32_t u;
    asm("cvt.rna.tf32.f32 %0, %1;" : "=r"(u) : "f"(f));
    return u;
}
__device__ __forceinline__ void mma8(float d[4], const uint32_t a[4],
                                     uint32_t b0, uint32_t b1) {
    asm volatile(
        "mma.sync.aligned.m16n8k8.row.col.f32.tf32.tf32.f32 "
        "{%0,%1,%2,%3},{%4,%5,%6,%7},{%8,%9},{%0,%1,%2,%3};"
        : "+f"(d[0]), "+f"(d[1]), "+f"(d[2]), "+f"(d[3])
        : "r"(a[0]), "r"(a[1]), "r"(a[2]), "r"(a[3]), "r"(b0), "r"(b1));
}
__device__ __forceinline__ int ilv(int klo) { return (klo & 3) * 2 + (klo >> 2); }

// ---------------- maxpool 2x2 ----------------
__global__ void maxpool_kernel(const float* __restrict__ x, float* __restrict__ out) {
    int idx = blockIdx.x * blockDim.x + threadIdx.x;
    if (idx >= BATCH * 128 * NPIX) return;
    int p  = idx & (NPIX - 1);
    int bc = idx >> 12;
    int y = p >> 6, xx = p & 63;
    const float* src = x + ((long)bc * 128 + 2 * y) * 128 + 2 * xx;
    out[idx] = fmaxf(fmaxf(src[0], src[1]), fmaxf(src[128], src[129]));
}

// ---------------- weight prep: OIHW -> [ocg][chunk][hi/lo][tap][oc64][ilv8] ----------------
__global__ void wprep_kernel(const float* __restrict__ W, float* __restrict__ dst,
                             int Cin, int Cout) {
    int idx = blockIdx.x * 256 + threadIdx.x;
    int total = Cout * Cin * 9;
    if (idx >= total) return;
    int tap = idx % 9;
    int rem = idx / 9;
    int ic  = rem % Cin;
    int oc  = rem / Cin;
    float wv = W[idx];
    float hi = __uint_as_float(f2tf32(wv));
    float lo = __uint_as_float(f2tf32(wv - hi));
    int ocg = oc >> 6, oc64 = oc & 63, chunk = ic >> 3, klo = ic & 7;
    int nch = Cin >> 3;
    long base = (long)(ocg * nch + chunk) * 9216;
    dst[base +        (tap * 64 + oc64) * 8 + ilv(klo)] = hi;
    dst[base + 4608 + (tap * 64 + oc64) * 8 + ilv(klo)] = lo;
}

// ======== tensor-core 3x3 dilated conv (pad = dil), tap-decomposed implicit GEMM ========
// CTA: 256 thr = 8 warps (2 mwarps x 4 nwarps). CTA tile: 64 oc x 128 px (2 y rows).
// warp tile m32 x n32. K-chunks of 8 ic, 9 taps. Weights hi+lo accumulate into same acc.
#define CONV_SMEM (14016 * 4)
template<bool ASPP>
__global__ void __launch_bounds__(256) conv_mma_kernel(
    const float* __restrict__ in, const float* __restrict__ wtbase,
    float* __restrict__ outbase, int Cin,
    const float* __restrict__ Abn, const float* __restrict__ Bbn,
    float* __restrict__ p1base, float* __restrict__ p2base)
{
    extern __shared__ float sm[];
    float* sIn = sm;             // 8 * 536
    float* sW  = sm + 4288;      // [hl][tap][oc64][8]
    float* sRS = sm + 13504;     // [8 warps][32]
    float* sRQ = sm + 13760;

    const int ytile = blockIdx.x;      // 0..31
    const int b     = blockIdx.z;
    const int nchunk = Cin >> 3;
    int dil, ocg, Cout;
    const float* wt;
    float* out;
    float *p1, *p2;
    if (ASPP) {
        int br = blockIdx.y;           // 0..2 -> dil 3,6,9
        dil = 3 * (br + 1); ocg = 0; Cout = 64;
        wt  = wtbase + (long)br * 294912;
        out = outbase + ((long)br * BATCH + b) * 64 * NPIX;
        p1  = p1base + br * 8192;
        p2  = p2base + br * 8192;
    } else {
        dil = 1; ocg = blockIdx.y; Cout = gridDim.y * 64;
        wt  = wtbase + (long)ocg * nchunk * 9216;   // FIX: per-ocg weight block
        out = outbase + (long)b * Cout * NPIX;
        p1  = p1base; p2 = p2base;
    }
    in += (long)b * Cin * NPIX;

    const int t = threadIdx.x, lane = t & 31, w = t >> 5;
    const int g = lane >> 2, tq = lane & 3;
    const int mwarp = w >> 2, nwarp = w & 3;
    const int yr    = nwarp >> 1;
    const int xbase = (nwarp & 1) * 32 + g;
    const int y0    = ytile * 2;

    for (int i = t; i < 4288; i += 256) sIn[i] = 0.f;

    float acc[2][4][4];
#pragma unroll
    for (int mf = 0; mf < 2; mf++)
#pragma unroll
        for (int nt = 0; nt < 4; nt++)
#pragma unroll
            for (int c = 0; c < 4; c++) acc[mf][nt][c] = 0.f;

    for (int chunk = 0; chunk < nchunk; chunk++) {
        __syncthreads();
        // ---- stage weights: pure float4 copy of pre-swizzled block ----
        {
            const float4* ws = (const float4*)(wt + (long)chunk * 9216);
            float4* wd = (float4*)sW;
#pragma unroll
            for (int i = t; i < 2304; i += 256) wd[i] = ws[i];
        }
        // ---- stage input rows (48 rows of 64), BN+ReLU + tf32 on load ----
        {
            const int ic0 = chunk * 8;
#pragma unroll
            for (int i = t; i < 3072; i += 256) {
                int col = i & 63;
                int row = i >> 6;
                int ic  = row / 6;
                int r2  = row - ic * 6;
                int ky  = r2 >> 1, yri = r2 & 1;
                int ry  = y0 + yri + (ky - 1) * dil;
                float v = 0.f;
                if (ry >= 0 && ry < 64) {
                    int c = ic0 + ic;
                    v = in[c * NPIX + ry * 64 + col];
                    if (Abn) v = fmaxf(v * Abn[c] + Bbn[c], 0.f);
                }
                sIn[ic * 536 + (ky * 2 + yri) * 88 + 12 + col] =
                    __uint_as_float(f2tf32(v));
            }
        }
        __syncthreads();

        // ---- 9 taps x (hi+lo) x 4 n-tiles ----
#pragma unroll
        for (int tap = 0; tap < 9; tap++) {
            const int ky = tap / 3, kx = tap % 3;
            const uint32_t* bp = (const uint32_t*)(sIn) +
                tq * 536 + (ky * 2 + yr) * 88 + 12 + xbase + (kx - 1) * dil;
            const float* wb = sW + (tap * 64 + mwarp * 32 + g) * 8 + 2 * tq;
            uint2 h0  = *(const uint2*)(wb);
            uint2 h0b = *(const uint2*)(wb + 64);
            uint2 h1  = *(const uint2*)(wb + 128);
            uint2 h1b = *(const uint2*)(wb + 192);
            uint2 l0  = *(const uint2*)(wb + 4608);
            uint2 l0b = *(const uint2*)(wb + 4672);
            uint2 l1  = *(const uint2*)(wb + 4736);
            uint2 l1b = *(const uint2*)(wb + 4800);
            uint32_t aH0[4] = {h0.x, h0b.x, h0.y, h0b.y};
            uint32_t aH1[4] = {h1.x, h1b.x, h1.y, h1b.y};
            uint32_t aL0[4] = {l0.x, l0b.x, l0.y, l0b.y};
            uint32_t aL1[4] = {l1.x, l1b.x, l1.y, l1b.y};
#pragma unroll
            for (int nt = 0; nt < 4; nt++) {
                uint32_t b0 = bp[nt * 8];
                uint32_t b1 = bp[nt * 8 + 2144];
                mma8(acc[0][nt], aH0, b0, b1);
                mma8(acc[0][nt], aL0, b0, b1);
                mma8(acc[1][nt], aH1, b0, b1);
                mma8(acc[1][nt], aL1, b0, b1);
            }
        }
    }

    // ---- epilogue: store + BN partials ----
    float s[2][2] = {{0.f, 0.f}, {0.f, 0.f}};
    float q[2][2] = {{0.f, 0.f}, {0.f, 0.f}};
    const int ocb = ocg * 64 + mwarp * 32;
#pragma unroll
    for (int mf = 0; mf < 2; mf++) {
        int oc = ocb + mf * 16 + g;
#pragma unroll
        for (int nt = 0; nt < 4; nt++) {
            int gx = (y0 + yr) * 64 + (nwarp & 1) * 32 + nt * 8 + 2 * tq;
            float c0 = acc[mf][nt][0], c1 = acc[mf][nt][1];
            float c2 = acc[mf][nt][2], c3 = acc[mf][nt][3];
            out[(long)oc * NPIX + gx]           = c0;
            out[(long)oc * NPIX + gx + 1]       = c1;
            out[(long)(oc + 8) * NPIX + gx]     = c2;
            out[(long)(oc + 8) * NPIX + gx + 1] = c3;
            s[mf][0] += c0 + c1; q[mf][0] += c0 * c0 + c1 * c1;
            s[mf][1] += c2 + c3; q[mf][1] += c2 * c2 + c3 * c3;
        }
    }
#pragma unroll
    for (int mf = 0; mf < 2; mf++)
#pragma unroll
        for (int ro = 0; ro < 2; ro++) {
            float a = s[mf][ro], qq = q[mf][ro];
            a  += __shfl_xor_sync(0xffffffffu, a, 1);
            qq += __shfl_xor_sync(0xffffffffu, qq, 1);
            a  += __shfl_xor_sync(0xffffffffu, a, 2);
            qq += __shfl_xor_sync(0xffffffffu, qq, 2);
            if (tq == 0) {
                sRS[w * 32 + mf * 16 + ro * 8 + g] = a;
                sRQ[w * 32 + mf * 16 + ro * 8 + g] = qq;
            }
        }
    __syncthreads();
    if (t < 64) {
        int mw = t >> 5, cl = t & 31;
        float a  = sRS[(mw * 4 + 0) * 32 + cl] + sRS[(mw * 4 + 1) * 32 + cl] +
                   sRS[(mw * 4 + 2) * 32 + cl] + sRS[(mw * 4 + 3) * 32 + cl];
        float qq = sRQ[(mw * 4 + 0) * 32 + cl] + sRQ[(mw * 4 + 1) * 32 + cl] +
                   sRQ[(mw * 4 + 2) * 32 + cl] + sRQ[(mw * 4 + 3) * 32 + cl];
        int slot = b * 32 + ytile;
        p1[slot * Cout + ocg * 64 + t] = a;
        p2[slot * Cout + ocg * 64 + t] = qq;
    }
}

// ---------------- BN finalize ----------------
__global__ void finalize_kernel(const float* __restrict__ p1, const float* __restrict__ p2,
                                const float* __restrict__ g, const float* __restrict__ be,
                                float* __restrict__ A, float* __restrict__ B,
                                int C, int nslots) {
    const int c = blockIdx.x, t = threadIdx.x;   // block 128
    float s = 0.f, q = 0.f;
    for (int slot = t; slot < nslots; slot += 128) {
        s += p1[slot * C + c];
        q += p2[slot * C + c];
    }
    __shared__ float rs[4], rq[4];
#pragma unroll
    for (int off = 16; off; off >>= 1) {
        s += __shfl_down_sync(0xffffffffu, s, off);
        q += __shfl_down_sync(0xffffffffu, q, off);
    }
    int lane = t & 31, wp = t >> 5;
    if (!lane) { rs[wp] = s; rq[wp] = q; }
    __syncthreads();
    if (t == 0) {
        s = rs[0] + rs[1] + rs[2] + rs[3];
        q = rq[0] + rq[1] + rq[2] + rq[3];
        const float inv = 1.f / (float)(BATCH * NPIX);
        float mean = s * inv;
        float var  = q * inv - mean * mean;
        float a = g[c] * rsqrtf(var + 1e-5f);
        A[c] = a;
        B[c] = be[c] - mean * a;
    }
}

// ---------------- 1x1 conv Cout=64 with input-BN + stats (aspp1) ----------------
__global__ void __launch_bounds__(256) conv1x1_bn_kernel(
    const float* __restrict__ in, const float* __restrict__ w,
    float* __restrict__ out, int Cin,
    const float* __restrict__ Abn, const float* __restrict__ Bbn,
    float* __restrict__ p1, float* __restrict__ p2)
{
    const int p0 = blockIdx.x * 64;
    const int b  = blockIdx.z;
    in  += (long)b * Cin * NPIX;
    out += (long)b * 64  * NPIX;
    const int t = threadIdx.x, tx = t & 15, ty = t >> 4;

    __shared__ float sW [16 * 68];
    __shared__ float sIn[16 * 64];

    float acc[4][4];
#pragma unroll
    for (int r = 0; r < 4; r++)
#pragma unroll
        for (int c = 0; c < 4; c++) acc[r][c] = 0.f;

    for (int ic0 = 0; ic0 < Cin; ic0 += 16) {
        __syncthreads();
        for (int idx = t; idx < 1024; idx += 256) {
            int ic = idx & 15, oc = idx >> 4;
            sW[ic * 68 + oc] = w[(long)oc * Cin + ic0 + ic];
        }
        for (int idx = t; idx < 1024; idx += 256) {
            int ic = idx >> 6, px = idx & 63;
            int c = ic0 + ic;
            float v = in[c * NPIX + p0 + px];
            sIn[idx] = fmaxf(v * Abn[c] + Bbn[c], 0.f);
        }
        __syncthreads();
#pragma unroll
        for (int ic = 0; ic < 16; ic++) {
            float4 a  = *(const float4*)(sW  + ic * 68 + ty * 4);
            float4 xv = *(const float4*)(sIn + ic * 64 + tx * 4);
            float av[4] = {a.x, a.y, a.z, a.w};
            float xa[4] = {xv.x, xv.y, xv.z, xv.w};
#pragma unroll
            for (int r = 0; r < 4; r++)
#pragma unroll
                for (int c = 0; c < 4; c++) acc[r][c] += av[r] * xa[c];
        }
    }
    float sums[4], sqs[4];
#pragma unroll
    for (int r = 0; r < 4; r++) {
        float s = 0.f, q = 0.f;
        float* op = out + (long)(ty * 4 + r) * NPIX + p0 + tx * 4;
#pragma unroll
        for (int c = 0; c < 4; c++) {
            float v = acc[r][c];
            op[c] = v; s += v; q += v * v;
        }
        sums[r] = s; sqs[r] = q;
    }
#pragma unroll
    for (int r = 0; r < 4; r++) {
        float a = sums[r], q = sqs[r];
#pragma unroll
        for (int off = 1; off < 16; off <<= 1) {
            a += __shfl_xor_sync(0xffffffffu, a, off);
            q += __shfl_xor_sync(0xffffffffu, q, off);
        }
        if (tx == 0) {
            int c = ty * 4 + r;
            int slot = b * 64 + blockIdx.x;
            p1[slot * 64 + c] = a;
            p2[slot * 64 + c] = q;
        }
    }
}

// ---------------- fused q/k/v 1x1 projections (branch BN on load) ----------------
__global__ void __launch_bounds__(256) qkv_kernel(
    const float* __restrict__ brin,
    const float* __restrict__ wq, const float* __restrict__ bq,
    const float* __restrict__ wk, const float* __restrict__ bk,
    const float* __restrict__ wv, const float* __restrict__ bv,
    float* __restrict__ qo, float* __restrict__ ko, float* __restrict__ vo,
    const float* __restrict__ Abase, const float* __restrict__ Bbase)
{
    const int p0  = blockIdx.x * 64;
    const int img = blockIdx.z;
    const int br  = img >> 2;
    const long ib = (long)img * 64 * NPIX;
    const float* A  = Abase + (2 + br) * 256;
    const float* Bb = Bbase + (2 + br) * 256;
    const int t = threadIdx.x, tx = t & 15, ty = t >> 4;

    __shared__ float sW [3 * 16 * 64];
    __shared__ float sIn[16 * 64];

    float acc[3][4][4];
#pragma unroll
    for (int m = 0; m < 3; m++)
#pragma unroll
        for (int r = 0; r < 4; r++)
#pragma unroll
            for (int c = 0; c < 4; c++) acc[m][r][c] = 0.f;

    for (int ic0 = 0; ic0 < 64; ic0 += 16) {
        __syncthreads();
        for (int i = t; i < 1024; i += 256) {
            int ic = i >> 6, px = i & 63;
            int c = ic0 + ic;
            float v = brin[ib + (long)c * NPIX + p0 + px];
            sIn[i] = fmaxf(v * A[c] + Bb[c], 0.f);
        }
        for (int i = t; i < 3072; i += 256) {
            int m = i >> 10, r = i & 1023;
            int ic = r & 15, oc = r >> 4;
            const float* wm = (m == 0) ? wq : ((m == 1) ? wk : wv);
            sW[m * 1024 + ic * 64 + oc] = wm[oc * 64 + ic0 + ic];
        }
        __syncthreads();
#pragma unroll
        for (int ic = 0; ic < 16; ic++) {
            float4 xv = *(const float4*)(sIn + ic * 64 + tx * 4);
            float xa[4] = {xv.x, xv.y, xv.z, xv.w};
#pragma unroll
            for (int m = 0; m < 3; m++) {
                float4 a = *(const float4*)(sW + m * 1024 + ic * 64 + ty * 4);
                float av[4] = {a.x, a.y, a.z, a.w};
#pragma unroll
                for (int r = 0; r < 4; r++)
#pragma unroll
                    for (int c = 0; c < 4; c++) acc[m][r][c] += av[r] * xa[c];
            }
        }
    }
    float* outs[3] = {qo, ko, vo};
    const float* bs[3] = {bq, bk, bv};
#pragma unroll
    for (int m = 0; m < 3; m++) {
#pragma unroll
        for (int r = 0; r < 4; r++) {
            float bb = bs[m][ty * 4 + r];
            float* op = outs[m] + ib + (long)(ty * 4 + r) * NPIX + p0 + tx * 4;
            op[0] = acc[m][r][0] + bb; op[1] = acc[m][r][1] + bb;
            op[2] = acc[m][r][2] + bb; op[3] = acc[m][r][3] + bb;
        }
    }
}

// ---------------- pos table ----------------
__global__ void pos_kernel(const float* __restrict__ rh, const float* __restrict__ rw) {
    int idx = blockIdx.x * blockDim.x + threadIdx.x;
    if (idx >= 64 * NPIX) return;
    int d = idx >> 12, n = idx & 4095, a = n >> 6, bb = n & 63;
    g_pos[idx] = rh[d * 64 + bb] + rw[d * 64 + a];
}

// ================= tf32 tensor-core flash attention =================
#define FLASH2_SMEM ((8192 + 4096 + 8192) * 4)

__global__ void __launch_bounds__(256, 1) flash_mma_kernel(
    const float* __restrict__ qg, const float* __restrict__ kg,
    const float* __restrict__ vg, float* __restrict__ outg)
{
    extern __shared__ uint32_t smu[];
    uint32_t* sK = smu;
    uint32_t* sV = smu + 8192;
    uint32_t* sP = smu + 12288;

    const int i0 = blockIdx.x * 128;
    const int b  = blockIdx.y, br = blockIdx.z;
    const long base = (long)(br * BATCH + b) * 64 * NPIX;
    const float* q = qg + base;
    const float* k = kg + base;
    const float* v = vg + base;
    float* outp = outg + (long)(b * 256 + br * 64) * NPIX;

    const int t = threadIdx.x;
    const int lane = t & 31, w = t >> 5;
    const int g = lane >> 2, tq = lane & 3;

    uint32_t Qf[16][4];
    {
        int i_r = i0 + w * 16 + g;
#pragma unroll
        for (int ks = 0; ks < 16; ks++) {
            int kc = ks * 8 + tq;
            const float* s0 = (kc < 64)     ? (q + kc * NPIX)       : (g_pos + (kc - 64) * NPIX);
            const float* s1 = (kc + 4 < 64) ? (q + (kc + 4) * NPIX) : (g_pos + (kc - 60) * NPIX);
            Qf[ks][0] = f2tf32(s0[i_r]);
            Qf[ks][1] = f2tf32(s0[i_r + 8]);
            Qf[ks][2] = f2tf32(s1[i_r]);
            Qf[ks][3] = f2tf32(s1[i_r + 8]);
        }
    }

    float Oa[8][4];
#pragma unroll
    for (int nt = 0; nt < 8; nt++)
#pragma unroll
        for (int c = 0; c < 4; c++) Oa[nt][c] = 0.f;
    float m0 = -CUDART_INF_F, m1 = -CUDART_INF_F, l0 = 0.f, l1 = 0.f;

    const int p00 = ((2 * tq) & 3) * 2 + (tq >> 1);
    const int p01 = ((2 * tq + 1) & 3) * 2 + ((2 * tq + 1) >> 2);

    for (int j0 = 0; j0 < NPIX; j0 += 64) {
        __syncthreads();
        for (int e = t; e < 8192; e += 256) {
            int klo = e & 7, joff = (e >> 3) & 3;
            int rest = e >> 5;
            int ks = rest & 15, jhi = rest >> 4;
            int j = jhi * 4 + joff;
            int kk = ks * 8 + klo;
            float val = (kk < 64) ? k[kk * NPIX + j0 + j]
                                  : q[(kk - 64) * NPIX + j0 + j];
            sK[ks * 512 + j * 8 + ilv(klo)] = f2tf32(val);
        }
        for (int e = t; e < 4096; e += 256) {
            int jlo = e & 7, doff = (e >> 3) & 3;
            int rest = e >> 5;
            int ksv = rest & 7, dhi = rest >> 3;
            int dd = dhi * 4 + doff;
            int j = ksv * 8 + jlo;
            sV[ksv * 512 + dd * 8 + ilv(jlo)] = f2tf32(v[dd * NPIX + j0 + j]);
        }
        __syncthreads();

        float Sa[8][4];
#pragma unroll
        for (int nt = 0; nt < 8; nt++)
#pragma unroll
            for (int c = 0; c < 4; c++) Sa[nt][c] = 0.f;
#pragma unroll
        for (int ks = 0; ks < 16; ks++) {
#pragma unroll
            for (int nt = 0; nt < 8; nt++) {
                uint2 bb = *(const uint2*)&sK[ks * 512 + (nt * 8 + g) * 8 + 2 * tq];
                mma8(Sa[nt], Qf[ks], bb.x, bb.y);
            }
        }

        float mx0 = -CUDART_INF_F, mx1 = -CUDART_INF_F;
#pragma unroll
        for (int nt = 0; nt < 8; nt++) {
            mx0 = fmaxf(mx0, fmaxf(Sa[nt][0], Sa[nt][1]));
            mx1 = fmaxf(mx1, fmaxf(Sa[nt][2], Sa[nt][3]));
        }
        mx0 = fmaxf(mx0, __shfl_xor_sync(0xffffffffu, mx0, 1));
        mx0 = fmaxf(mx0, __shfl_xor_sync(0xffffffffu, mx0, 2));
        mx1 = fmaxf(mx1, __shfl_xor_sync(0xffffffffu, mx1, 1));
        mx1 = fmaxf(mx1, __shfl_xor_sync(0xffffffffu, mx1, 2));
        float mn0 = fmaxf(m0, mx0), mn1 = fmaxf(m1, mx1);
        float al0 = __expf(m0 - mn0), al1 = __expf(m1 - mn1);

        float su0 = 0.f, su1 = 0.f;
        const int pb = w * 1024 + g * 8;
#pragma unroll
        for (int nt = 0; nt < 8; nt++) {
            float e00 = __expf(Sa[nt][0] - mn0);
            float e01 = __expf(Sa[nt][1] - mn0);
            float e10 = __expf(Sa[nt][2] - mn1);
            float e11 = __expf(Sa[nt][3] - mn1);
            su0 += e00 + e01; su1 += e10 + e11;
            sP[pb + nt * 128 + p00]      = f2tf32(e00);
            sP[pb + nt * 128 + p01]      = f2tf32(e01);
            sP[pb + nt * 128 + 64 + p00] = f2tf32(e10);
            sP[pb + nt * 128 + 64 + p01] = f2tf32(e11);
        }
        su0 += __shfl_xor_sync(0xffffffffu, su0, 1);
        su0 += __shfl_xor_sync(0xffffffffu, su0, 2);
        su1 += __shfl_xor_sync(0xffffffffu, su1, 1);
        su1 += __shfl_xor_sync(0xffffffffu, su1, 2);
        l0 = l0 * al0 + su0; l1 = l1 * al1 + su1;
        m0 = mn0; m1 = mn1;
#pragma unroll
        for (int nt = 0; nt < 8; nt++) {
            Oa[nt][0] *= al0; Oa[nt][1] *= al0;
            Oa[nt][2] *= al1; Oa[nt][3] *= al1;
        }
        __syncwarp();

#pragma unroll
        for (int ks = 0; ks < 8; ks++) {
            const uint32_t* ap = &sP[w * 1024 + ks * 128 + g * 8 + 2 * tq];
            uint2 a02 = *(const uint2*)ap;
            uint2 a13 = *(const uint2*)(ap + 64);
            uint32_t a[4] = {a02.x, a13.x, a02.y, a13.y};
#pragma unroll
            for (int nt = 0; nt < 8; nt++) {
                uint2 bb = *(const uint2*)&sV[ks * 512 + (nt * 8 + g) * 8 + 2 * tq];
                mma8(Oa[nt], a, bb.x, bb.y);
            }
        }
    }

    float inv0 = 1.f / l0, inv1 = 1.f / l1;
    int pix = i0 + w * 16 + g;
#pragma unroll
    for (int nt = 0; nt < 8; nt++) {
        int d0 = nt * 8 + 2 * tq;
        outp[(long)d0 * NPIX + pix]           = Oa[nt][0] * inv0;
        outp[(long)(d0 + 1) * NPIX + pix]     = Oa[nt][1] * inv0;
        outp[(long)d0 * NPIX + pix + 8]       = Oa[nt][2] * inv1;
        outp[(long)(d0 + 1) * NPIX + pix + 8] = Oa[nt][3] * inv1;
    }
}

// ---------------- host orchestration ----------------
extern "C" void kernel_launch(void* const* d_in, const int* in_sizes, int n_in,
                              void* d_out, int out_size) {
    const float* x      = (const float*)d_in[0];
    const float* dc_w1  = (const float*)d_in[1];
    // d_in[2] = dc_b1 : conv bias cancels in train-mode BN
    const float* dc_g1  = (const float*)d_in[3];
    const float* dc_be1 = (const float*)d_in[4];
    const float* dc_w2  = (const float*)d_in[5];
    // d_in[6] = dc_b2 : cancels
    const float* dc_g2  = (const float*)d_in[7];
    const float* dc_be2 = (const float*)d_in[8];
    const float* aw[4]  = {(const float*)d_in[9],  (const float*)d_in[12],
                           (const float*)d_in[15], (const float*)d_in[18]};
    const float* ag[4]  = {(const float*)d_in[10], (const float*)d_in[13],
                           (const float*)d_in[16], (const float*)d_in[19]};
    const float* ab[4]  = {(const float*)d_in[11], (const float*)d_in[14],
                           (const float*)d_in[17], (const float*)d_in[20]};
    const float* wq = (const float*)d_in[21]; const float* bq = (const float*)d_in[22];
    const float* wk = (const float*)d_in[23]; const float* bk = (const float*)d_in[24];
    const float* wv = (const float*)d_in[25]; const float* bv = (const float*)d_in[26];
    const float* rel_h = (const float*)d_in[27];
    const float* rel_w = (const float*)d_in[28];

    float *pool, *buf1, *buf2, *brb, *qb, *kb, *vb, *p1, *p2, *An, *Bn, *wt;
    cudaGetSymbolAddress((void**)&pool, g_pool);
    cudaGetSymbolAddress((void**)&buf1, g_buf1);
    cudaGetSymbolAddress((void**)&buf2, g_buf2);
    cudaGetSymbolAddress((void**)&brb,  g_br);
    cudaGetSymbolAddress((void**)&qb,   g_q);
    cudaGetSymbolAddress((void**)&kb,   g_k);
    cudaGetSymbolAddress((void**)&vb,   g_v);
    cudaGetSymbolAddress((void**)&p1,   g_p1);
    cudaGetSymbolAddress((void**)&p2,   g_p2);
    cudaGetSymbolAddress((void**)&An,   g_An);
    cudaGetSymbolAddress((void**)&Bn,   g_Bn);
    cudaGetSymbolAddress((void**)&wt,   g_wt);

    float* wt1 = wt;                 // conv1: 589824
    float* wt2 = wt + 589824;        // conv2: 1179648
    float* wtA = wt + 1769472;       // aspp 3x3 convs: 3 x 294912

    cudaFuncSetAttribute((const void*)conv_mma_kernel<false>,
                         cudaFuncAttributeMaxDynamicSharedMemorySize, CONV_SMEM);
    cudaFuncSetAttribute((const void*)conv_mma_kernel<true>,
                         cudaFuncAttributeMaxDynamicSharedMemorySize, CONV_SMEM);
    cudaFuncSetAttribute((const void*)flash_mma_kernel,
                         cudaFuncAttributeMaxDynamicSharedMemorySize, FLASH2_SMEM);

    // weight prep (tf32 hi/lo, fragment-swizzled)
    wprep_kernel<<<(256 * 128 * 9 + 255) / 256, 256>>>(dc_w1, wt1, 128, 256);
    wprep_kernel<<<(256 * 256 * 9 + 255) / 256, 256>>>(dc_w2, wt2, 256, 256);
    for (int i = 0; i < 3; i++)
        wprep_kernel<<<(64 * 256 * 9 + 255) / 256, 256>>>(
            aw[i + 1], wtA + (long)i * 294912, 256, 64);

    // mpconv
    maxpool_kernel<<<(BATCH * 128 * NPIX + 255) / 256, 256>>>(x, pool);
    conv_mma_kernel<false><<<dim3(32, 4, BATCH), 256, CONV_SMEM>>>(
        pool, wt1, buf1, 128, nullptr, nullptr, p1, p2);
    finalize_kernel<<<256, 128>>>(p1, p2, dc_g1, dc_be1, An + 0, Bn + 0, 256, 128);
    conv_mma_kernel<false><<<dim3(32, 4, BATCH), 256, CONV_SMEM>>>(
        buf1, wt2, buf2, 256, An + 0, Bn + 0, p1, p2);
    finalize_kernel<<<256, 128>>>(p1, p2, dc_g2, dc_be2, An + 256, Bn + 256, 256, 128);

    // ASPP dilated branches (2,3,4) in one launch; 1x1 branch separate
    conv_mma_kernel<true><<<dim3(32, 3, BATCH), 256, CONV_SMEM>>>(
        buf2, wtA, brb + (long)BATCH * 64 * NPIX, 256, An + 256, Bn + 256, p1, p2);
    for (int i = 0; i < 3; i++)
        finalize_kernel<<<64, 128>>>(p1 + i * 8192, p2 + i * 8192, ag[i + 1], ab[i + 1],
                                     An + (3 + i) * 256, Bn + (3 + i) * 256, 64, 128);
    conv1x1_bn_kernel<<<dim3(64, 1, BATCH), 256>>>(
        buf2, aw[0], brb, 256, An + 256, Bn + 256, p1 + 32768, p2 + 32768);
    finalize_kernel<<<64, 128>>>(p1 + 32768, p2 + 32768, ag[0], ab[0],
                                 An + 2 * 256, Bn + 2 * 256, 64, 256);

    // fused qkv (branch BN on load) + pos
    qkv_kernel<<<dim3(64, 1, 16), 256>>>(brb, wq, bq, wk, bk, wv, bv,
                                         qb, kb, vb, An, Bn);
    pos_kernel<<<(64 * NPIX + 255) / 256, 256>>>(rel_h, rel_w);

    // tensor-core flash attention -> concat output
    flash_mma_kernel<<<dim3(32, BATCH, 4), 256, FLASH2_SMEM>>>(qb, kb, vb, (float*)d_out);
}

// round 8
// speedup vs baseline: 2.1064x; 1.2792x over previous
#include <cuda_runtime.h>
#include <math_constants.h>
#include <stdint.h>

#define BATCH 4
#define NPIX 4096   // 64*64

// ---------------- scratch (device globals; no cudaMalloc allowed) ----------------
__device__ float g_pool[BATCH * 128 * NPIX];
__device__ float g_buf1[BATCH * 256 * NPIX];
__device__ float g_buf2[BATCH * 256 * NPIX];
__device__ float g_br  [4 * BATCH * 64 * NPIX];
__device__ float g_q   [4 * BATCH * 64 * NPIX];   // plain q (for Q' fragments)
__device__ float g_kf  [16 * 4096 * 128];         // K' fragment-paired tf32
__device__ float g_vf  [16 * 64 * 256 * 16];      // V  fragment-paired tf32
__device__ float g_pos [64 * NPIX];
__device__ float g_p1  [256 * 256];
__device__ float g_p2  [256 * 256];
__device__ float g_An  [6 * 256];
__device__ float g_Bn  [6 * 256];
__device__ float g_wt  [2654208];   // pre-swizzled tf32 hi/lo conv weights

__device__ __forceinline__ uint32_t f2tf32(float f) {
    uint32_t u;
    asm("cvt.rna.tf32.f32 %0, %1;" : "=r"(u) : "f"(f));
    return u;
}
__device__ __forceinline__ void mma8(float d[4], const uint32_t a[4],
                                     uint32_t b0, uint32_t b1) {
    asm volatile(
        "mma.sync.aligned.m16n8k8.row.col.f32.tf32.tf32.f32 "
        "{%0,%1,%2,%3},{%4,%5,%6,%7},{%8,%9},{%0,%1,%2,%3};"
        : "+f"(d[0]), "+f"(d[1]), "+f"(d[2]), "+f"(d[3])
        : "r"(a[0]), "r"(a[1]), "r"(a[2]), "r"(a[3]), "r"(b0), "r"(b1));
}
__device__ __forceinline__ int ilv(int klo) { return (klo & 3) * 2 + (klo >> 2); }

// ---------------- maxpool 2x2 ----------------
__global__ void maxpool_kernel(const float* __restrict__ x, float* __restrict__ out) {
    int idx = blockIdx.x * blockDim.x + threadIdx.x;
    if (idx >= BATCH * 128 * NPIX) return;
    int p  = idx & (NPIX - 1);
    int bc = idx >> 12;
    int y = p >> 6, xx = p & 63;
    const float* src = x + ((long)bc * 128 + 2 * y) * 128 + 2 * xx;
    out[idx] = fmaxf(fmaxf(src[0], src[1]), fmaxf(src[128], src[129]));
}

// ---------------- weight prep: OIHW -> [ocg][chunk][hi/lo][tap][oc64][ilv8] ----------------
__global__ void wprep_kernel(const float* __restrict__ W, float* __restrict__ dst,
                             int Cin, int Cout) {
    int idx = blockIdx.x * 256 + threadIdx.x;
    int total = Cout * Cin * 9;
    if (idx >= total) return;
    int tap = idx % 9;
    int rem = idx / 9;
    int ic  = rem % Cin;
    int oc  = rem / Cin;
    float wv = W[idx];
    float hi = __uint_as_float(f2tf32(wv));
    float lo = __uint_as_float(f2tf32(wv - hi));
    int ocg = oc >> 6, oc64 = oc & 63, chunk = ic >> 3, klo = ic & 7;
    int nch = Cin >> 3;
    long base = (long)(ocg * nch + chunk) * 9216;
    dst[base +        (tap * 64 + oc64) * 8 + ilv(klo)] = hi;
    dst[base + 4608 + (tap * 64 + oc64) * 8 + ilv(klo)] = lo;
}

// ======== tensor-core 3x3 dilated conv (pad = dil), tap-decomposed implicit GEMM ========
#define CONV_SMEM (14016 * 4)
template<bool ASPP>
__global__ void __launch_bounds__(256) conv_mma_kernel(
    const float* __restrict__ in, const float* __restrict__ wtbase,
    float* __restrict__ outbase, int Cin,
    const float* __restrict__ Abn, const float* __restrict__ Bbn,
    float* __restrict__ p1base, float* __restrict__ p2base)
{
    extern __shared__ float sm[];
    float* sIn = sm;             // 8 * 536
    float* sW  = sm + 4288;      // [hl][tap][oc64][8]
    float* sRS = sm + 13504;     // [8 warps][32]
    float* sRQ = sm + 13760;

    const int ytile = blockIdx.x;      // 0..31
    const int b     = blockIdx.z;
    const int nchunk = Cin >> 3;
    int dil, ocg, Cout;
    const float* wt;
    float* out;
    float *p1, *p2;
    if (ASPP) {
        int br = blockIdx.y;           // 0..2 -> dil 3,6,9
        dil = 3 * (br + 1); ocg = 0; Cout = 64;
        wt  = wtbase + (long)br * 294912;
        out = outbase + ((long)br * BATCH + b) * 64 * NPIX;
        p1  = p1base + br * 8192;
        p2  = p2base + br * 8192;
    } else {
        dil = 1; ocg = blockIdx.y; Cout = gridDim.y * 64;
        wt  = wtbase + (long)ocg * nchunk * 9216;
        out = outbase + (long)b * Cout * NPIX;
        p1  = p1base; p2 = p2base;
    }
    in += (long)b * Cin * NPIX;

    const int t = threadIdx.x, lane = t & 31, w = t >> 5;
    const int g = lane >> 2, tq = lane & 3;
    const int mwarp = w >> 2, nwarp = w & 3;
    const int yr    = nwarp >> 1;
    const int xbase = (nwarp & 1) * 32 + g;
    const int y0    = ytile * 2;

    for (int i = t; i < 4288; i += 256) sIn[i] = 0.f;

    float acc[2][4][4];
#pragma unroll
    for (int mf = 0; mf < 2; mf++)
#pragma unroll
        for (int nt = 0; nt < 4; nt++)
#pragma unroll
            for (int c = 0; c < 4; c++) acc[mf][nt][c] = 0.f;

    for (int chunk = 0; chunk < nchunk; chunk++) {
        __syncthreads();
        {
            const float4* ws = (const float4*)(wt + (long)chunk * 9216);
            float4* wd = (float4*)sW;
#pragma unroll
            for (int i = t; i < 2304; i += 256) wd[i] = ws[i];
        }
        {
            const int ic0 = chunk * 8;
#pragma unroll
            for (int i = t; i < 3072; i += 256) {
                int col = i & 63;
                int row = i >> 6;
                int ic  = row / 6;
                int r2  = row - ic * 6;
                int ky  = r2 >> 1, yri = r2 & 1;
                int ry  = y0 + yri + (ky - 1) * dil;
                float v = 0.f;
                if (ry >= 0 && ry < 64) {
                    int c = ic0 + ic;
                    v = in[c * NPIX + ry * 64 + col];
                    if (Abn) v = fmaxf(v * Abn[c] + Bbn[c], 0.f);
                }
                sIn[ic * 536 + (ky * 2 + yri) * 88 + 12 + col] =
                    __uint_as_float(f2tf32(v));
            }
        }
        __syncthreads();

#pragma unroll
        for (int tap = 0; tap < 9; tap++) {
            const int ky = tap / 3, kx = tap % 3;
            const uint32_t* bp = (const uint32_t*)(sIn) +
                tq * 536 + (ky * 2 + yr) * 88 + 12 + xbase + (kx - 1) * dil;
            const float* wb = sW + (tap * 64 + mwarp * 32 + g) * 8 + 2 * tq;
            uint2 h0  = *(const uint2*)(wb);
            uint2 h0b = *(const uint2*)(wb + 64);
            uint2 h1  = *(const uint2*)(wb + 128);
            uint2 h1b = *(const uint2*)(wb + 192);
            uint2 l0  = *(const uint2*)(wb + 4608);
            uint2 l0b = *(const uint2*)(wb + 4672);
            uint2 l1  = *(const uint2*)(wb + 4736);
            uint2 l1b = *(const uint2*)(wb + 4800);
            uint32_t aH0[4] = {h0.x, h0b.x, h0.y, h0b.y};
            uint32_t aH1[4] = {h1.x, h1b.x, h1.y, h1b.y};
            uint32_t aL0[4] = {l0.x, l0b.x, l0.y, l0b.y};
            uint32_t aL1[4] = {l1.x, l1b.x, l1.y, l1b.y};
#pragma unroll
            for (int nt = 0; nt < 4; nt++) {
                uint32_t b0 = bp[nt * 8];
                uint32_t b1 = bp[nt * 8 + 2144];
                mma8(acc[0][nt], aH0, b0, b1);
                mma8(acc[0][nt], aL0, b0, b1);
                mma8(acc[1][nt], aH1, b0, b1);
                mma8(acc[1][nt], aL1, b0, b1);
            }
        }
    }

    // ---- epilogue: store + BN partials ----
    float s[2][2] = {{0.f, 0.f}, {0.f, 0.f}};
    float q[2][2] = {{0.f, 0.f}, {0.f, 0.f}};
    const int ocb = ocg * 64 + mwarp * 32;
#pragma unroll
    for (int mf = 0; mf < 2; mf++) {
        int oc = ocb + mf * 16 + g;
#pragma unroll
        for (int nt = 0; nt < 4; nt++) {
            int gx = (y0 + yr) * 64 + (nwarp & 1) * 32 + nt * 8 + 2 * tq;
            float c0 = acc[mf][nt][0], c1 = acc[mf][nt][1];
            float c2 = acc[mf][nt][2], c3 = acc[mf][nt][3];
            out[(long)oc * NPIX + gx]           = c0;
            out[(long)oc * NPIX + gx + 1]       = c1;
            out[(long)(oc + 8) * NPIX + gx]     = c2;
            out[(long)(oc + 8) * NPIX + gx + 1] = c3;
            s[mf][0] += c0 + c1; q[mf][0] += c0 * c0 + c1 * c1;
            s[mf][1] += c2 + c3; q[mf][1] += c2 * c2 + c3 * c3;
        }
    }
#pragma unroll
    for (int mf = 0; mf < 2; mf++)
#pragma unroll
        for (int ro = 0; ro < 2; ro++) {
            float a = s[mf][ro], qq = q[mf][ro];
            a  += __shfl_xor_sync(0xffffffffu, a, 1);
            qq += __shfl_xor_sync(0xffffffffu, qq, 1);
            a  += __shfl_xor_sync(0xffffffffu, a, 2);
            qq += __shfl_xor_sync(0xffffffffu, qq, 2);
            if (tq == 0) {
                sRS[w * 32 + mf * 16 + ro * 8 + g] = a;
                sRQ[w * 32 + mf * 16 + ro * 8 + g] = qq;
            }
        }
    __syncthreads();
    if (t < 64) {
        int mw = t >> 5, cl = t & 31;
        float a  = sRS[(mw * 4 + 0) * 32 + cl] + sRS[(mw * 4 + 1) * 32 + cl] +
                   sRS[(mw * 4 + 2) * 32 + cl] + sRS[(mw * 4 + 3) * 32 + cl];
        float qq = sRQ[(mw * 4 + 0) * 32 + cl] + sRQ[(mw * 4 + 1) * 32 + cl] +
                   sRQ[(mw * 4 + 2) * 32 + cl] + sRQ[(mw * 4 + 3) * 32 + cl];
        int slot = b * 32 + ytile;
        p1[slot * Cout + ocg * 64 + t] = a;
        p2[slot * Cout + ocg * 64 + t] = qq;
    }
}

// ---------------- BN finalize ----------------
__global__ void finalize_kernel(const float* __restrict__ p1, const float* __restrict__ p2,
                                const float* __restrict__ g, const float* __restrict__ be,
                                float* __restrict__ A, float* __restrict__ B,
                                int C, int nslots) {
    const int c = blockIdx.x, t = threadIdx.x;
    float s = 0.f, q = 0.f;
    for (int slot = t; slot < nslots; slot += 128) {
        s += p1[slot * C + c];
        q += p2[slot * C + c];
    }
    __shared__ float rs[4], rq[4];
#pragma unroll
    for (int off = 16; off; off >>= 1) {
        s += __shfl_down_sync(0xffffffffu, s, off);
        q += __shfl_down_sync(0xffffffffu, q, off);
    }
    int lane = t & 31, wp = t >> 5;
    if (!lane) { rs[wp] = s; rq[wp] = q; }
    __syncthreads();
    if (t == 0) {
        s = rs[0] + rs[1] + rs[2] + rs[3];
        q = rq[0] + rq[1] + rq[2] + rq[3];
        const float inv = 1.f / (float)(BATCH * NPIX);
        float mean = s * inv;
        float var  = q * inv - mean * mean;
        float a = g[c] * rsqrtf(var + 1e-5f);
        A[c] = a;
        B[c] = be[c] - mean * a;
    }
}

// ---------------- 1x1 conv Cout=64 with input-BN + stats (aspp1) ----------------
__global__ void __launch_bounds__(256) conv1x1_bn_kernel(
    const float* __restrict__ in, const float* __restrict__ w,
    float* __restrict__ out, int Cin,
    const float* __restrict__ Abn, const float* __restrict__ Bbn,
    float* __restrict__ p1, float* __restrict__ p2)
{
    const int p0 = blockIdx.x * 64;
    const int b  = blockIdx.z;
    in  += (long)b * Cin * NPIX;
    out += (long)b * 64  * NPIX;
    const int t = threadIdx.x, tx = t & 15, ty = t >> 4;

    __shared__ float sW [16 * 68];
    __shared__ float sIn[16 * 64];

    float acc[4][4];
#pragma unroll
    for (int r = 0; r < 4; r++)
#pragma unroll
        for (int c = 0; c < 4; c++) acc[r][c] = 0.f;

    for (int ic0 = 0; ic0 < Cin; ic0 += 16) {
        __syncthreads();
        for (int idx = t; idx < 1024; idx += 256) {
            int ic = idx & 15, oc = idx >> 4;
            sW[ic * 68 + oc] = w[(long)oc * Cin + ic0 + ic];
        }
        for (int idx = t; idx < 1024; idx += 256) {
            int ic = idx >> 6, px = idx & 63;
            int c = ic0 + ic;
            float v = in[c * NPIX + p0 + px];
            sIn[idx] = fmaxf(v * Abn[c] + Bbn[c], 0.f);
        }
        __syncthreads();
#pragma unroll
        for (int ic = 0; ic < 16; ic++) {
            float4 a  = *(const float4*)(sW  + ic * 68 + ty * 4);
            float4 xv = *(const float4*)(sIn + ic * 64 + tx * 4);
            float av[4] = {a.x, a.y, a.z, a.w};
            float xa[4] = {xv.x, xv.y, xv.z, xv.w};
#pragma unroll
            for (int r = 0; r < 4; r++)
#pragma unroll
                for (int c = 0; c < 4; c++) acc[r][c] += av[r] * xa[c];
        }
    }
    float sums[4], sqs[4];
#pragma unroll
    for (int r = 0; r < 4; r++) {
        float s = 0.f, q = 0.f;
        float* op = out + (long)(ty * 4 + r) * NPIX + p0 + tx * 4;
#pragma unroll
        for (int c = 0; c < 4; c++) {
            float v = acc[r][c];
            op[c] = v; s += v; q += v * v;
        }
        sums[r] = s; sqs[r] = q;
    }
#pragma unroll
    for (int r = 0; r < 4; r++) {
        float a = sums[r], q = sqs[r];
#pragma unroll
        for (int off = 1; off < 16; off <<= 1) {
            a += __shfl_xor_sync(0xffffffffu, a, off);
            q += __shfl_xor_sync(0xffffffffu, q, off);
        }
        if (tx == 0) {
            int c = ty * 4 + r;
            int slot = b * 64 + blockIdx.x;
            p1[slot * 64 + c] = a;
            p2[slot * 64 + c] = q;
        }
    }
}

// ---------------- fused q/k/v 1x1 projections -> q plain + K'/V fragment layouts ----------------
__global__ void __launch_bounds__(256) qkv_kernel(
    const float* __restrict__ brin,
    const float* __restrict__ wq, const float* __restrict__ bq,
    const float* __restrict__ wk, const float* __restrict__ bk,
    const float* __restrict__ wv, const float* __restrict__ bv,
    float* __restrict__ qo, float* __restrict__ kf, float* __restrict__ vf,
    const float* __restrict__ Abase, const float* __restrict__ Bbase)
{
    const int p0  = blockIdx.x * 64;
    const int img = blockIdx.z;
    const int br  = img >> 2;
    const long ib = (long)img * 64 * NPIX;
    const float* A  = Abase + (2 + br) * 256;
    const float* Bb = Bbase + (2 + br) * 256;
    const int t = threadIdx.x, tx = t & 15, ty = t >> 4;

    float* kfp = kf + (long)img * 524288;   // [j 4096][128 paired]
    float* vfp = vf + (long)img * 262144;   // [d 64][kp 256][16 paired]

    __shared__ float sW [3 * 16 * 64];
    __shared__ float sIn[16 * 64];

    float acc[3][4][4];
#pragma unroll
    for (int m = 0; m < 3; m++)
#pragma unroll
        for (int r = 0; r < 4; r++)
#pragma unroll
            for (int c = 0; c < 4; c++) acc[m][r][c] = 0.f;

    for (int ic0 = 0; ic0 < 64; ic0 += 16) {
        __syncthreads();
        for (int i = t; i < 1024; i += 256) {
            int ic = i >> 6, px = i & 63;
            int c = ic0 + ic;
            float v = brin[ib + (long)c * NPIX + p0 + px];
            sIn[i] = fmaxf(v * A[c] + Bb[c], 0.f);
        }
        for (int i = t; i < 3072; i += 256) {
            int m = i >> 10, r = i & 1023;
            int ic = r & 15, oc = r >> 4;
            const float* wm = (m == 0) ? wq : ((m == 1) ? wk : wv);
            sW[m * 1024 + ic * 64 + oc] = wm[oc * 64 + ic0 + ic];
        }
        __syncthreads();
#pragma unroll
        for (int ic = 0; ic < 16; ic++) {
            float4 xv = *(const float4*)(sIn + ic * 64 + tx * 4);
            float xa[4] = {xv.x, xv.y, xv.z, xv.w};
#pragma unroll
            for (int m = 0; m < 3; m++) {
                float4 a = *(const float4*)(sW + m * 1024 + ic * 64 + ty * 4);
                float av[4] = {a.x, a.y, a.z, a.w};
#pragma unroll
                for (int r = 0; r < 4; r++)
#pragma unroll
                    for (int c = 0; c < 4; c++) acc[m][r][c] += av[r] * xa[c];
            }
        }
    }
    const float* bs[3] = {bq, bk, bv};
#pragma unroll
    for (int m = 0; m < 3; m++) {
#pragma unroll
        for (int r = 0; r < 4; r++) {
            int oc = ty * 4 + r;
            float bb = bs[m][oc];
#pragma unroll
            for (int ci = 0; ci < 4; ci++) {
                int j = p0 + tx * 4 + ci;
                float val = acc[m][r][ci] + bb;
                if (m == 0) {
                    qo[ib + (long)oc * NPIX + j] = val;            // plain q
                    int kk = 64 + oc, ks = kk >> 3, klo = kk & 7;
                    int slot = (ks >> 1) * 16 + (klo & 3) * 4 + (ks & 1) * 2 + (klo >> 2);
                    kfp[j * 128 + slot] = __uint_as_float(f2tf32(val));
                } else if (m == 1) {
                    int kk = oc, ks = kk >> 3, klo = kk & 7;
                    int slot = (ks >> 1) * 16 + (klo & 3) * 4 + (ks & 1) * 2 + (klo >> 2);
                    kfp[j * 128 + slot] = __uint_as_float(f2tf32(val));
                } else {
                    int ksv = j >> 3, jlo = j & 7;
                    int slot = (jlo & 3) * 4 + (ksv & 1) * 2 + (jlo >> 2);
                    vfp[(oc * 256 + (ksv >> 1)) * 16 + slot] = __uint_as_float(f2tf32(val));
                }
            }
        }
    }
}

// ---------------- pos table ----------------
__global__ void pos_kernel(const float* __restrict__ rh, const float* __restrict__ rw) {
    int idx = blockIdx.x * blockDim.x + threadIdx.x;
    if (idx >= 64 * NPIX) return;
    int d = idx >> 12, n = idx & 4095, a = n >> 6, bb = n & 63;
    g_pos[idx] = rh[d * 64 + bb] + rw[d * 64 + a];
}

// ================= fragment-direct tf32 flash attention =================
// Loads B-fragments straight from gmem (L2) fragment-paired layouts; no staging,
// no __syncthreads in mainloop (sP is per-warp).
#define FLASH3_SMEM (8192 * 4)

__global__ void __launch_bounds__(256, 1) flash_mma_kernel(
    const float* __restrict__ qg, const float* __restrict__ kf,
    const float* __restrict__ vf, float* __restrict__ outg)
{
    extern __shared__ uint32_t smu[];
    uint32_t* sP = smu;   // [warp 8][ks 8][i 16][8 interleaved]

    const int i0 = blockIdx.x * 128;
    const int b  = blockIdx.y, br = blockIdx.z;
    const int img = br * BATCH + b;
    const float* q = qg + (long)img * 64 * NPIX;
    const uint4* KF = (const uint4*)(kf + (long)img * 524288);  // [j][kp 8][uint4: tq]
    const uint4* VF = (const uint4*)(vf + (long)img * 262144);  // [d][kp 256][uint4: tq]
    float* outp = outg + (long)(b * 256 + br * 64) * NPIX;

    const int t = threadIdx.x;
    const int lane = t & 31, w = t >> 5;
    const int g = lane >> 2, tq = lane & 3;

    // ---- Q' fragments (regs, whole kernel) ----
    uint32_t Qf[16][4];
    {
        int i_r = i0 + w * 16 + g;
#pragma unroll
        for (int ks = 0; ks < 16; ks++) {
            int kc = ks * 8 + tq;
            const float* s0 = (kc < 64)     ? (q + kc * NPIX)       : (g_pos + (kc - 64) * NPIX);
            const float* s1 = (kc + 4 < 64) ? (q + (kc + 4) * NPIX) : (g_pos + (kc - 60) * NPIX);
            Qf[ks][0] = f2tf32(s0[i_r]);
            Qf[ks][1] = f2tf32(s0[i_r + 8]);
            Qf[ks][2] = f2tf32(s1[i_r]);
            Qf[ks][3] = f2tf32(s1[i_r + 8]);
        }
    }

    float Oa[8][4];
#pragma unroll
    for (int nt = 0; nt < 8; nt++)
#pragma unroll
        for (int c = 0; c < 4; c++) Oa[nt][c] = 0.f;
    float m0 = -CUDART_INF_F, m1 = -CUDART_INF_F, l0 = 0.f, l1 = 0.f;

    const int p00 = ((2 * tq) & 3) * 2 + (tq >> 1);
    const int p01 = ((2 * tq + 1) & 3) * 2 + ((2 * tq + 1) >> 2);
    const int pb  = w * 1024 + g * 8;

    for (int j0 = 0; j0 < NPIX; j0 += 64) {
        // ---- S = Q' K' (fragments direct from gmem) ----
        float Sa[8][4];
#pragma unroll
        for (int nt = 0; nt < 8; nt++)
#pragma unroll
            for (int c = 0; c < 4; c++) Sa[nt][c] = 0.f;
#pragma unroll
        for (int kp = 0; kp < 8; kp++) {
#pragma unroll
            for (int nt = 0; nt < 8; nt++) {
                uint4 kb = KF[(j0 + nt * 8 + g) * 32 + kp * 4 + tq];
                mma8(Sa[nt], Qf[2 * kp],     kb.x, kb.y);
                mma8(Sa[nt], Qf[2 * kp + 1], kb.z, kb.w);
            }
        }

        // ---- online softmax ----
        float mx0 = -CUDART_INF_F, mx1 = -CUDART_INF_F;
#pragma unroll
        for (int nt = 0; nt < 8; nt++) {
            mx0 = fmaxf(mx0, fmaxf(Sa[nt][0], Sa[nt][1]));
            mx1 = fmaxf(mx1, fmaxf(Sa[nt][2], Sa[nt][3]));
        }
        mx0 = fmaxf(mx0, __shfl_xor_sync(0xffffffffu, mx0, 1));
        mx0 = fmaxf(mx0, __shfl_xor_sync(0xffffffffu, mx0, 2));
        mx1 = fmaxf(mx1, __shfl_xor_sync(0xffffffffu, mx1, 1));
        mx1 = fmaxf(mx1, __shfl_xor_sync(0xffffffffu, mx1, 2));
        float mn0 = fmaxf(m0, mx0), mn1 = fmaxf(m1, mx1);
        float al0 = __expf(m0 - mn0), al1 = __expf(m1 - mn1);

        float su0 = 0.f, su1 = 0.f;
#pragma unroll
        for (int nt = 0; nt < 8; nt++) {
            float e00 = __expf(Sa[nt][0] - mn0);
            float e01 = __expf(Sa[nt][1] - mn0);
            float e10 = __expf(Sa[nt][2] - mn1);
            float e11 = __expf(Sa[nt][3] - mn1);
            su0 += e00 + e01; su1 += e10 + e11;
            sP[pb + nt * 128 + p00]      = f2tf32(e00);
            sP[pb + nt * 128 + p01]      = f2tf32(e01);
            sP[pb + nt * 128 + 64 + p00] = f2tf32(e10);
            sP[pb + nt * 128 + 64 + p01] = f2tf32(e11);
        }
        su0 += __shfl_xor_sync(0xffffffffu, su0, 1);
        su0 += __shfl_xor_sync(0xffffffffu, su0, 2);
        su1 += __shfl_xor_sync(0xffffffffu, su1, 1);
        su1 += __shfl_xor_sync(0xffffffffu, su1, 2);
        l0 = l0 * al0 + su0; l1 = l1 * al1 + su1;
        m0 = mn0; m1 = mn1;
#pragma unroll
        for (int nt = 0; nt < 8; nt++) {
            Oa[nt][0] *= al0; Oa[nt][1] *= al0;
            Oa[nt][2] *= al1; Oa[nt][3] *= al1;
        }
        __syncwarp();

        // ---- O += P V (A from sP, B fragments direct from gmem) ----
#pragma unroll
        for (int kpl = 0; kpl < 4; kpl++) {
            const uint32_t* ape = &sP[w * 1024 + (2 * kpl) * 128 + g * 8 + 2 * tq];
            uint2 e02 = *(const uint2*)ape;
            uint2 e13 = *(const uint2*)(ape + 64);
            uint2 o02 = *(const uint2*)(ape + 128);
            uint2 o13 = *(const uint2*)(ape + 192);
            uint32_t ae[4] = {e02.x, e13.x, e02.y, e13.y};
            uint32_t ao[4] = {o02.x, o13.x, o02.y, o13.y};
#pragma unroll
            for (int nt = 0; nt < 8; nt++) {
                uint4 vb = VF[((nt * 8 + g) * 256 + (j0 >> 4) + kpl) * 4 + tq];
                mma8(Oa[nt], ae, vb.x, vb.y);
                mma8(Oa[nt], ao, vb.z, vb.w);
            }
        }
        __syncwarp();
    }

    float inv0 = 1.f / l0, inv1 = 1.f / l1;
    int pix = i0 + w * 16 + g;
#pragma unroll
    for (int nt = 0; nt < 8; nt++) {
        int d0 = nt * 8 + 2 * tq;
        outp[(long)d0 * NPIX + pix]           = Oa[nt][0] * inv0;
        outp[(long)(d0 + 1) * NPIX + pix]     = Oa[nt][1] * inv0;
        outp[(long)d0 * NPIX + pix + 8]       = Oa[nt][2] * inv1;
        outp[(long)(d0 + 1) * NPIX + pix + 8] = Oa[nt][3] * inv1;
    }
}

// ---------------- host orchestration ----------------
extern "C" void kernel_launch(void* const* d_in, const int* in_sizes, int n_in,
                              void* d_out, int out_size) {
    const float* x      = (const float*)d_in[0];
    const float* dc_w1  = (const float*)d_in[1];
    const float* dc_g1  = (const float*)d_in[3];
    const float* dc_be1 = (const float*)d_in[4];
    const float* dc_w2  = (const float*)d_in[5];
    const float* dc_g2  = (const float*)d_in[7];
    const float* dc_be2 = (const float*)d_in[8];
    const float* aw[4]  = {(const float*)d_in[9],  (const float*)d_in[12],
                           (const float*)d_in[15], (const float*)d_in[18]};
    const float* ag[4]  = {(const float*)d_in[10], (const float*)d_in[13],
                           (const float*)d_in[16], (const float*)d_in[19]};
    const float* ab[4]  = {(const float*)d_in[11], (const float*)d_in[14],
                           (const float*)d_in[17], (const float*)d_in[20]};
    const float* wq = (const float*)d_in[21]; const float* bq = (const float*)d_in[22];
    const float* wk = (const float*)d_in[23]; const float* bk = (const float*)d_in[24];
    const float* wv = (const float*)d_in[25]; const float* bv = (const float*)d_in[26];
    const float* rel_h = (const float*)d_in[27];
    const float* rel_w = (const float*)d_in[28];

    float *pool, *buf1, *buf2, *brb, *qb, *kfb, *vfb, *p1, *p2, *An, *Bn, *wt;
    cudaGetSymbolAddress((void**)&pool, g_pool);
    cudaGetSymbolAddress((void**)&buf1, g_buf1);
    cudaGetSymbolAddress((void**)&buf2, g_buf2);
    cudaGetSymbolAddress((void**)&brb,  g_br);
    cudaGetSymbolAddress((void**)&qb,   g_q);
    cudaGetSymbolAddress((void**)&kfb,  g_kf);
    cudaGetSymbolAddress((void**)&vfb,  g_vf);
    cudaGetSymbolAddress((void**)&p1,   g_p1);
    cudaGetSymbolAddress((void**)&p2,   g_p2);
    cudaGetSymbolAddress((void**)&An,   g_An);
    cudaGetSymbolAddress((void**)&Bn,   g_Bn);
    cudaGetSymbolAddress((void**)&wt,   g_wt);

    float* wt1 = wt;                 // conv1: 589824
    float* wt2 = wt + 589824;        // conv2: 1179648
    float* wtA = wt + 1769472;       // aspp 3x3 convs: 3 x 294912

    cudaFuncSetAttribute((const void*)conv_mma_kernel<false>,
                         cudaFuncAttributeMaxDynamicSharedMemorySize, CONV_SMEM);
    cudaFuncSetAttribute((const void*)conv_mma_kernel<true>,
                         cudaFuncAttributeMaxDynamicSharedMemorySize, CONV_SMEM);
    cudaFuncSetAttribute((const void*)flash_mma_kernel,
                         cudaFuncAttributeMaxDynamicSharedMemorySize, FLASH3_SMEM);

    // weight prep (tf32 hi/lo, fragment-swizzled)
    wprep_kernel<<<(256 * 128 * 9 + 255) / 256, 256>>>(dc_w1, wt1, 128, 256);
    wprep_kernel<<<(256 * 256 * 9 + 255) / 256, 256>>>(dc_w2, wt2, 256, 256);
    for (int i = 0; i < 3; i++)
        wprep_kernel<<<(64 * 256 * 9 + 255) / 256, 256>>>(
            aw[i + 1], wtA + (long)i * 294912, 256, 64);

    // mpconv
    maxpool_kernel<<<(BATCH * 128 * NPIX + 255) / 256, 256>>>(x, pool);
    conv_mma_kernel<false><<<dim3(32, 4, BATCH), 256, CONV_SMEM>>>(
        pool, wt1, buf1, 128, nullptr, nullptr, p1, p2);
    finalize_kernel<<<256, 128>>>(p1, p2, dc_g1, dc_be1, An + 0, Bn + 0, 256, 128);
    conv_mma_kernel<false><<<dim3(32, 4, BATCH), 256, CONV_SMEM>>>(
        buf1, wt2, buf2, 256, An + 0, Bn + 0, p1, p2);
    finalize_kernel<<<256, 128>>>(p1, p2, dc_g2, dc_be2, An + 256, Bn + 256, 256, 128);

    // ASPP dilated branches (2,3,4) fused; 1x1 branch separate
    conv_mma_kernel<true><<<dim3(32, 3, BATCH), 256, CONV_SMEM>>>(
        buf2, wtA, brb + (long)BATCH * 64 * NPIX, 256, An + 256, Bn + 256, p1, p2);
    for (int i = 0; i < 3; i++)
        finalize_kernel<<<64, 128>>>(p1 + i * 8192, p2 + i * 8192, ag[i + 1], ab[i + 1],
                                     An + (3 + i) * 256, Bn + (3 + i) * 256, 64, 128);
    conv1x1_bn_kernel<<<dim3(64, 1, BATCH), 256>>>(
        buf2, aw[0], brb, 256, An + 256, Bn + 256, p1 + 32768, p2 + 32768);
    finalize_kernel<<<64, 128>>>(p1 + 32768, p2 + 32768, ag[0], ab[0],
                                 An + 2 * 256, Bn + 2 * 256, 64, 256);

    // fused qkv -> q plain + K'/V fragment layouts; pos table
    qkv_kernel<<<dim3(64, 1, 16), 256>>>(brb, wq, bq, wk, bk, wv, bv,
                                         qb, kfb, vfb, An, Bn);
    pos_kernel<<<(64 * NPIX + 255) / 256, 256>>>(rel_h, rel_w);

    // fragment-direct flash attention -> concat output
    flash_mma_kernel<<<dim3(32, BATCH, 4), 256, FLASH3_SMEM>>>(
        qb, kfb, vfb, (float*)d_out);
}

// round 9
// speedup vs baseline: 2.2156x; 1.0518x over previous
#include <cuda_runtime.h>
#include <math_constants.h>
#include <stdint.h>

#define BATCH 4
#define NPIX 4096   // 64*64

// ---------------- scratch (device globals; no cudaMalloc allowed) ----------------
__device__ float g_pool[BATCH * 128 * NPIX];
__device__ float g_buf1[BATCH * 256 * NPIX];
__device__ float g_buf2[BATCH * 256 * NPIX];
__device__ float g_br  [4 * BATCH * 64 * NPIX];
__device__ float g_q   [4 * BATCH * 64 * NPIX];   // plain q (for Q' fragments)
__device__ float g_kf  [16 * 4096 * 128];         // K' fragment-paired tf32
__device__ float g_vf  [16 * 64 * 256 * 16];      // V  fragment-paired tf32
__device__ float g_pos [64 * NPIX];
__device__ float g_p1  [256 * 256];
__device__ float g_p2  [256 * 256];
__device__ float g_An  [6 * 256];
__device__ float g_Bn  [6 * 256];
__device__ float g_wt  [2654208];   // pre-swizzled tf32 hi/lo conv weights

__device__ __forceinline__ uint32_t f2tf32(float f) {
    uint32_t u;
    asm("cvt.rna.tf32.f32 %0, %1;" : "=r"(u) : "f"(f));
    return u;
}
__device__ __forceinline__ void mma8(float d[4], const uint32_t a[4],
                                     uint32_t b0, uint32_t b1) {
    asm volatile(
        "mma.sync.aligned.m16n8k8.row.col.f32.tf32.tf32.f32 "
        "{%0,%1,%2,%3},{%4,%5,%6,%7},{%8,%9},{%0,%1,%2,%3};"
        : "+f"(d[0]), "+f"(d[1]), "+f"(d[2]), "+f"(d[3])
        : "r"(a[0]), "r"(a[1]), "r"(a[2]), "r"(a[3]), "r"(b0), "r"(b1));
}
__device__ __forceinline__ int ilv(int klo) { return (klo & 3) * 2 + (klo >> 2); }

// ---------------- maxpool 2x2 ----------------
__global__ void maxpool_kernel(const float* __restrict__ x, float* __restrict__ out) {
    int idx = blockIdx.x * blockDim.x + threadIdx.x;
    if (idx >= BATCH * 128 * NPIX) return;
    int p  = idx & (NPIX - 1);
    int bc = idx >> 12;
    int y = p >> 6, xx = p & 63;
    const float* src = x + ((long)bc * 128 + 2 * y) * 128 + 2 * xx;
    out[idx] = fmaxf(fmaxf(src[0], src[1]), fmaxf(src[128], src[129]));
}

// ---------------- weight prep: OIHW -> [ocg][chunk][hi/lo][tap][oc64][ilv8] ----------------
__global__ void wprep_kernel(const float* __restrict__ W, float* __restrict__ dst,
                             int Cin, int Cout) {
    int idx = blockIdx.x * 256 + threadIdx.x;
    int total = Cout * Cin * 9;
    if (idx >= total) return;
    int tap = idx % 9;
    int rem = idx / 9;
    int ic  = rem % Cin;
    int oc  = rem / Cin;
    float wv = W[idx];
    float hi = __uint_as_float(f2tf32(wv));
    float lo = __uint_as_float(f2tf32(wv - hi));
    int ocg = oc >> 6, oc64 = oc & 63, chunk = ic >> 3, klo = ic & 7;
    int nch = Cin >> 3;
    long base = (long)(ocg * nch + chunk) * 9216;
    dst[base +        (tap * 64 + oc64) * 8 + ilv(klo)] = hi;
    dst[base + 4608 + (tap * 64 + oc64) * 8 + ilv(klo)] = lo;
}

// ======== tensor-core 3x3 dilated conv, 4-row CTA tiles + cp.async weights ========
// CTA: 256 thr = 8 warps (mwarp = w>>2 in {0,1}, yr = w&3 in {0..3}).
// CTA tile: 64 oc x 256 px (4 y rows). warp tile: m32 x n64 (8 n-tiles).
// K-chunks of 8 ic, 9 taps, weights hi+lo accumulate into same acc (exact weights).
// sIn: [ic 8][ky 3][yr 4][88] stride 1064/ic, zero x-halos. sW 9216. sRed 512.
#define CONV_SMEM (18240 * 4)
template<bool ASPP>
__global__ void __launch_bounds__(256, 2) conv_mma_kernel(
    const float* __restrict__ in, const float* __restrict__ wtbase,
    float* __restrict__ outbase, int Cin,
    const float* __restrict__ Abn, const float* __restrict__ Bbn,
    float* __restrict__ p1base, float* __restrict__ p2base)
{
    extern __shared__ float sm[];
    float* sIn = sm;             // 8 * 1064
    float* sW  = sm + 8512;      // [hl][tap][oc64][8]
    float* sRS = sm + 17728;     // [8 warps][32]
    float* sRQ = sm + 17984;

    const int ytile = blockIdx.x;      // 0..15
    const int b     = blockIdx.z;
    const int nchunk = Cin >> 3;
    int dil, ocg, Cout;
    const float* wt;
    float* out;
    float *p1, *p2;
    if (ASPP) {
        int br = blockIdx.y;           // 0..2 -> dil 3,6,9
        dil = 3 * (br + 1); ocg = 0; Cout = 64;
        wt  = wtbase + (long)br * 294912;
        out = outbase + ((long)br * BATCH + b) * 64 * NPIX;
        p1  = p1base + br * 8192;
        p2  = p2base + br * 8192;
    } else {
        dil = 1; ocg = blockIdx.y; Cout = gridDim.y * 64;
        wt  = wtbase + (long)ocg * nchunk * 9216;
        out = outbase + (long)b * Cout * NPIX;
        p1  = p1base; p2 = p2base;
    }
    in += (long)b * Cin * NPIX;

    const int t = threadIdx.x, lane = t & 31, w = t >> 5;
    const int g = lane >> 2, tq = lane & 3;
    const int mwarp = w >> 2;
    const int yr    = w & 3;
    const int y0    = ytile * 4;

    const uint32_t swu = (uint32_t)__cvta_generic_to_shared(sW);

    for (int i = t; i < 8512; i += 256) sIn[i] = 0.f;

    float acc[2][8][4];
#pragma unroll
    for (int mf = 0; mf < 2; mf++)
#pragma unroll
        for (int nt = 0; nt < 8; nt++)
#pragma unroll
            for (int c = 0; c < 4; c++) acc[mf][nt][c] = 0.f;

    for (int chunk = 0; chunk < nchunk; chunk++) {
        __syncthreads();
        // ---- weights: cp.async copy of pre-swizzled block (overlaps input staging) ----
        {
            const float4* ws = (const float4*)(wt + (long)chunk * 9216);
#pragma unroll
            for (int i = t; i < 2304; i += 256)
                asm volatile("cp.async.cg.shared.global [%0], [%1], 16;\n"
                             :: "r"(swu + i * 16), "l"(ws + i));
            asm volatile("cp.async.commit_group;\n");
        }
        // ---- input rows: 8 ic x 12 (3ky x 4yr) x 64, BN+ReLU + tf32 on load ----
        {
            const int ic0 = chunk * 8;
#pragma unroll
            for (int i = t; i < 6144; i += 256) {
                int col = i & 63;
                int row = i >> 6;            // 0..95
                int ic  = row / 12;
                int r2  = row - ic * 12;
                int ky  = r2 >> 2, yri = r2 & 3;
                int ry  = y0 + yri + (ky - 1) * dil;
                float v = 0.f;
                if (ry >= 0 && ry < 64) {
                    int c = ic0 + ic;
                    v = in[c * NPIX + ry * 64 + col];
                    if (Abn) v = fmaxf(v * Abn[c] + Bbn[c], 0.f);
                }
                sIn[ic * 1064 + (ky * 4 + yri) * 88 + 12 + col] =
                    __uint_as_float(f2tf32(v));
            }
        }
        asm volatile("cp.async.wait_group 0;\n" ::: "memory");
        __syncthreads();

        // ---- 9 taps x (hi+lo) x 8 n-tiles ----
#pragma unroll
        for (int tap = 0; tap < 9; tap++) {
            const int ky = tap / 3, kx = tap % 3;
            const uint32_t* bp = (const uint32_t*)(sIn) +
                tq * 1064 + (ky * 4 + yr) * 88 + 12 + g + (kx - 1) * dil;
            const float* wb = sW + (tap * 64 + mwarp * 32 + g) * 8 + 2 * tq;
            uint2 h0  = *(const uint2*)(wb);
            uint2 h0b = *(const uint2*)(wb + 64);
            uint2 h1  = *(const uint2*)(wb + 128);
            uint2 h1b = *(const uint2*)(wb + 192);
            uint2 l0  = *(const uint2*)(wb + 4608);
            uint2 l0b = *(const uint2*)(wb + 4672);
            uint2 l1  = *(const uint2*)(wb + 4736);
            uint2 l1b = *(const uint2*)(wb + 4800);
            uint32_t aH0[4] = {h0.x, h0b.x, h0.y, h0b.y};
            uint32_t aH1[4] = {h1.x, h1b.x, h1.y, h1b.y};
            uint32_t aL0[4] = {l0.x, l0b.x, l0.y, l0b.y};
            uint32_t aL1[4] = {l1.x, l1b.x, l1.y, l1b.y};
#pragma unroll
            for (int nt = 0; nt < 8; nt++) {
                uint32_t b0 = bp[nt * 8];
                uint32_t b1 = bp[nt * 8 + 4256];
                mma8(acc[0][nt], aH0, b0, b1);
                mma8(acc[0][nt], aL0, b0, b1);
                mma8(acc[1][nt], aH1, b0, b1);
                mma8(acc[1][nt], aL1, b0, b1);
            }
        }
    }

    // ---- epilogue: store + BN partials ----
    float s[2][2] = {{0.f, 0.f}, {0.f, 0.f}};
    float q[2][2] = {{0.f, 0.f}, {0.f, 0.f}};
    const int ocb = ocg * 64 + mwarp * 32;
#pragma unroll
    for (int mf = 0; mf < 2; mf++) {
        int oc = ocb + mf * 16 + g;
#pragma unroll
        for (int nt = 0; nt < 8; nt++) {
            int gx = (y0 + yr) * 64 + nt * 8 + 2 * tq;
            float c0 = acc[mf][nt][0], c1 = acc[mf][nt][1];
            float c2 = acc[mf][nt][2], c3 = acc[mf][nt][3];
            out[(long)oc * NPIX + gx]           = c0;
            out[(long)oc * NPIX + gx + 1]       = c1;
            out[(long)(oc + 8) * NPIX + gx]     = c2;
            out[(long)(oc + 8) * NPIX + gx + 1] = c3;
            s[mf][0] += c0 + c1; q[mf][0] += c0 * c0 + c1 * c1;
            s[mf][1] += c2 + c3; q[mf][1] += c2 * c2 + c3 * c3;
        }
    }
#pragma unroll
    for (int mf = 0; mf < 2; mf++)
#pragma unroll
        for (int ro = 0; ro < 2; ro++) {
            float a = s[mf][ro], qq = q[mf][ro];
            a  += __shfl_xor_sync(0xffffffffu, a, 1);
            qq += __shfl_xor_sync(0xffffffffu, qq, 1);
            a  += __shfl_xor_sync(0xffffffffu, a, 2);
            qq += __shfl_xor_sync(0xffffffffu, qq, 2);
            if (tq == 0) {
                sRS[w * 32 + mf * 16 + ro * 8 + g] = a;
                sRQ[w * 32 + mf * 16 + ro * 8 + g] = qq;
            }
        }
    __syncthreads();
    if (t < 64) {
        int mw = t >> 5, cl = t & 31;
        float a  = sRS[(mw * 4 + 0) * 32 + cl] + sRS[(mw * 4 + 1) * 32 + cl] +
                   sRS[(mw * 4 + 2) * 32 + cl] + sRS[(mw * 4 + 3) * 32 + cl];
        float qq = sRQ[(mw * 4 + 0) * 32 + cl] + sRQ[(mw * 4 + 1) * 32 + cl] +
                   sRQ[(mw * 4 + 2) * 32 + cl] + sRQ[(mw * 4 + 3) * 32 + cl];
        int slot = b * 16 + ytile;
        p1[slot * Cout + ocg * 64 + t] = a;
        p2[slot * Cout + ocg * 64 + t] = qq;
    }
}

// ---------------- BN finalize ----------------
__global__ void finalize_kernel(const float* __restrict__ p1, const float* __restrict__ p2,
                                const float* __restrict__ g, const float* __restrict__ be,
                                float* __restrict__ A, float* __restrict__ B,
                                int C, int nslots) {
    const int c = blockIdx.x, t = threadIdx.x;
    float s = 0.f, q = 0.f;
    for (int slot = t; slot < nslots; slot += 128) {
        s += p1[slot * C + c];
        q += p2[slot * C + c];
    }
    __shared__ float rs[4], rq[4];
#pragma unroll
    for (int off = 16; off; off >>= 1) {
        s += __shfl_down_sync(0xffffffffu, s, off);
        q += __shfl_down_sync(0xffffffffu, q, off);
    }
    int lane = t & 31, wp = t >> 5;
    if (!lane) { rs[wp] = s; rq[wp] = q; }
    __syncthreads();
    if (t == 0) {
        s = rs[0] + rs[1] + rs[2] + rs[3];
        q = rq[0] + rq[1] + rq[2] + rq[3];
        const float inv = 1.f / (float)(BATCH * NPIX);
        float mean = s * inv;
        float var  = q * inv - mean * mean;
        float a = g[c] * rsqrtf(var + 1e-5f);
        A[c] = a;
        B[c] = be[c] - mean * a;
    }
}

// ---------------- 1x1 conv Cout=64 with input-BN + stats (aspp1) ----------------
__global__ void __launch_bounds__(256) conv1x1_bn_kernel(
    const float* __restrict__ in, const float* __restrict__ w,
    float* __restrict__ out, int Cin,
    const float* __restrict__ Abn, const float* __restrict__ Bbn,
    float* __restrict__ p1, float* __restrict__ p2)
{
    const int p0 = blockIdx.x * 64;
    const int b  = blockIdx.z;
    in  += (long)b * Cin * NPIX;
    out += (long)b * 64  * NPIX;
    const int t = threadIdx.x, tx = t & 15, ty = t >> 4;

    __shared__ float sW [16 * 68];
    __shared__ float sIn[16 * 64];

    float acc[4][4];
#pragma unroll
    for (int r = 0; r < 4; r++)
#pragma unroll
        for (int c = 0; c < 4; c++) acc[r][c] = 0.f;

    for (int ic0 = 0; ic0 < Cin; ic0 += 16) {
        __syncthreads();
        for (int idx = t; idx < 1024; idx += 256) {
            int ic = idx & 15, oc = idx >> 4;
            sW[ic * 68 + oc] = w[(long)oc * Cin + ic0 + ic];
        }
        for (int idx = t; idx < 1024; idx += 256) {
            int ic = idx >> 6, px = idx & 63;
            int c = ic0 + ic;
            float v = in[c * NPIX + p0 + px];
            sIn[idx] = fmaxf(v * Abn[c] + Bbn[c], 0.f);
        }
        __syncthreads();
#pragma unroll
        for (int ic = 0; ic < 16; ic++) {
            float4 a  = *(const float4*)(sW  + ic * 68 + ty * 4);
            float4 xv = *(const float4*)(sIn + ic * 64 + tx * 4);
            float av[4] = {a.x, a.y, a.z, a.w};
            float xa[4] = {xv.x, xv.y, xv.z, xv.w};
#pragma unroll
            for (int r = 0; r < 4; r++)
#pragma unroll
                for (int c = 0; c < 4; c++) acc[r][c] += av[r] * xa[c];
        }
    }
    float sums[4], sqs[4];
#pragma unroll
    for (int r = 0; r < 4; r++) {
        float s = 0.f, q = 0.f;
        float* op = out + (long)(ty * 4 + r) * NPIX + p0 + tx * 4;
#pragma unroll
        for (int c = 0; c < 4; c++) {
            float v = acc[r][c];
            op[c] = v; s += v; q += v * v;
        }
        sums[r] = s; sqs[r] = q;
    }
#pragma unroll
    for (int r = 0; r < 4; r++) {
        float a = sums[r], q = sqs[r];
#pragma unroll
        for (int off = 1; off < 16; off <<= 1) {
            a += __shfl_xor_sync(0xffffffffu, a, off);
            q += __shfl_xor_sync(0xffffffffu, q, off);
        }
        if (tx == 0) {
            int c = ty * 4 + r;
            int slot = b * 64 + blockIdx.x;
            p1[slot * 64 + c] = a;
            p2[slot * 64 + c] = q;
        }
    }
}

// ---------------- fused q/k/v 1x1 projections -> q plain + K'/V fragment layouts ----------------
__global__ void __launch_bounds__(256) qkv_kernel(
    const float* __restrict__ brin,
    const float* __restrict__ wq, const float* __restrict__ bq,
    const float* __restrict__ wk, const float* __restrict__ bk,
    const float* __restrict__ wv, const float* __restrict__ bv,
    float* __restrict__ qo, float* __restrict__ kf, float* __restrict__ vf,
    const float* __restrict__ Abase, const float* __restrict__ Bbase)
{
    const int p0  = blockIdx.x * 64;
    const int img = blockIdx.z;
    const int br  = img >> 2;
    const long ib = (long)img * 64 * NPIX;
    const float* A  = Abase + (2 + br) * 256;
    const float* Bb = Bbase + (2 + br) * 256;
    const int t = threadIdx.x, tx = t & 15, ty = t >> 4;

    float* kfp = kf + (long)img * 524288;   // [j 4096][128 paired]
    float* vfp = vf + (long)img * 262144;   // [d 64][kp 256][16 paired]

    __shared__ float sW [3 * 16 * 64];
    __shared__ float sIn[16 * 64];

    float acc[3][4][4];
#pragma unroll
    for (int m = 0; m < 3; m++)
#pragma unroll
        for (int r = 0; r < 4; r++)
#pragma unroll
            for (int c = 0; c < 4; c++) acc[m][r][c] = 0.f;

    for (int ic0 = 0; ic0 < 64; ic0 += 16) {
        __syncthreads();
        for (int i = t; i < 1024; i += 256) {
            int ic = i >> 6, px = i & 63;
            int c = ic0 + ic;
            float v = brin[ib + (long)c * NPIX + p0 + px];
            sIn[i] = fmaxf(v * A[c] + Bb[c], 0.f);
        }
        for (int i = t; i < 3072; i += 256) {
            int m = i >> 10, r = i & 1023;
            int ic = r & 15, oc = r >> 4;
            const float* wm = (m == 0) ? wq : ((m == 1) ? wk : wv);
            sW[m * 1024 + ic * 64 + oc] = wm[oc * 64 + ic0 + ic];
        }
        __syncthreads();
#pragma unroll
        for (int ic = 0; ic < 16; ic++) {
            float4 xv = *(const float4*)(sIn + ic * 64 + tx * 4);
            float xa[4] = {xv.x, xv.y, xv.z, xv.w};
#pragma unroll
            for (int m = 0; m < 3; m++) {
                float4 a = *(const float4*)(sW + m * 1024 + ic * 64 + ty * 4);
                float av[4] = {a.x, a.y, a.z, a.w};
#pragma unroll
                for (int r = 0; r < 4; r++)
#pragma unroll
                    for (int c = 0; c < 4; c++) acc[m][r][c] += av[r] * xa[c];
            }
        }
    }
    const float* bs[3] = {bq, bk, bv};
#pragma unroll
    for (int m = 0; m < 3; m++) {
#pragma unroll
        for (int r = 0; r < 4; r++) {
            int oc = ty * 4 + r;
            float bb = bs[m][oc];
#pragma unroll
            for (int ci = 0; ci < 4; ci++) {
                int j = p0 + tx * 4 + ci;
                float val = acc[m][r][ci] + bb;
                if (m == 0) {
                    qo[ib + (long)oc * NPIX + j] = val;            // plain q
                    int kk = 64 + oc, ks = kk >> 3, klo = kk & 7;
                    int slot = (ks >> 1) * 16 + (klo & 3) * 4 + (ks & 1) * 2 + (klo >> 2);
                    kfp[j * 128 + slot] = __uint_as_float(f2tf32(val));
                } else if (m == 1) {
                    int kk = oc, ks = kk >> 3, klo = kk & 7;
                    int slot = (ks >> 1) * 16 + (klo & 3) * 4 + (ks & 1) * 2 + (klo >> 2);
                    kfp[j * 128 + slot] = __uint_as_float(f2tf32(val));
                } else {
                    int ksv = j >> 3, jlo = j & 7;
                    int slot = (jlo & 3) * 4 + (ksv & 1) * 2 + (jlo >> 2);
                    vfp[(oc * 256 + (ksv >> 1)) * 16 + slot] = __uint_as_float(f2tf32(val));
                }
            }
        }
    }
}

// ---------------- pos table ----------------
__global__ void pos_kernel(const float* __restrict__ rh, const float* __restrict__ rw) {
    int idx = blockIdx.x * blockDim.x + threadIdx.x;
    if (idx >= 64 * NPIX) return;
    int d = idx >> 12, n = idx & 4095, a = n >> 6, bb = n & 63;
    g_pos[idx] = rh[d * 64 + bb] + rw[d * 64 + a];
}

// ================= fragment-direct tf32 flash attention =================
#define FLASH3_SMEM (8192 * 4)

__global__ void __launch_bounds__(256, 1) flash_mma_kernel(
    const float* __restrict__ qg, const float* __restrict__ kf,
    const float* __restrict__ vf, float* __restrict__ outg)
{
    extern __shared__ uint32_t smu[];
    uint32_t* sP = smu;   // [warp 8][ks 8][i 16][8 interleaved]

    const int i0 = blockIdx.x * 128;
    const int b  = blockIdx.y, br = blockIdx.z;
    const int img = br * BATCH + b;
    const float* q = qg + (long)img * 64 * NPIX;
    const uint4* KF = (const uint4*)(kf + (long)img * 524288);
    const uint4* VF = (const uint4*)(vf + (long)img * 262144);
    float* outp = outg + (long)(b * 256 + br * 64) * NPIX;

    const int t = threadIdx.x;
    const int lane = t & 31, w = t >> 5;
    const int g = lane >> 2, tq = lane & 3;

    uint32_t Qf[16][4];
    {
        int i_r = i0 + w * 16 + g;
#pragma unroll
        for (int ks = 0; ks < 16; ks++) {
            int kc = ks * 8 + tq;
            const float* s0 = (kc < 64)     ? (q + kc * NPIX)       : (g_pos + (kc - 64) * NPIX);
            const float* s1 = (kc + 4 < 64) ? (q + (kc + 4) * NPIX) : (g_pos + (kc - 60) * NPIX);
            Qf[ks][0] = f2tf32(s0[i_r]);
            Qf[ks][1] = f2tf32(s0[i_r + 8]);
            Qf[ks][2] = f2tf32(s1[i_r]);
            Qf[ks][3] = f2tf32(s1[i_r + 8]);
        }
    }

    float Oa[8][4];
#pragma unroll
    for (int nt = 0; nt < 8; nt++)
#pragma unroll
        for (int c = 0; c < 4; c++) Oa[nt][c] = 0.f;
    float m0 = -CUDART_INF_F, m1 = -CUDART_INF_F, l0 = 0.f, l1 = 0.f;

    const int p00 = ((2 * tq) & 3) * 2 + (tq >> 1);
    const int p01 = ((2 * tq + 1) & 3) * 2 + ((2 * tq + 1) >> 2);
    const int pb  = w * 1024 + g * 8;

    for (int j0 = 0; j0 < NPIX; j0 += 64) {
        float Sa[8][4];
#pragma unroll
        for (int nt = 0; nt < 8; nt++)
#pragma unroll
            for (int c = 0; c < 4; c++) Sa[nt][c] = 0.f;
#pragma unroll
        for (int kp = 0; kp < 8; kp++) {
#pragma unroll
            for (int nt = 0; nt < 8; nt++) {
                uint4 kb = KF[(j0 + nt * 8 + g) * 32 + kp * 4 + tq];
                mma8(Sa[nt], Qf[2 * kp],     kb.x, kb.y);
                mma8(Sa[nt], Qf[2 * kp + 1], kb.z, kb.w);
            }
        }

        float mx0 = -CUDART_INF_F, mx1 = -CUDART_INF_F;
#pragma unroll
        for (int nt = 0; nt < 8; nt++) {
            mx0 = fmaxf(mx0, fmaxf(Sa[nt][0], Sa[nt][1]));
            mx1 = fmaxf(mx1, fmaxf(Sa[nt][2], Sa[nt][3]));
        }
        mx0 = fmaxf(mx0, __shfl_xor_sync(0xffffffffu, mx0, 1));
        mx0 = fmaxf(mx0, __shfl_xor_sync(0xffffffffu, mx0, 2));
        mx1 = fmaxf(mx1, __shfl_xor_sync(0xffffffffu, mx1, 1));
        mx1 = fmaxf(mx1, __shfl_xor_sync(0xffffffffu, mx1, 2));
        float mn0 = fmaxf(m0, mx0), mn1 = fmaxf(m1, mx1);
        float al0 = __expf(m0 - mn0), al1 = __expf(m1 - mn1);

        float su0 = 0.f, su1 = 0.f;
#pragma unroll
        for (int nt = 0; nt < 8; nt++) {
            float e00 = __expf(Sa[nt][0] - mn0);
            float e01 = __expf(Sa[nt][1] - mn0);
            float e10 = __expf(Sa[nt][2] - mn1);
            float e11 = __expf(Sa[nt][3] - mn1);
            su0 += e00 + e01; su1 += e10 + e11;
            sP[pb + nt * 128 + p00]      = f2tf32(e00);
            sP[pb + nt * 128 + p01]      = f2tf32(e01);
            sP[pb + nt * 128 + 64 + p00] = f2tf32(e10);
            sP[pb + nt * 128 + 64 + p01] = f2tf32(e11);
        }
        su0 += __shfl_xor_sync(0xffffffffu, su0, 1);
        su0 += __shfl_xor_sync(0xffffffffu, su0, 2);
        su1 += __shfl_xor_sync(0xffffffffu, su1, 1);
        su1 += __shfl_xor_sync(0xffffffffu, su1, 2);
        l0 = l0 * al0 + su0; l1 = l1 * al1 + su1;
        m0 = mn0; m1 = mn1;
#pragma unroll
        for (int nt = 0; nt < 8; nt++) {
            Oa[nt][0] *= al0; Oa[nt][1] *= al0;
            Oa[nt][2] *= al1; Oa[nt][3] *= al1;
        }
        __syncwarp();

#pragma unroll
        for (int kpl = 0; kpl < 4; kpl++) {
            const uint32_t* ape = &sP[w * 1024 + (2 * kpl) * 128 + g * 8 + 2 * tq];
            uint2 e02 = *(const uint2*)ape;
            uint2 e13 = *(const uint2*)(ape + 64);
            uint2 o02 = *(const uint2*)(ape + 128);
            uint2 o13 = *(const uint2*)(ape + 192);
            uint32_t ae[4] = {e02.x, e13.x, e02.y, e13.y};
            uint32_t ao[4] = {o02.x, o13.x, o02.y, o13.y};
#pragma unroll
            for (int nt = 0; nt < 8; nt++) {
                uint4 vb = VF[((nt * 8 + g) * 256 + (j0 >> 4) + kpl) * 4 + tq];
                mma8(Oa[nt], ae, vb.x, vb.y);
                mma8(Oa[nt], ao, vb.z, vb.w);
            }
        }
        __syncwarp();
    }

    float inv0 = 1.f / l0, inv1 = 1.f / l1;
    int pix = i0 + w * 16 + g;
#pragma unroll
    for (int nt = 0; nt < 8; nt++) {
        int d0 = nt * 8 + 2 * tq;
        outp[(long)d0 * NPIX + pix]           = Oa[nt][0] * inv0;
        outp[(long)(d0 + 1) * NPIX + pix]     = Oa[nt][1] * inv0;
        outp[(long)d0 * NPIX + pix + 8]       = Oa[nt][2] * inv1;
        outp[(long)(d0 + 1) * NPIX + pix + 8] = Oa[nt][3] * inv1;
    }
}

// ---------------- host orchestration ----------------
extern "C" void kernel_launch(void* const* d_in, const int* in_sizes, int n_in,
                              void* d_out, int out_size) {
    const float* x      = (const float*)d_in[0];
    const float* dc_w1  = (const float*)d_in[1];
    const float* dc_g1  = (const float*)d_in[3];
    const float* dc_be1 = (const float*)d_in[4];
    const float* dc_w2  = (const float*)d_in[5];
    const float* dc_g2  = (const float*)d_in[7];
    const float* dc_be2 = (const float*)d_in[8];
    const float* aw[4]  = {(const float*)d_in[9],  (const float*)d_in[12],
                           (const float*)d_in[15], (const float*)d_in[18]};
    const float* ag[4]  = {(const float*)d_in[10], (const float*)d_in[13],
                           (const float*)d_in[16], (const float*)d_in[19]};
    const float* ab[4]  = {(const float*)d_in[11], (const float*)d_in[14],
                           (const float*)d_in[17], (const float*)d_in[20]};
    const float* wq = (const float*)d_in[21]; const float* bq = (const float*)d_in[22];
    const float* wk = (const float*)d_in[23]; const float* bk = (const float*)d_in[24];
    const float* wv = (const float*)d_in[25]; const float* bv = (const float*)d_in[26];
    const float* rel_h = (const float*)d_in[27];
    const float* rel_w = (const float*)d_in[28];

    float *pool, *buf1, *buf2, *brb, *qb, *kfb, *vfb, *p1, *p2, *An, *Bn, *wt;
    cudaGetSymbolAddress((void**)&pool, g_pool);
    cudaGetSymbolAddress((void**)&buf1, g_buf1);
    cudaGetSymbolAddress((void**)&buf2, g_buf2);
    cudaGetSymbolAddress((void**)&brb,  g_br);
    cudaGetSymbolAddress((void**)&qb,   g_q);
    cudaGetSymbolAddress((void**)&kfb,  g_kf);
    cudaGetSymbolAddress((void**)&vfb,  g_vf);
    cudaGetSymbolAddress((void**)&p1,   g_p1);
    cudaGetSymbolAddress((void**)&p2,   g_p2);
    cudaGetSymbolAddress((void**)&An,   g_An);
    cudaGetSymbolAddress((void**)&Bn,   g_Bn);
    cudaGetSymbolAddress((void**)&wt,   g_wt);

    float* wt1 = wt;                 // conv1: 589824
    float* wt2 = wt + 589824;        // conv2: 1179648
    float* wtA = wt + 1769472;       // aspp 3x3 convs: 3 x 294912

    cudaFuncSetAttribute((const void*)conv_mma_kernel<false>,
                         cudaFuncAttributeMaxDynamicSharedMemorySize, CONV_SMEM);
    cudaFuncSetAttribute((const void*)conv_mma_kernel<true>,
                         cudaFuncAttributeMaxDynamicSharedMemorySize, CONV_SMEM);
    cudaFuncSetAttribute((const void*)flash_mma_kernel,
                         cudaFuncAttributeMaxDynamicSharedMemorySize, FLASH3_SMEM);

    // weight prep (tf32 hi/lo, fragment-swizzled)
    wprep_kernel<<<(256 * 128 * 9 + 255) / 256, 256>>>(dc_w1, wt1, 128, 256);
    wprep_kernel<<<(256 * 256 * 9 + 255) / 256, 256>>>(dc_w2, wt2, 256, 256);
    for (int i = 0; i < 3; i++)
        wprep_kernel<<<(64 * 256 * 9 + 255) / 256, 256>>>(
            aw[i + 1], wtA + (long)i * 294912, 256, 64);

    // mpconv (4-row conv tiles)
    maxpool_kernel<<<(BATCH * 128 * NPIX + 255) / 256, 256>>>(x, pool);
    conv_mma_kernel<false><<<dim3(16, 4, BATCH), 256, CONV_SMEM>>>(
        pool, wt1, buf1, 128, nullptr, nullptr, p1, p2);
    finalize_kernel<<<256, 128>>>(p1, p2, dc_g1, dc_be1, An + 0, Bn + 0, 256, 64);
    conv_mma_kernel<false><<<dim3(16, 4, BATCH), 256, CONV_SMEM>>>(
        buf1, wt2, buf2, 256, An + 0, Bn + 0, p1, p2);
    finalize_kernel<<<256, 128>>>(p1, p2, dc_g2, dc_be2, An + 256, Bn + 256, 256, 64);

    // ASPP dilated branches (2,3,4) fused; 1x1 branch separate
    conv_mma_kernel<true><<<dim3(16, 3, BATCH), 256, CONV_SMEM>>>(
        buf2, wtA, brb + (long)BATCH * 64 * NPIX, 256, An + 256, Bn + 256, p1, p2);
    for (int i = 0; i < 3; i++)
        finalize_kernel<<<64, 128>>>(p1 + i * 8192, p2 + i * 8192, ag[i + 1], ab[i + 1],
                                     An + (3 + i) * 256, Bn + (3 + i) * 256, 64, 64);
    conv1x1_bn_kernel<<<dim3(64, 1, BATCH), 256>>>(
        buf2, aw[0], brb, 256, An + 256, Bn + 256, p1 + 32768, p2 + 32768);
    finalize_kernel<<<64, 128>>>(p1 + 32768, p2 + 32768, ag[0], ab[0],
                                 An + 2 * 256, Bn + 2 * 256, 64, 256);

    // fused qkv -> q plain + K'/V fragment layouts; pos table
    qkv_kernel<<<dim3(64, 1, 16), 256>>>(brb, wq, bq, wk, bk, wv, bv,
                                         qb, kfb, vfb, An, Bn);
    pos_kernel<<<(64 * NPIX + 255) / 256, 256>>>(rel_h, rel_w);

    // fragment-direct flash attention -> concat output
    flash_mma_kernel<<<dim3(32, BATCH, 4), 256, FLASH3_SMEM>>>(
        qb, kfb, vfb, (float*)d_out);
}

// round 10
// speedup vs baseline: 2.2309x; 1.0069x over previous
#include <cuda_runtime.h>
#include <math_constants.h>
#include <stdint.h>

#define BATCH 4
#define NPIX 4096   // 64*64

// ---------------- scratch (device globals; no cudaMalloc allowed) ----------------
__device__ float g_pool [BATCH * 128 * NPIX];     // maxpool out (tf32-rounded)
__device__ float g_buf1 [BATCH * 256 * NPIX];     // conv1 raw out
__device__ float g_buf1t[BATCH * 256 * NPIX];     // tf32(relu(BN(buf1)))
__device__ float g_buf2 [BATCH * 256 * NPIX];     // conv2 raw out
__device__ float g_buf2t[BATCH * 256 * NPIX];     // tf32(relu(BN(buf2)))
__device__ float g_br  [4 * BATCH * 64 * NPIX];
__device__ float g_q   [4 * BATCH * 64 * NPIX];   // plain q
__device__ float g_kf  [16 * 4096 * 128];         // K' fragment-paired tf32
__device__ float g_vf  [16 * 64 * 256 * 16];      // V  fragment-paired tf32
__device__ float g_pos [64 * NPIX];
__device__ float g_p1  [256 * 256];
__device__ float g_p2  [256 * 256];
__device__ float g_An  [6 * 256];
__device__ float g_Bn  [6 * 256];
__device__ float g_wt  [2654208];   // pre-swizzled tf32 hi/lo conv weights

__device__ __forceinline__ uint32_t f2tf32(float f) {
    uint32_t u;
    asm("cvt.rna.tf32.f32 %0, %1;" : "=r"(u) : "f"(f));
    return u;
}
__device__ __forceinline__ void mma8(float d[4], const uint32_t a[4],
                                     uint32_t b0, uint32_t b1) {
    asm volatile(
        "mma.sync.aligned.m16n8k8.row.col.f32.tf32.tf32.f32 "
        "{%0,%1,%2,%3},{%4,%5,%6,%7},{%8,%9},{%0,%1,%2,%3};"
        : "+f"(d[0]), "+f"(d[1]), "+f"(d[2]), "+f"(d[3])
        : "r"(a[0]), "r"(a[1]), "r"(a[2]), "r"(a[3]), "r"(b0), "r"(b1));
}
__device__ __forceinline__ int ilv(int klo) { return (klo & 3) * 2 + (klo >> 2); }

// ---------------- maxpool 2x2 (emits tf32-rounded: conv1 input) ----------------
__global__ void maxpool_kernel(const float* __restrict__ x, float* __restrict__ out) {
    int idx = blockIdx.x * blockDim.x + threadIdx.x;
    if (idx >= BATCH * 128 * NPIX) return;
    int p  = idx & (NPIX - 1);
    int bc = idx >> 12;
    int y = p >> 6, xx = p & 63;
    const float* src = x + ((long)bc * 128 + 2 * y) * 128 + 2 * xx;
    float v = fmaxf(fmaxf(src[0], src[1]), fmaxf(src[128], src[129]));
    out[idx] = __uint_as_float(f2tf32(v));
}

// ---------------- bnprep: out = tf32(relu(A*v + B)), float4 ----------------
__global__ void bnprep_kernel(const float* __restrict__ in, float* __restrict__ out,
                              const float* __restrict__ A, const float* __restrict__ B,
                              int total4) {
    for (int i = blockIdx.x * blockDim.x + threadIdx.x; i < total4;
         i += gridDim.x * blockDim.x) {
        int c = (i >> 10) & 255;                 // 1024 float4 per (b,c)
        float a = A[c], bb = B[c];
        float4 v = ((const float4*)in)[i];
        float4 o;
        o.x = __uint_as_float(f2tf32(fmaxf(v.x * a + bb, 0.f)));
        o.y = __uint_as_float(f2tf32(fmaxf(v.y * a + bb, 0.f)));
        o.z = __uint_as_float(f2tf32(fmaxf(v.z * a + bb, 0.f)));
        o.w = __uint_as_float(f2tf32(fmaxf(v.w * a + bb, 0.f)));
        ((float4*)out)[i] = o;
    }
}

// ---------------- weight prep: OIHW -> [ocg][chunk][hi/lo][tap][oc64][ilv8] ----------------
__global__ void wprep_kernel(const float* __restrict__ W, float* __restrict__ dst,
                             int Cin, int Cout) {
    int idx = blockIdx.x * 256 + threadIdx.x;
    int total = Cout * Cin * 9;
    if (idx >= total) return;
    int tap = idx % 9;
    int rem = idx / 9;
    int ic  = rem % Cin;
    int oc  = rem / Cin;
    float wv = W[idx];
    float hi = __uint_as_float(f2tf32(wv));
    float lo = __uint_as_float(f2tf32(wv - hi));
    int ocg = oc >> 6, oc64 = oc & 63, chunk = ic >> 3, klo = ic & 7;
    int nch = Cin >> 3;
    long base = (long)(ocg * nch + chunk) * 9216;
    dst[base +        (tap * 64 + oc64) * 8 + ilv(klo)] = hi;
    dst[base + 4608 + (tap * 64 + oc64) * 8 + ilv(klo)] = lo;
}

// ======== tensor-core 3x3 dilated conv: pure cp.async staging (inputs pre-converted) ========
// CTA: 256 thr = 8 warps. CTA tile: 64 oc x 256 px (4 y rows). warp m32 x n64.
// Inputs are pre-rounded tf32 floats; staging = raw cp.async (zero-fill OOB rows).
#define CONV_SMEM (18240 * 4)
template<bool ASPP>
__global__ void __launch_bounds__(256, 2) conv_mma_kernel(
    const float* __restrict__ in, const float* __restrict__ wtbase,
    float* __restrict__ outbase, int Cin,
    float* __restrict__ p1base, float* __restrict__ p2base)
{
    extern __shared__ float sm[];
    float* sIn = sm;             // 8 * 1064 ([ic][ky*4+yr][88], zero x-halos)
    float* sW  = sm + 8512;      // [hl][tap][oc64][8]
    float* sRS = sm + 17728;     // [8 warps][32]
    float* sRQ = sm + 17984;

    const int ytile = blockIdx.x;      // 0..15
    const int b     = blockIdx.z;
    const int nchunk = Cin >> 3;
    int dil, ocg, Cout;
    const float* wt;
    float* out;
    float *p1, *p2;
    if (ASPP) {
        int br = blockIdx.y;           // 0..2 -> dil 3,6,9
        dil = 3 * (br + 1); ocg = 0; Cout = 64;
        wt  = wtbase + (long)br * 294912;
        out = outbase + ((long)br * BATCH + b) * 64 * NPIX;
        p1  = p1base + br * 8192;
        p2  = p2base + br * 8192;
    } else {
        dil = 1; ocg = blockIdx.y; Cout = gridDim.y * 64;
        wt  = wtbase + (long)ocg * nchunk * 9216;
        out = outbase + (long)b * Cout * NPIX;
        p1  = p1base; p2 = p2base;
    }
    in += (long)b * Cin * NPIX;

    const int t = threadIdx.x, lane = t & 31, w = t >> 5;
    const int g = lane >> 2, tq = lane & 3;
    const int mwarp = w >> 2;
    const int yr    = w & 3;
    const int y0    = ytile * 4;

    const uint32_t swu  = (uint32_t)__cvta_generic_to_shared(sW);
    const uint32_t sinu = (uint32_t)__cvta_generic_to_shared(sIn);

    for (int i = t; i < 8512; i += 256) sIn[i] = 0.f;

    float acc[2][8][4];
#pragma unroll
    for (int mf = 0; mf < 2; mf++)
#pragma unroll
        for (int nt = 0; nt < 8; nt++)
#pragma unroll
            for (int c = 0; c < 4; c++) acc[mf][nt][c] = 0.f;

    for (int chunk = 0; chunk < nchunk; chunk++) {
        __syncthreads();
        // ---- weights: 2304 float4 cp.async of pre-swizzled block ----
        {
            const float4* ws = (const float4*)(wt + (long)chunk * 9216);
#pragma unroll
            for (int i = t; i < 2304; i += 256)
                asm volatile("cp.async.cg.shared.global [%0], [%1], 16;\n"
                             :: "r"(swu + i * 16), "l"(ws + i));
        }
        // ---- inputs: 1536 float4 cp.async, OOB rows zero-filled ----
        {
            const float* inc = in + (long)chunk * 8 * NPIX;
#pragma unroll
            for (int e = t; e < 1536; e += 256) {
                int fx  = e & 15;
                int row = e >> 4;            // 0..95
                int ic  = row / 12;
                int r2  = row - ic * 12;
                int ky  = r2 >> 2, yri = r2 & 3;
                int ry  = y0 + yri + (ky - 1) * dil;
                int ok  = (ry >= 0 && ry < 64);
                uint32_t dst = sinu + (uint32_t)(ic * 4256 + (ky * 4 + yri) * 352 + 48 + fx * 16);
                const float4* src = (const float4*)(inc + ic * NPIX + (ok ? ry : 0) * 64) + fx;
                int ssz = ok ? 16 : 0;
                asm volatile("cp.async.cg.shared.global [%0], [%1], 16, %2;\n"
                             :: "r"(dst), "l"(src), "r"(ssz));
            }
        }
        asm volatile("cp.async.commit_group;\n");
        asm volatile("cp.async.wait_group 0;\n" ::: "memory");
        __syncthreads();

        // ---- 9 taps x (hi+lo) x 8 n-tiles ----
#pragma unroll
        for (int tap = 0; tap < 9; tap++) {
            const int ky = tap / 3, kx = tap % 3;
            const uint32_t* bp = (const uint32_t*)(sIn) +
                tq * 1064 + (ky * 4 + yr) * 88 + 12 + g + (kx - 1) * dil;
            const float* wb = sW + (tap * 64 + mwarp * 32 + g) * 8 + 2 * tq;
            uint2 h0  = *(const uint2*)(wb);
            uint2 h0b = *(const uint2*)(wb + 64);
            uint2 h1  = *(const uint2*)(wb + 128);
            uint2 h1b = *(const uint2*)(wb + 192);
            uint2 l0  = *(const uint2*)(wb + 4608);
            uint2 l0b = *(const uint2*)(wb + 4672);
            uint2 l1  = *(const uint2*)(wb + 4736);
            uint2 l1b = *(const uint2*)(wb + 4800);
            uint32_t aH0[4] = {h0.x, h0b.x, h0.y, h0b.y};
            uint32_t aH1[4] = {h1.x, h1b.x, h1.y, h1b.y};
            uint32_t aL0[4] = {l0.x, l0b.x, l0.y, l0b.y};
            uint32_t aL1[4] = {l1.x, l1b.x, l1.y, l1b.y};
#pragma unroll
            for (int nt = 0; nt < 8; nt++) {
                uint32_t b0 = bp[nt * 8];
                uint32_t b1 = bp[nt * 8 + 4256];
                mma8(acc[0][nt], aH0, b0, b1);
                mma8(acc[0][nt], aL0, b0, b1);
                mma8(acc[1][nt], aH1, b0, b1);
                mma8(acc[1][nt], aL1, b0, b1);
            }
        }
    }

    // ---- epilogue: store + BN partials ----
    float s[2][2] = {{0.f, 0.f}, {0.f, 0.f}};
    float q[2][2] = {{0.f, 0.f}, {0.f, 0.f}};
    const int ocb = ocg * 64 + mwarp * 32;
#pragma unroll
    for (int mf = 0; mf < 2; mf++) {
        int oc = ocb + mf * 16 + g;
#pragma unroll
        for (int nt = 0; nt < 8; nt++) {
            int gx = (y0 + yr) * 64 + nt * 8 + 2 * tq;
            float c0 = acc[mf][nt][0], c1 = acc[mf][nt][1];
            float c2 = acc[mf][nt][2], c3 = acc[mf][nt][3];
            out[(long)oc * NPIX + gx]           = c0;
            out[(long)oc * NPIX + gx + 1]       = c1;
            out[(long)(oc + 8) * NPIX + gx]     = c2;
            out[(long)(oc + 8) * NPIX + gx + 1] = c3;
            s[mf][0] += c0 + c1; q[mf][0] += c0 * c0 + c1 * c1;
            s[mf][1] += c2 + c3; q[mf][1] += c2 * c2 + c3 * c3;
        }
    }
#pragma unroll
    for (int mf = 0; mf < 2; mf++)
#pragma unroll
        for (int ro = 0; ro < 2; ro++) {
            float a = s[mf][ro], qq = q[mf][ro];
            a  += __shfl_xor_sync(0xffffffffu, a, 1);
            qq += __shfl_xor_sync(0xffffffffu, qq, 1);
            a  += __shfl_xor_sync(0xffffffffu, a, 2);
            qq += __shfl_xor_sync(0xffffffffu, qq, 2);
            if (tq == 0) {
                sRS[w * 32 + mf * 16 + ro * 8 + g] = a;
                sRQ[w * 32 + mf * 16 + ro * 8 + g] = qq;
            }
        }
    __syncthreads();
    if (t < 64) {
        int mw = t >> 5, cl = t & 31;
        float a  = sRS[(mw * 4 + 0) * 32 + cl] + sRS[(mw * 4 + 1) * 32 + cl] +
                   sRS[(mw * 4 + 2) * 32 + cl] + sRS[(mw * 4 + 3) * 32 + cl];
        float qq = sRQ[(mw * 4 + 0) * 32 + cl] + sRQ[(mw * 4 + 1) * 32 + cl] +
                   sRQ[(mw * 4 + 2) * 32 + cl] + sRQ[(mw * 4 + 3) * 32 + cl];
        int slot = b * 16 + ytile;
        p1[slot * Cout + ocg * 64 + t] = a;
        p2[slot * Cout + ocg * 64 + t] = qq;
    }
}

// ---------------- BN finalize ----------------
__global__ void finalize_kernel(const float* __restrict__ p1, const float* __restrict__ p2,
                                const float* __restrict__ g, const float* __restrict__ be,
                                float* __restrict__ A, float* __restrict__ B,
                                int C, int nslots) {
    const int c = blockIdx.x, t = threadIdx.x;
    float s = 0.f, q = 0.f;
    for (int slot = t; slot < nslots; slot += 128) {
        s += p1[slot * C + c];
        q += p2[slot * C + c];
    }
    __shared__ float rs[4], rq[4];
#pragma unroll
    for (int off = 16; off; off >>= 1) {
        s += __shfl_down_sync(0xffffffffu, s, off);
        q += __shfl_down_sync(0xffffffffu, q, off);
    }
    int lane = t & 31, wp = t >> 5;
    if (!lane) { rs[wp] = s; rq[wp] = q; }
    __syncthreads();
    if (t == 0) {
        s = rs[0] + rs[1] + rs[2] + rs[3];
        q = rq[0] + rq[1] + rq[2] + rq[3];
        const float inv = 1.f / (float)(BATCH * NPIX);
        float mean = s * inv;
        float var  = q * inv - mean * mean;
        float a = g[c] * rsqrtf(var + 1e-5f);
        A[c] = a;
        B[c] = be[c] - mean * a;
    }
}

// ---------------- 1x1 conv Cout=64 with input-BN + stats (aspp1, exact fp32) ----------------
__global__ void __launch_bounds__(256) conv1x1_bn_kernel(
    const float* __restrict__ in, const float* __restrict__ w,
    float* __restrict__ out, int Cin,
    const float* __restrict__ Abn, const float* __restrict__ Bbn,
    float* __restrict__ p1, float* __restrict__ p2)
{
    const int p0 = blockIdx.x * 64;
    const int b  = blockIdx.z;
    in  += (long)b * Cin * NPIX;
    out += (long)b * 64  * NPIX;
    const int t = threadIdx.x, tx = t & 15, ty = t >> 4;

    __shared__ float sW [16 * 68];
    __shared__ float sIn[16 * 64];

    float acc[4][4];
#pragma unroll
    for (int r = 0; r < 4; r++)
#pragma unroll
        for (int c = 0; c < 4; c++) acc[r][c] = 0.f;

    for (int ic0 = 0; ic0 < Cin; ic0 += 16) {
        __syncthreads();
        for (int idx = t; idx < 1024; idx += 256) {
            int ic = idx & 15, oc = idx >> 4;
            sW[ic * 68 + oc] = w[(long)oc * Cin + ic0 + ic];
        }
        for (int idx = t; idx < 1024; idx += 256) {
            int ic = idx >> 6, px = idx & 63;
            int c = ic0 + ic;
            float v = in[c * NPIX + p0 + px];
            sIn[idx] = fmaxf(v * Abn[c] + Bbn[c], 0.f);
        }
        __syncthreads();
#pragma unroll
        for (int ic = 0; ic < 16; ic++) {
            float4 a  = *(const float4*)(sW  + ic * 68 + ty * 4);
            float4 xv = *(const float4*)(sIn + ic * 64 + tx * 4);
            float av[4] = {a.x, a.y, a.z, a.w};
            float xa[4] = {xv.x, xv.y, xv.z, xv.w};
#pragma unroll
            for (int r = 0; r < 4; r++)
#pragma unroll
                for (int c = 0; c < 4; c++) acc[r][c] += av[r] * xa[c];
        }
    }
    float sums[4], sqs[4];
#pragma unroll
    for (int r = 0; r < 4; r++) {
        float s = 0.f, q = 0.f;
        float* op = out + (long)(ty * 4 + r) * NPIX + p0 + tx * 4;
#pragma unroll
        for (int c = 0; c < 4; c++) {
            float v = acc[r][c];
            op[c] = v; s += v; q += v * v;
        }
        sums[r] = s; sqs[r] = q;
    }
#pragma unroll
    for (int r = 0; r < 4; r++) {
        float a = sums[r], q = sqs[r];
#pragma unroll
        for (int off = 1; off < 16; off <<= 1) {
            a += __shfl_xor_sync(0xffffffffu, a, off);
            q += __shfl_xor_sync(0xffffffffu, q, off);
        }
        if (tx == 0) {
            int c = ty * 4 + r;
            int slot = b * 64 + blockIdx.x;
            p1[slot * 64 + c] = a;
            p2[slot * 64 + c] = q;
        }
    }
}

// ---------------- fused q/k/v 1x1 projections -> q plain + K'/V fragment layouts ----------------
__global__ void __launch_bounds__(256) qkv_kernel(
    const float* __restrict__ brin,
    const float* __restrict__ wq, const float* __restrict__ bq,
    const float* __restrict__ wk, const float* __restrict__ bk,
    const float* __restrict__ wv, const float* __restrict__ bv,
    float* __restrict__ qo, float* __restrict__ kf, float* __restrict__ vf,
    const float* __restrict__ Abase, const float* __restrict__ Bbase)
{
    const int p0  = blockIdx.x * 64;
    const int img = blockIdx.z;
    const int br  = img >> 2;
    const long ib = (long)img * 64 * NPIX;
    const float* A  = Abase + (2 + br) * 256;
    const float* Bb = Bbase + (2 + br) * 256;
    const int t = threadIdx.x, tx = t & 15, ty = t >> 4;

    float* kfp = kf + (long)img * 524288;
    float* vfp = vf + (long)img * 262144;

    __shared__ float sW [3 * 16 * 64];
    __shared__ float sIn[16 * 64];

    float acc[3][4][4];
#pragma unroll
    for (int m = 0; m < 3; m++)
#pragma unroll
        for (int r = 0; r < 4; r++)
#pragma unroll
            for (int c = 0; c < 4; c++) acc[m][r][c] = 0.f;

    for (int ic0 = 0; ic0 < 64; ic0 += 16) {
        __syncthreads();
        for (int i = t; i < 1024; i += 256) {
            int ic = i >> 6, px = i & 63;
            int c = ic0 + ic;
            float v = brin[ib + (long)c * NPIX + p0 + px];
            sIn[i] = fmaxf(v * A[c] + Bb[c], 0.f);
        }
        for (int i = t; i < 3072; i += 256) {
            int m = i >> 10, r = i & 1023;
            int ic = r & 15, oc = r >> 4;
            const float* wm = (m == 0) ? wq : ((m == 1) ? wk : wv);
            sW[m * 1024 + ic * 64 + oc] = wm[oc * 64 + ic0 + ic];
        }
        __syncthreads();
#pragma unroll
        for (int ic = 0; ic < 16; ic++) {
            float4 xv = *(const float4*)(sIn + ic * 64 + tx * 4);
            float xa[4] = {xv.x, xv.y, xv.z, xv.w};
#pragma unroll
            for (int m = 0; m < 3; m++) {
                float4 a = *(const float4*)(sW + m * 1024 + ic * 64 + ty * 4);
                float av[4] = {a.x, a.y, a.z, a.w};
#pragma unroll
                for (int r = 0; r < 4; r++)
#pragma unroll
                    for (int c = 0; c < 4; c++) acc[m][r][c] += av[r] * xa[c];
            }
        }
    }
    const float* bs[3] = {bq, bk, bv};
#pragma unroll
    for (int m = 0; m < 3; m++) {
#pragma unroll
        for (int r = 0; r < 4; r++) {
            int oc = ty * 4 + r;
            float bb = bs[m][oc];
#pragma unroll
            for (int ci = 0; ci < 4; ci++) {
                int j = p0 + tx * 4 + ci;
                float val = acc[m][r][ci] + bb;
                if (m == 0) {
                    qo[ib + (long)oc * NPIX + j] = val;
                    int kk = 64 + oc, ks = kk >> 3, klo = kk & 7;
                    int slot = (ks >> 1) * 16 + (klo & 3) * 4 + (ks & 1) * 2 + (klo >> 2);
                    kfp[j * 128 + slot] = __uint_as_float(f2tf32(val));
                } else if (m == 1) {
                    int kk = oc, ks = kk >> 3, klo = kk & 7;
                    int slot = (ks >> 1) * 16 + (klo & 3) * 4 + (ks & 1) * 2 + (klo >> 2);
                    kfp[j * 128 + slot] = __uint_as_float(f2tf32(val));
                } else {
                    int ksv = j >> 3, jlo = j & 7;
                    int slot = (jlo & 3) * 4 + (ksv & 1) * 2 + (jlo >> 2);
                    vfp[(oc * 256 + (ksv >> 1)) * 16 + slot] = __uint_as_float(f2tf32(val));
                }
            }
        }
    }
}

// ---------------- pos table ----------------
__global__ void pos_kernel(const float* __restrict__ rh, const float* __restrict__ rw) {
    int idx = blockIdx.x * blockDim.x + threadIdx.x;
    if (idx >= 64 * NPIX) return;
    int d = idx >> 12, n = idx & 4095, a = n >> 6, bb = n & 63;
    g_pos[idx] = rh[d * 64 + bb] + rw[d * 64 + a];
}

// ================= fragment-direct tf32 flash attention =================
#define FLASH3_SMEM (8192 * 4)

__global__ void __launch_bounds__(256, 1) flash_mma_kernel(
    const float* __restrict__ qg, const float* __restrict__ kf,
    const float* __restrict__ vf, float* __restrict__ outg)
{
    extern __shared__ uint32_t smu[];
    uint32_t* sP = smu;

    const int i0 = blockIdx.x * 128;
    const int b  = blockIdx.y, br = blockIdx.z;
    const int img = br * BATCH + b;
    const float* q = qg + (long)img * 64 * NPIX;
    const uint4* KF = (const uint4*)(kf + (long)img * 524288);
    const uint4* VF = (const uint4*)(vf + (long)img * 262144);
    float* outp = outg + (long)(b * 256 + br * 64) * NPIX;

    const int t = threadIdx.x;
    const int lane = t & 31, w = t >> 5;
    const int g = lane >> 2, tq = lane & 3;

    uint32_t Qf[16][4];
    {
        int i_r = i0 + w * 16 + g;
#pragma unroll
        for (int ks = 0; ks < 16; ks++) {
            int kc = ks * 8 + tq;
            const float* s0 = (kc < 64)     ? (q + kc * NPIX)       : (g_pos + (kc - 64) * NPIX);
            const float* s1 = (kc + 4 < 64) ? (q + (kc + 4) * NPIX) : (g_pos + (kc - 60) * NPIX);
            Qf[ks][0] = f2tf32(s0[i_r]);
            Qf[ks][1] = f2tf32(s0[i_r + 8]);
            Qf[ks][2] = f2tf32(s1[i_r]);
            Qf[ks][3] = f2tf32(s1[i_r + 8]);
        }
    }

    float Oa[8][4];
#pragma unroll
    for (int nt = 0; nt < 8; nt++)
#pragma unroll
        for (int c = 0; c < 4; c++) Oa[nt][c] = 0.f;
    float m0 = -CUDART_INF_F, m1 = -CUDART_INF_F, l0 = 0.f, l1 = 0.f;

    const int p00 = ((2 * tq) & 3) * 2 + (tq >> 1);
    const int p01 = ((2 * tq + 1) & 3) * 2 + ((2 * tq + 1) >> 2);
    const int pb  = w * 1024 + g * 8;

    for (int j0 = 0; j0 < NPIX; j0 += 64) {
        float Sa[8][4];
#pragma unroll
        for (int nt = 0; nt < 8; nt++)
#pragma unroll
            for (int c = 0; c < 4; c++) Sa[nt][c] = 0.f;
#pragma unroll
        for (int kp = 0; kp < 8; kp++) {
#pragma unroll
            for (int nt = 0; nt < 8; nt++) {
                uint4 kb = KF[(j0 + nt * 8 + g) * 32 + kp * 4 + tq];
                mma8(Sa[nt], Qf[2 * kp],     kb.x, kb.y);
                mma8(Sa[nt], Qf[2 * kp + 1], kb.z, kb.w);
            }
        }

        float mx0 = -CUDART_INF_F, mx1 = -CUDART_INF_F;
#pragma unroll
        for (int nt = 0; nt < 8; nt++) {
            mx0 = fmaxf(mx0, fmaxf(Sa[nt][0], Sa[nt][1]));
            mx1 = fmaxf(mx1, fmaxf(Sa[nt][2], Sa[nt][3]));
        }
        mx0 = fmaxf(mx0, __shfl_xor_sync(0xffffffffu, mx0, 1));
        mx0 = fmaxf(mx0, __shfl_xor_sync(0xffffffffu, mx0, 2));
        mx1 = fmaxf(mx1, __shfl_xor_sync(0xffffffffu, mx1, 1));
        mx1 = fmaxf(mx1, __shfl_xor_sync(0xffffffffu, mx1, 2));
        float mn0 = fmaxf(m0, mx0), mn1 = fmaxf(m1, mx1);
        float al0 = __expf(m0 - mn0), al1 = __expf(m1 - mn1);

        float su0 = 0.f, su1 = 0.f;
#pragma unroll
        for (int nt = 0; nt < 8; nt++) {
            float e00 = __expf(Sa[nt][0] - mn0);
            float e01 = __expf(Sa[nt][1] - mn0);
            float e10 = __expf(Sa[nt][2] - mn1);
            float e11 = __expf(Sa[nt][3] - mn1);
            su0 += e00 + e01; su1 += e10 + e11;
            sP[pb + nt * 128 + p00]      = f2tf32(e00);
            sP[pb + nt * 128 + p01]      = f2tf32(e01);
            sP[pb + nt * 128 + 64 + p00] = f2tf32(e10);
            sP[pb + nt * 128 + 64 + p01] = f2tf32(e11);
        }
        su0 += __shfl_xor_sync(0xffffffffu, su0, 1);
        su0 += __shfl_xor_sync(0xffffffffu, su0, 2);
        su1 += __shfl_xor_sync(0xffffffffu, su1, 1);
        su1 += __shfl_xor_sync(0xffffffffu, su1, 2);
        l0 = l0 * al0 + su0; l1 = l1 * al1 + su1;
        m0 = mn0; m1 = mn1;
#pragma unroll
        for (int nt = 0; nt < 8; nt++) {
            Oa[nt][0] *= al0; Oa[nt][1] *= al0;
            Oa[nt][2] *= al1; Oa[nt][3] *= al1;
        }
        __syncwarp();

#pragma unroll
        for (int kpl = 0; kpl < 4; kpl++) {
            const uint32_t* ape = &sP[w * 1024 + (2 * kpl) * 128 + g * 8 + 2 * tq];
            uint2 e02 = *(const uint2*)ape;
            uint2 e13 = *(const uint2*)(ape + 64);
            uint2 o02 = *(const uint2*)(ape + 128);
            uint2 o13 = *(const uint2*)(ape + 192);
            uint32_t ae[4] = {e02.x, e13.x, e02.y, e13.y};
            uint32_t ao[4] = {o02.x, o13.x, o02.y, o13.y};
#pragma unroll
            for (int nt = 0; nt < 8; nt++) {
                uint4 vb = VF[((nt * 8 + g) * 256 + (j0 >> 4) + kpl) * 4 + tq];
                mma8(Oa[nt], ae, vb.x, vb.y);
                mma8(Oa[nt], ao, vb.z, vb.w);
            }
        }
        __syncwarp();
    }

    float inv0 = 1.f / l0, inv1 = 1.f / l1;
    int pix = i0 + w * 16 + g;
#pragma unroll
    for (int nt = 0; nt < 8; nt++) {
        int d0 = nt * 8 + 2 * tq;
        outp[(long)d0 * NPIX + pix]           = Oa[nt][0] * inv0;
        outp[(long)(d0 + 1) * NPIX + pix]     = Oa[nt][1] * inv0;
        outp[(long)d0 * NPIX + pix + 8]       = Oa[nt][2] * inv1;
        outp[(long)(d0 + 1) * NPIX + pix + 8] = Oa[nt][3] * inv1;
    }
}

// ---------------- host orchestration ----------------
extern "C" void kernel_launch(void* const* d_in, const int* in_sizes, int n_in,
                              void* d_out, int out_size) {
    const float* x      = (const float*)d_in[0];
    const float* dc_w1  = (const float*)d_in[1];
    const float* dc_g1  = (const float*)d_in[3];
    const float* dc_be1 = (const float*)d_in[4];
    const float* dc_w2  = (const float*)d_in[5];
    const float* dc_g2  = (const float*)d_in[7];
    const float* dc_be2 = (const float*)d_in[8];
    const float* aw[4]  = {(const float*)d_in[9],  (const float*)d_in[12],
                           (const float*)d_in[15], (const float*)d_in[18]};
    const float* ag[4]  = {(const float*)d_in[10], (const float*)d_in[13],
                           (const float*)d_in[16], (const float*)d_in[19]};
    const float* ab[4]  = {(const float*)d_in[11], (const float*)d_in[14],
                           (const float*)d_in[17], (const float*)d_in[20]};
    const float* wq = (const float*)d_in[21]; const float* bq = (const float*)d_in[22];
    const float* wk = (const float*)d_in[23]; const float* bk = (const float*)d_in[24];
    const float* wv = (const float*)d_in[25]; const float* bv = (const float*)d_in[26];
    const float* rel_h = (const float*)d_in[27];
    const float* rel_w = (const float*)d_in[28];

    float *pool, *buf1, *buf1t, *buf2, *buf2t, *brb, *qb, *kfb, *vfb;
    float *p1, *p2, *An, *Bn, *wt;
    cudaGetSymbolAddress((void**)&pool,  g_pool);
    cudaGetSymbolAddress((void**)&buf1,  g_buf1);
    cudaGetSymbolAddress((void**)&buf1t, g_buf1t);
    cudaGetSymbolAddress((void**)&buf2,  g_buf2);
    cudaGetSymbolAddress((void**)&buf2t, g_buf2t);
    cudaGetSymbolAddress((void**)&brb,   g_br);
    cudaGetSymbolAddress((void**)&qb,    g_q);
    cudaGetSymbolAddress((void**)&kfb,   g_kf);
    cudaGetSymbolAddress((void**)&vfb,   g_vf);
    cudaGetSymbolAddress((void**)&p1,    g_p1);
    cudaGetSymbolAddress((void**)&p2,    g_p2);
    cudaGetSymbolAddress((void**)&An,    g_An);
    cudaGetSymbolAddress((void**)&Bn,    g_Bn);
    cudaGetSymbolAddress((void**)&wt,    g_wt);

    float* wt1 = wt;                 // conv1: 589824
    float* wt2 = wt + 589824;        // conv2: 1179648
    float* wtA = wt + 1769472;       // aspp 3x3 convs: 3 x 294912

    cudaFuncSetAttribute((const void*)conv_mma_kernel<false>,
                         cudaFuncAttributeMaxDynamicSharedMemorySize, CONV_SMEM);
    cudaFuncSetAttribute((const void*)conv_mma_kernel<true>,
                         cudaFuncAttributeMaxDynamicSharedMemorySize, CONV_SMEM);
    cudaFuncSetAttribute((const void*)flash_mma_kernel,
                         cudaFuncAttributeMaxDynamicSharedMemorySize, FLASH3_SMEM);

    // weight prep (tf32 hi/lo, fragment-swizzled)
    wprep_kernel<<<(256 * 128 * 9 + 255) / 256, 256>>>(dc_w1, wt1, 128, 256);
    wprep_kernel<<<(256 * 256 * 9 + 255) / 256, 256>>>(dc_w2, wt2, 256, 256);
    for (int i = 0; i < 3; i++)
        wprep_kernel<<<(64 * 256 * 9 + 255) / 256, 256>>>(
            aw[i + 1], wtA + (long)i * 294912, 256, 64);

    const int T4 = BATCH * 256 * NPIX / 4;

    // mpconv: pool(tf32) -> conv1 -> fin1 -> bnprep1 -> conv2 -> fin2 -> bnprep2
    maxpool_kernel<<<(BATCH * 128 * NPIX + 255) / 256, 256>>>(x, pool);
    conv_mma_kernel<false><<<dim3(16, 4, BATCH), 256, CONV_SMEM>>>(
        pool, wt1, buf1, 128, p1, p2);
    finalize_kernel<<<256, 128>>>(p1, p2, dc_g1, dc_be1, An + 0, Bn + 0, 256, 64);
    bnprep_kernel<<<2048, 256>>>(buf1, buf1t, An + 0, Bn + 0, T4);
    conv_mma_kernel<false><<<dim3(16, 4, BATCH), 256, CONV_SMEM>>>(
        buf1t, wt2, buf2, 256, p1, p2);
    finalize_kernel<<<256, 128>>>(p1, p2, dc_g2, dc_be2, An + 256, Bn + 256, 256, 64);
    bnprep_kernel<<<2048, 256>>>(buf2, buf2t, An + 256, Bn + 256, T4);

    // ASPP dilated branches (2,3,4) fused (read buf2t); 1x1 branch exact (raw buf2)
    conv_mma_kernel<true><<<dim3(16, 3, BATCH), 256, CONV_SMEM>>>(
        buf2t, wtA, brb + (long)BATCH * 64 * NPIX, 256, p1, p2);
    for (int i = 0; i < 3; i++)
        finalize_kernel<<<64, 128>>>(p1 + i * 8192, p2 + i * 8192, ag[i + 1], ab[i + 1],
                                     An + (3 + i) * 256, Bn + (3 + i) * 256, 64, 64);
    conv1x1_bn_kernel<<<dim3(64, 1, BATCH), 256>>>(
        buf2, aw[0], brb, 256, An + 256, Bn + 256, p1 + 32768, p2 + 32768);
    finalize_kernel<<<64, 128>>>(p1 + 32768, p2 + 32768, ag[0], ab[0],
                                 An + 2 * 256, Bn + 2 * 256, 64, 256);

    // fused qkv -> q plain + K'/V fragment layouts; pos table
    qkv_kernel<<<dim3(64, 1, 16), 256>>>(brb, wq, bq, wk, bk, wv, bv,
                                         qb, kfb, vfb, An, Bn);
    pos_kernel<<<(64 * NPIX + 255) / 256, 256>>>(rel_h, rel_w);

    // fragment-direct flash attention -> concat output
    flash_mma_kernel<<<dim3(32, BATCH, 4), 256, FLASH3_SMEM>>>(
        qb, kfb, vfb, (float*)d_out);
}

// round 11
// speedup vs baseline: 2.2530x; 1.0099x over previous
#include <cuda_runtime.h>
#include <math_constants.h>
#include <stdint.h>

#define BATCH 4
#define NPIX 4096   // 64*64

// ---------------- scratch (device globals; no cudaMalloc allowed) ----------------
__device__ float g_pool [BATCH * 128 * NPIX];     // maxpool out (tf32-rounded)
__device__ float g_buf1 [BATCH * 256 * NPIX];     // conv1 raw out
__device__ float g_buf1t[BATCH * 256 * NPIX];     // tf32(relu(BN(buf1)))
__device__ float g_buf2 [BATCH * 256 * NPIX];     // conv2 raw out
__device__ float g_buf2t[BATCH * 256 * NPIX];     // tf32(relu(BN(buf2)))
__device__ float g_br  [4 * BATCH * 64 * NPIX];
__device__ float g_q   [4 * BATCH * 64 * NPIX];   // plain q
__device__ float g_kf  [16 * 4096 * 128];         // K' fragment-paired tf32
__device__ float g_vf  [16 * 64 * 256 * 16];      // V  fragment-paired tf32
__device__ float g_pos [64 * NPIX];
__device__ float g_p1  [256 * 256];
__device__ float g_p2  [256 * 256];
__device__ float g_An  [6 * 256];
__device__ float g_Bn  [6 * 256];
__device__ float g_wt  [2654208];   // pre-swizzled tf32 hi/lo conv weights

__device__ __forceinline__ uint32_t f2tf32(float f) {
    uint32_t u;
    asm("cvt.rna.tf32.f32 %0, %1;" : "=r"(u) : "f"(f));
    return u;
}
__device__ __forceinline__ void mma8(float d[4], const uint32_t a[4],
                                     uint32_t b0, uint32_t b1) {
    asm volatile(
        "mma.sync.aligned.m16n8k8.row.col.f32.tf32.tf32.f32 "
        "{%0,%1,%2,%3},{%4,%5,%6,%7},{%8,%9},{%0,%1,%2,%3};"
        : "+f"(d[0]), "+f"(d[1]), "+f"(d[2]), "+f"(d[3])
        : "r"(a[0]), "r"(a[1]), "r"(a[2]), "r"(a[3]), "r"(b0), "r"(b1));
}
__device__ __forceinline__ int ilv(int klo) { return (klo & 3) * 2 + (klo >> 2); }

// ---------------- maxpool 2x2 (emits tf32-rounded: conv1 input) ----------------
__global__ void maxpool_kernel(const float* __restrict__ x, float* __restrict__ out) {
    int idx = blockIdx.x * blockDim.x + threadIdx.x;
    if (idx >= BATCH * 128 * NPIX) return;
    int p  = idx & (NPIX - 1);
    int bc = idx >> 12;
    int y = p >> 6, xx = p & 63;
    const float* src = x + ((long)bc * 128 + 2 * y) * 128 + 2 * xx;
    float v = fmaxf(fmaxf(src[0], src[1]), fmaxf(src[128], src[129]));
    out[idx] = __uint_as_float(f2tf32(v));
}

// ---------------- bnprep: out = tf32(relu(A*v + B)), float4 ----------------
__global__ void bnprep_kernel(const float* __restrict__ in, float* __restrict__ out,
                              const float* __restrict__ A, const float* __restrict__ B,
                              int total4) {
    for (int i = blockIdx.x * blockDim.x + threadIdx.x; i < total4;
         i += gridDim.x * blockDim.x) {
        int c = (i >> 10) & 255;
        float a = A[c], bb = B[c];
        float4 v = ((const float4*)in)[i];
        float4 o;
        o.x = __uint_as_float(f2tf32(fmaxf(v.x * a + bb, 0.f)));
        o.y = __uint_as_float(f2tf32(fmaxf(v.y * a + bb, 0.f)));
        o.z = __uint_as_float(f2tf32(fmaxf(v.z * a + bb, 0.f)));
        o.w = __uint_as_float(f2tf32(fmaxf(v.w * a + bb, 0.f)));
        ((float4*)out)[i] = o;
    }
}

// ---------------- weight prep: OIHW -> [octile][chunk][hi/lo][tap][ocl][ilv8] ----------------
__global__ void wprep_kernel(const float* __restrict__ W, float* __restrict__ dst,
                             int Cin, int Cout, int OCT) {
    int idx = blockIdx.x * 256 + threadIdx.x;
    int total = Cout * Cin * 9;
    if (idx >= total) return;
    int tap = idx % 9;
    int rem = idx / 9;
    int ic  = rem % Cin;
    int oc  = rem / Cin;
    float wv = W[idx];
    float hi = __uint_as_float(f2tf32(wv));
    float lo = __uint_as_float(f2tf32(wv - hi));
    int ocg = oc / OCT, ocl = oc % OCT, chunk = ic >> 3, klo = ic & 7;
    int nch = Cin >> 3;
    long base = (long)(ocg * nch + chunk) * (2 * 9 * OCT * 8);
    dst[base +               (tap * OCT + ocl) * 8 + ilv(klo)] = hi;
    dst[base + 9 * OCT * 8 + (tap * OCT + ocl) * 8 + ilv(klo)] = lo;
}

// ======== tensor-core 3x3 dilated conv: 2-stage cp.async pipeline, 512 thr, 1 CTA/SM ========
// conv1/2 (AS=false): MW=4 (128 oc) x NR=4 rows (256 px). ASPP (AS=true): MW=2 x NR=8.
// 16 warps: mwarp = w/NR, yr = w%NR. Chunk c+1 staged while chunk c computes.
template<bool AS>
__global__ void __launch_bounds__(512, 1) conv_mma_kernel(
    const float* __restrict__ in, const float* __restrict__ wtbase,
    float* __restrict__ outbase, int Cin,
    float* __restrict__ p1base, float* __restrict__ p2base)
{
    constexpr int MW   = AS ? 2 : 4;
    constexpr int NR   = AS ? 8 : 4;
    constexpr int OCT  = MW * 32;
    constexpr int ICS  = 3 * NR * 88 + 8;     // per-ic smem stride (≡8 mod 32: no conflicts)
    constexpr int SIN  = 8 * ICS;
    constexpr int WBLK = 4608 * MW;           // hi+lo weight floats per chunk
    constexpr int LOFF = 9 * OCT * 8;         // lo-half offset (floats)
    constexpr int STAGE = SIN + WBLK;
    constexpr int B1OFF = 4 * ICS;
    constexpr int INF4 = 8 * 3 * NR * 16;     // input float4 per chunk
    constexpr int WF4  = WBLK / 4;
    constexpr int NYT  = 64 / NR;

    extern __shared__ float sm[];
    float* sRS = sm + 2 * STAGE;
    float* sRQ = sRS + 512;

    const int ytile = blockIdx.x;
    const int b     = blockIdx.z;
    const int nchunk = Cin >> 3;
    int dil, ocg, Cout;
    const float* wt;
    float* out;
    float *p1, *p2;
    if (AS) {
        int br = blockIdx.y;               // 0..2 -> dil 3,6,9
        dil = 3 * (br + 1); ocg = 0; Cout = 64;
        wt  = wtbase + (long)br * 294912;
        out = outbase + ((long)br * BATCH + b) * 64 * NPIX;
        p1  = p1base + br * 8192;
        p2  = p2base + br * 8192;
    } else {
        dil = 1; ocg = blockIdx.y; Cout = gridDim.y * OCT;
        wt  = wtbase + (long)ocg * nchunk * WBLK;
        out = outbase + (long)b * Cout * NPIX;
        p1  = p1base; p2 = p2base;
    }
    in += (long)b * Cin * NPIX;

    const int t = threadIdx.x, lane = t & 31, w = t >> 5;
    const int g = lane >> 2, tq = lane & 3;
    const int mwarp = w / NR;
    const int yr    = w % NR;
    const int y0    = ytile * NR;

    const uint32_t smb = (uint32_t)__cvta_generic_to_shared(sm);

    // zero both input stages (halos persist), then barrier before cp.async writes
    for (int i = t; i < SIN; i += 512) { sm[i] = 0.f; sm[STAGE + i] = 0.f; }
    __syncthreads();

    auto issue = [&](int c, int s) {
        const uint32_t stb = smb + (uint32_t)(s * STAGE * 4);
        // weights
        const float4* ws = (const float4*)(wt + (long)c * WBLK);
        const uint32_t swu = stb + (uint32_t)(SIN * 4);
#pragma unroll
        for (int i = t; i < WF4; i += 512)
            asm volatile("cp.async.cg.shared.global [%0], [%1], 16;\n"
                         :: "r"(swu + i * 16), "l"(ws + i));
        // inputs (OOB rows zero-filled)
        const float* inc = in + (long)c * 8 * NPIX;
#pragma unroll
        for (int e = t; e < INF4; e += 512) {
            int fx  = e & 15;
            int row = e >> 4;
            int ic  = row / (3 * NR);
            int r2  = row - ic * (3 * NR);
            int ky  = r2 / NR, yri = r2 - ky * NR;
            int ry  = y0 + yri + (ky - 1) * dil;
            int ok  = (ry >= 0 && ry < 64);
            uint32_t dst = stb + (uint32_t)((ic * ICS + (ky * NR + yri) * 88 + 12) * 4 + fx * 16);
            const float4* src = (const float4*)(inc + ic * NPIX + (ok ? ry : 0) * 64) + fx;
            int ssz = ok ? 16 : 0;
            asm volatile("cp.async.cg.shared.global [%0], [%1], 16, %2;\n"
                         :: "r"(dst), "l"(src), "r"(ssz));
        }
        asm volatile("cp.async.commit_group;\n");
    };

    float acc[2][8][4];
#pragma unroll
    for (int mf = 0; mf < 2; mf++)
#pragma unroll
        for (int nt = 0; nt < 8; nt++)
#pragma unroll
            for (int c = 0; c < 4; c++) acc[mf][nt][c] = 0.f;

    issue(0, 0);

    for (int chunk = 0; chunk < nchunk; chunk++) {
        const int s = chunk & 1;
        if (chunk + 1 < nchunk) {
            issue(chunk + 1, s ^ 1);
            asm volatile("cp.async.wait_group 1;\n" ::: "memory");
        } else {
            asm volatile("cp.async.wait_group 0;\n" ::: "memory");
        }
        __syncthreads();

        const float* sIn = sm + s * STAGE;
        const float* sW  = sIn + SIN;

#pragma unroll
        for (int tap = 0; tap < 9; tap++) {
            const int ky = tap / 3, kx = tap % 3;
            const uint32_t* bp = (const uint32_t*)(sIn) +
                tq * ICS + (ky * NR + yr) * 88 + 12 + g + (kx - 1) * dil;
            const float* wb = sW + (tap * OCT + mwarp * 32 + g) * 8 + 2 * tq;
            uint2 h0  = *(const uint2*)(wb);
            uint2 h0b = *(const uint2*)(wb + 64);
            uint2 h1  = *(const uint2*)(wb + 128);
            uint2 h1b = *(const uint2*)(wb + 192);
            uint2 l0  = *(const uint2*)(wb + LOFF);
            uint2 l0b = *(const uint2*)(wb + LOFF + 64);
            uint2 l1  = *(const uint2*)(wb + LOFF + 128);
            uint2 l1b = *(const uint2*)(wb + LOFF + 192);
            uint32_t aH0[4] = {h0.x, h0b.x, h0.y, h0b.y};
            uint32_t aH1[4] = {h1.x, h1b.x, h1.y, h1b.y};
            uint32_t aL0[4] = {l0.x, l0b.x, l0.y, l0b.y};
            uint32_t aL1[4] = {l1.x, l1b.x, l1.y, l1b.y};
#pragma unroll
            for (int nt = 0; nt < 8; nt++) {
                uint32_t b0 = bp[nt * 8];
                uint32_t b1 = bp[nt * 8 + B1OFF];
                mma8(acc[0][nt], aH0, b0, b1);
                mma8(acc[0][nt], aL0, b0, b1);
                mma8(acc[1][nt], aH1, b0, b1);
                mma8(acc[1][nt], aL1, b0, b1);
            }
        }
        __syncthreads();   // protect buf[s] before it is re-staged (chunk+2)
    }

    // ---- epilogue: store + BN partials ----
    float s_[2][2] = {{0.f, 0.f}, {0.f, 0.f}};
    float q_[2][2] = {{0.f, 0.f}, {0.f, 0.f}};
    const int ocb = ocg * OCT + mwarp * 32;
#pragma unroll
    for (int mf = 0; mf < 2; mf++) {
        int oc = ocb + mf * 16 + g;
#pragma unroll
        for (int nt = 0; nt < 8; nt++) {
            int gx = (y0 + yr) * 64 + nt * 8 + 2 * tq;
            float c0 = acc[mf][nt][0], c1 = acc[mf][nt][1];
            float c2 = acc[mf][nt][2], c3 = acc[mf][nt][3];
            out[(long)oc * NPIX + gx]           = c0;
            out[(long)oc * NPIX + gx + 1]       = c1;
            out[(long)(oc + 8) * NPIX + gx]     = c2;
            out[(long)(oc + 8) * NPIX + gx + 1] = c3;
            s_[mf][0] += c0 + c1; q_[mf][0] += c0 * c0 + c1 * c1;
            s_[mf][1] += c2 + c3; q_[mf][1] += c2 * c2 + c3 * c3;
        }
    }
#pragma unroll
    for (int mf = 0; mf < 2; mf++)
#pragma unroll
        for (int ro = 0; ro < 2; ro++) {
            float a = s_[mf][ro], qq = q_[mf][ro];
            a  += __shfl_xor_sync(0xffffffffu, a, 1);
            qq += __shfl_xor_sync(0xffffffffu, qq, 1);
            a  += __shfl_xor_sync(0xffffffffu, a, 2);
            qq += __shfl_xor_sync(0xffffffffu, qq, 2);
            if (tq == 0) {
                sRS[w * 32 + mf * 16 + ro * 8 + g] = a;
                sRQ[w * 32 + mf * 16 + ro * 8 + g] = qq;
            }
        }
    __syncthreads();
    if (t < OCT) {
        int mw = t >> 5, cl = t & 31;
        float a = 0.f, qq = 0.f;
#pragma unroll
        for (int j = 0; j < NR; j++) {
            a  += sRS[(mw * NR + j) * 32 + cl];
            qq += sRQ[(mw * NR + j) * 32 + cl];
        }
        int slot = b * NYT + ytile;
        p1[slot * Cout + ocg * OCT + t] = a;
        p2[slot * Cout + ocg * OCT + t] = qq;
    }
}

// ---------------- BN finalize ----------------
__global__ void finalize_kernel(const float* __restrict__ p1, const float* __restrict__ p2,
                                const float* __restrict__ g, const float* __restrict__ be,
                                float* __restrict__ A, float* __restrict__ B,
                                int C, int nslots) {
    const int c = blockIdx.x, t = threadIdx.x;
    float s = 0.f, q = 0.f;
    for (int slot = t; slot < nslots; slot += 128) {
        s += p1[slot * C + c];
        q += p2[slot * C + c];
    }
    __shared__ float rs[4], rq[4];
#pragma unroll
    for (int off = 16; off; off >>= 1) {
        s += __shfl_down_sync(0xffffffffu, s, off);
        q += __shfl_down_sync(0xffffffffu, q, off);
    }
    int lane = t & 31, wp = t >> 5;
    if (!lane) { rs[wp] = s; rq[wp] = q; }
    __syncthreads();
    if (t == 0) {
        s = rs[0] + rs[1] + rs[2] + rs[3];
        q = rq[0] + rq[1] + rq[2] + rq[3];
        const float inv = 1.f / (float)(BATCH * NPIX);
        float mean = s * inv;
        float var  = q * inv - mean * mean;
        float a = g[c] * rsqrtf(var + 1e-5f);
        A[c] = a;
        B[c] = be[c] - mean * a;
    }
}

// ---------------- 1x1 conv Cout=64 with input-BN + stats (aspp1, exact fp32) ----------------
__global__ void __launch_bounds__(256) conv1x1_bn_kernel(
    const float* __restrict__ in, const float* __restrict__ w,
    float* __restrict__ out, int Cin,
    const float* __restrict__ Abn, const float* __restrict__ Bbn,
    float* __restrict__ p1, float* __restrict__ p2)
{
    const int p0 = blockIdx.x * 64;
    const int b  = blockIdx.z;
    in  += (long)b * Cin * NPIX;
    out += (long)b * 64  * NPIX;
    const int t = threadIdx.x, tx = t & 15, ty = t >> 4;

    __shared__ float sW [16 * 68];
    __shared__ float sIn[16 * 64];

    float acc[4][4];
#pragma unroll
    for (int r = 0; r < 4; r++)
#pragma unroll
        for (int c = 0; c < 4; c++) acc[r][c] = 0.f;

    for (int ic0 = 0; ic0 < Cin; ic0 += 16) {
        __syncthreads();
        for (int idx = t; idx < 1024; idx += 256) {
            int ic = idx & 15, oc = idx >> 4;
            sW[ic * 68 + oc] = w[(long)oc * Cin + ic0 + ic];
        }
        for (int idx = t; idx < 1024; idx += 256) {
            int ic = idx >> 6, px = idx & 63;
            int c = ic0 + ic;
            float v = in[c * NPIX + p0 + px];
            sIn[idx] = fmaxf(v * Abn[c] + Bbn[c], 0.f);
        }
        __syncthreads();
#pragma unroll
        for (int ic = 0; ic < 16; ic++) {
            float4 a  = *(const float4*)(sW  + ic * 68 + ty * 4);
            float4 xv = *(const float4*)(sIn + ic * 64 + tx * 4);
            float av[4] = {a.x, a.y, a.z, a.w};
            float xa[4] = {xv.x, xv.y, xv.z, xv.w};
#pragma unroll
            for (int r = 0; r < 4; r++)
#pragma unroll
                for (int c = 0; c < 4; c++) acc[r][c] += av[r] * xa[c];
        }
    }
    float sums[4], sqs[4];
#pragma unroll
    for (int r = 0; r < 4; r++) {
        float s = 0.f, q = 0.f;
        float* op = out + (long)(ty * 4 + r) * NPIX + p0 + tx * 4;
#pragma unroll
        for (int c = 0; c < 4; c++) {
            float v = acc[r][c];
            op[c] = v; s += v; q += v * v;
        }
        sums[r] = s; sqs[r] = q;
    }
#pragma unroll
    for (int r = 0; r < 4; r++) {
        float a = sums[r], q = sqs[r];
#pragma unroll
        for (int off = 1; off < 16; off <<= 1) {
            a += __shfl_xor_sync(0xffffffffu, a, off);
            q += __shfl_xor_sync(0xffffffffu, q, off);
        }
        if (tx == 0) {
            int c = ty * 4 + r;
            int slot = b * 64 + blockIdx.x;
            p1[slot * 64 + c] = a;
            p2[slot * 64 + c] = q;
        }
    }
}

// ---------------- fused q/k/v 1x1 projections -> q plain + K'/V fragment layouts ----------------
__global__ void __launch_bounds__(256) qkv_kernel(
    const float* __restrict__ brin,
    const float* __restrict__ wq, const float* __restrict__ bq,
    const float* __restrict__ wk, const float* __restrict__ bk,
    const float* __restrict__ wv, const float* __restrict__ bv,
    float* __restrict__ qo, float* __restrict__ kf, float* __restrict__ vf,
    const float* __restrict__ Abase, const float* __restrict__ Bbase)
{
    const int p0  = blockIdx.x * 64;
    const int img = blockIdx.z;
    const int br  = img >> 2;
    const long ib = (long)img * 64 * NPIX;
    const float* A  = Abase + (2 + br) * 256;
    const float* Bb = Bbase + (2 + br) * 256;
    const int t = threadIdx.x, tx = t & 15, ty = t >> 4;

    float* kfp = kf + (long)img * 524288;
    float* vfp = vf + (long)img * 262144;

    __shared__ float sW [3 * 16 * 64];
    __shared__ float sIn[16 * 64];

    float acc[3][4][4];
#pragma unroll
    for (int m = 0; m < 3; m++)
#pragma unroll
        for (int r = 0; r < 4; r++)
#pragma unroll
            for (int c = 0; c < 4; c++) acc[m][r][c] = 0.f;

    for (int ic0 = 0; ic0 < 64; ic0 += 16) {
        __syncthreads();
        for (int i = t; i < 1024; i += 256) {
            int ic = i >> 6, px = i & 63;
            int c = ic0 + ic;
            float v = brin[ib + (long)c * NPIX + p0 + px];
            sIn[i] = fmaxf(v * A[c] + Bb[c], 0.f);
        }
        for (int i = t; i < 3072; i += 256) {
            int m = i >> 10, r = i & 1023;
            int ic = r & 15, oc = r >> 4;
            const float* wm = (m == 0) ? wq : ((m == 1) ? wk : wv);
            sW[m * 1024 + ic * 64 + oc] = wm[oc * 64 + ic0 + ic];
        }
        __syncthreads();
#pragma unroll
        for (int ic = 0; ic < 16; ic++) {
            float4 xv = *(const float4*)(sIn + ic * 64 + tx * 4);
            float xa[4] = {xv.x, xv.y, xv.z, xv.w};
#pragma unroll
            for (int m = 0; m < 3; m++) {
                float4 a = *(const float4*)(sW + m * 1024 + ic * 64 + ty * 4);
                float av[4] = {a.x, a.y, a.z, a.w};
#pragma unroll
                for (int r = 0; r < 4; r++)
#pragma unroll
                    for (int c = 0; c < 4; c++) acc[m][r][c] += av[r] * xa[c];
            }
        }
    }
    const float* bs[3] = {bq, bk, bv};
#pragma unroll
    for (int m = 0; m < 3; m++) {
#pragma unroll
        for (int r = 0; r < 4; r++) {
            int oc = ty * 4 + r;
            float bb = bs[m][oc];
#pragma unroll
            for (int ci = 0; ci < 4; ci++) {
                int j = p0 + tx * 4 + ci;
                float val = acc[m][r][ci] + bb;
                if (m == 0) {
                    qo[ib + (long)oc * NPIX + j] = val;
                    int kk = 64 + oc, ks = kk >> 3, klo = kk & 7;
                    int slot = (ks >> 1) * 16 + (klo & 3) * 4 + (ks & 1) * 2 + (klo >> 2);
                    kfp[j * 128 + slot] = __uint_as_float(f2tf32(val));
                } else if (m == 1) {
                    int kk = oc, ks = kk >> 3, klo = kk & 7;
                    int slot = (ks >> 1) * 16 + (klo & 3) * 4 + (ks & 1) * 2 + (klo >> 2);
                    kfp[j * 128 + slot] = __uint_as_float(f2tf32(val));
                } else {
                    int ksv = j >> 3, jlo = j & 7;
                    int slot = (jlo & 3) * 4 + (ksv & 1) * 2 + (jlo >> 2);
                    vfp[(oc * 256 + (ksv >> 1)) * 16 + slot] = __uint_as_float(f2tf32(val));
                }
            }
        }
    }
}

// ---------------- pos table ----------------
__global__ void pos_kernel(const float* __restrict__ rh, const float* __restrict__ rw) {
    int idx = blockIdx.x * blockDim.x + threadIdx.x;
    if (idx >= 64 * NPIX) return;
    int d = idx >> 12, n = idx & 4095, a = n >> 6, bb = n & 63;
    g_pos[idx] = rh[d * 64 + bb] + rw[d * 64 + a];
}

// ================= fragment-direct tf32 flash attention =================
#define FLASH3_SMEM (8192 * 4)

__global__ void __launch_bounds__(256, 1) flash_mma_kernel(
    const float* __restrict__ qg, const float* __restrict__ kf,
    const float* __restrict__ vf, float* __restrict__ outg)
{
    extern __shared__ uint32_t smu[];
    uint32_t* sP = smu;

    const int i0 = blockIdx.x * 128;
    const int b  = blockIdx.y, br = blockIdx.z;
    const int img = br * BATCH + b;
    const float* q = qg + (long)img * 64 * NPIX;
    const uint4* KF = (const uint4*)(kf + (long)img * 524288);
    const uint4* VF = (const uint4*)(vf + (long)img * 262144);
    float* outp = outg + (long)(b * 256 + br * 64) * NPIX;

    const int t = threadIdx.x;
    const int lane = t & 31, w = t >> 5;
    const int g = lane >> 2, tq = lane & 3;

    uint32_t Qf[16][4];
    {
        int i_r = i0 + w * 16 + g;
#pragma unroll
        for (int ks = 0; ks < 16; ks++) {
            int kc = ks * 8 + tq;
            const float* s0 = (kc < 64)     ? (q + kc * NPIX)       : (g_pos + (kc - 64) * NPIX);
            const float* s1 = (kc + 4 < 64) ? (q + (kc + 4) * NPIX) : (g_pos + (kc - 60) * NPIX);
            Qf[ks][0] = f2tf32(s0[i_r]);
            Qf[ks][1] = f2tf32(s0[i_r + 8]);
            Qf[ks][2] = f2tf32(s1[i_r]);
            Qf[ks][3] = f2tf32(s1[i_r + 8]);
        }
    }

    float Oa[8][4];
#pragma unroll
    for (int nt = 0; nt < 8; nt++)
#pragma unroll
        for (int c = 0; c < 4; c++) Oa[nt][c] = 0.f;
    float m0 = -CUDART_INF_F, m1 = -CUDART_INF_F, l0 = 0.f, l1 = 0.f;

    const int p00 = ((2 * tq) & 3) * 2 + (tq >> 1);
    const int p01 = ((2 * tq + 1) & 3) * 2 + ((2 * tq + 1) >> 2);
    const int pb  = w * 1024 + g * 8;

    for (int j0 = 0; j0 < NPIX; j0 += 64) {
        float Sa[8][4];
#pragma unroll
        for (int nt = 0; nt < 8; nt++)
#pragma unroll
            for (int c = 0; c < 4; c++) Sa[nt][c] = 0.f;
#pragma unroll
        for (int kp = 0; kp < 8; kp++) {
#pragma unroll
            for (int nt = 0; nt < 8; nt++) {
                uint4 kb = KF[(j0 + nt * 8 + g) * 32 + kp * 4 + tq];
                mma8(Sa[nt], Qf[2 * kp],     kb.x, kb.y);
                mma8(Sa[nt], Qf[2 * kp + 1], kb.z, kb.w);
            }
        }

        float mx0 = -CUDART_INF_F, mx1 = -CUDART_INF_F;
#pragma unroll
        for (int nt = 0; nt < 8; nt++) {
            mx0 = fmaxf(mx0, fmaxf(Sa[nt][0], Sa[nt][1]));
            mx1 = fmaxf(mx1, fmaxf(Sa[nt][2], Sa[nt][3]));
        }
        mx0 = fmaxf(mx0, __shfl_xor_sync(0xffffffffu, mx0, 1));
        mx0 = fmaxf(mx0, __shfl_xor_sync(0xffffffffu, mx0, 2));
        mx1 = fmaxf(mx1, __shfl_xor_sync(0xffffffffu, mx1, 1));
        mx1 = fmaxf(mx1, __shfl_xor_sync(0xffffffffu, mx1, 2));
        float mn0 = fmaxf(m0, mx0), mn1 = fmaxf(m1, mx1);
        float al0 = __expf(m0 - mn0), al1 = __expf(m1 - mn1);

        float su0 = 0.f, su1 = 0.f;
#pragma unroll
        for (int nt = 0; nt < 8; nt++) {
            float e00 = __expf(Sa[nt][0] - mn0);
            float e01 = __expf(Sa[nt][1] - mn0);
            float e10 = __expf(Sa[nt][2] - mn1);
            float e11 = __expf(Sa[nt][3] - mn1);
            su0 += e00 + e01; su1 += e10 + e11;
            sP[pb + nt * 128 + p00]      = f2tf32(e00);
            sP[pb + nt * 128 + p01]      = f2tf32(e01);
            sP[pb + nt * 128 + 64 + p00] = f2tf32(e10);
            sP[pb + nt * 128 + 64 + p01] = f2tf32(e11);
        }
        su0 += __shfl_xor_sync(0xffffffffu, su0, 1);
        su0 += __shfl_xor_sync(0xffffffffu, su0, 2);
        su1 += __shfl_xor_sync(0xffffffffu, su1, 1);
        su1 += __shfl_xor_sync(0xffffffffu, su1, 2);
        l0 = l0 * al0 + su0; l1 = l1 * al1 + su1;
        m0 = mn0; m1 = mn1;
#pragma unroll
        for (int nt = 0; nt < 8; nt++) {
            Oa[nt][0] *= al0; Oa[nt][1] *= al0;
            Oa[nt][2] *= al1; Oa[nt][3] *= al1;
        }
        __syncwarp();

#pragma unroll
        for (int kpl = 0; kpl < 4; kpl++) {
            const uint32_t* ape = &sP[w * 1024 + (2 * kpl) * 128 + g * 8 + 2 * tq];
            uint2 e02 = *(const uint2*)ape;
            uint2 e13 = *(const uint2*)(ape + 64);
            uint2 o02 = *(const uint2*)(ape + 128);
            uint2 o13 = *(const uint2*)(ape + 192);
            uint32_t ae[4] = {e02.x, e13.x, e02.y, e13.y};
            uint32_t ao[4] = {o02.x, o13.x, o02.y, o13.y};
#pragma unroll
            for (int nt = 0; nt < 8; nt++) {
                uint4 vb = VF[((nt * 8 + g) * 256 + (j0 >> 4) + kpl) * 4 + tq];
                mma8(Oa[nt], ae, vb.x, vb.y);
                mma8(Oa[nt], ao, vb.z, vb.w);
            }
        }
        __syncwarp();
    }

    float inv0 = 1.f / l0, inv1 = 1.f / l1;
    int pix = i0 + w * 16 + g;
#pragma unroll
    for (int nt = 0; nt < 8; nt++) {
        int d0 = nt * 8 + 2 * tq;
        outp[(long)d0 * NPIX + pix]           = Oa[nt][0] * inv0;
        outp[(long)(d0 + 1) * NPIX + pix]     = Oa[nt][1] * inv0;
        outp[(long)d0 * NPIX + pix + 8]       = Oa[nt][2] * inv1;
        outp[(long)(d0 + 1) * NPIX + pix + 8] = Oa[nt][3] * inv1;
    }
}

// ---------------- host orchestration ----------------
extern "C" void kernel_launch(void* const* d_in, const int* in_sizes, int n_in,
                              void* d_out, int out_size) {
    const float* x      = (const float*)d_in[0];
    const float* dc_w1  = (const float*)d_in[1];
    const float* dc_g1  = (const float*)d_in[3];
    const float* dc_be1 = (const float*)d_in[4];
    const float* dc_w2  = (const float*)d_in[5];
    const float* dc_g2  = (const float*)d_in[7];
    const float* dc_be2 = (const float*)d_in[8];
    const float* aw[4]  = {(const float*)d_in[9],  (const float*)d_in[12],
                           (const float*)d_in[15], (const float*)d_in[18]};
    const float* ag[4]  = {(const float*)d_in[10], (const float*)d_in[13],
                           (const float*)d_in[16], (const float*)d_in[19]};
    const float* ab[4]  = {(const float*)d_in[11], (const float*)d_in[14],
                           (const float*)d_in[17], (const float*)d_in[20]};
    const float* wq = (const float*)d_in[21]; const float* bq = (const float*)d_in[22];
    const float* wk = (const float*)d_in[23]; const float* bk = (const float*)d_in[24];
    const float* wv = (const float*)d_in[25]; const float* bv = (const float*)d_in[26];
    const float* rel_h = (const float*)d_in[27];
    const float* rel_w = (const float*)d_in[28];

    float *pool, *buf1, *buf1t, *buf2, *buf2t, *brb, *qb, *kfb, *vfb;
    float *p1, *p2, *An, *Bn, *wt;
    cudaGetSymbolAddress((void**)&pool,  g_pool);
    cudaGetSymbolAddress((void**)&buf1,  g_buf1);
    cudaGetSymbolAddress((void**)&buf1t, g_buf1t);
    cudaGetSymbolAddress((void**)&buf2,  g_buf2);
    cudaGetSymbolAddress((void**)&buf2t, g_buf2t);
    cudaGetSymbolAddress((void**)&brb,   g_br);
    cudaGetSymbolAddress((void**)&qb,    g_q);
    cudaGetSymbolAddress((void**)&kfb,   g_kf);
    cudaGetSymbolAddress((void**)&vfb,   g_vf);
    cudaGetSymbolAddress((void**)&p1,    g_p1);
    cudaGetSymbolAddress((void**)&p2,    g_p2);
    cudaGetSymbolAddress((void**)&An,    g_An);
    cudaGetSymbolAddress((void**)&Bn,    g_Bn);
    cudaGetSymbolAddress((void**)&wt,    g_wt);

    float* wt1 = wt;                 // conv1: 589824 (OCT=128)
    float* wt2 = wt + 589824;        // conv2: 1179648 (OCT=128)
    float* wtA = wt + 1769472;       // aspp: 3 x 294912 (OCT=64)

    // smem sizes: conv stage=26944, aspp stage=26176 floats; +1024 reduction
    const int CSMEM = (2 * 26944 + 1024) * 4;   // 219648 B
    const int ASMEM = (2 * 26176 + 1024) * 4;   // 213504 B
    cudaFuncSetAttribute((const void*)conv_mma_kernel<false>,
                         cudaFuncAttributeMaxDynamicSharedMemorySize, CSMEM);
    cudaFuncSetAttribute((const void*)conv_mma_kernel<true>,
                         cudaFuncAttributeMaxDynamicSharedMemorySize, ASMEM);
    cudaFuncSetAttribute((const void*)flash_mma_kernel,
                         cudaFuncAttributeMaxDynamicSharedMemorySize, FLASH3_SMEM);

    // weight prep
    wprep_kernel<<<(256 * 128 * 9 + 255) / 256, 256>>>(dc_w1, wt1, 128, 256, 128);
    wprep_kernel<<<(256 * 256 * 9 + 255) / 256, 256>>>(dc_w2, wt2, 256, 256, 128);
    for (int i = 0; i < 3; i++)
        wprep_kernel<<<(64 * 256 * 9 + 255) / 256, 256>>>(
            aw[i + 1], wtA + (long)i * 294912, 256, 64, 64);

    const int T4 = BATCH * 256 * NPIX / 4;

    // mpconv: pool(tf32) -> conv1 -> fin1 -> bnprep1 -> conv2 -> fin2 -> bnprep2
    maxpool_kernel<<<(BATCH * 128 * NPIX + 255) / 256, 256>>>(x, pool);
    conv_mma_kernel<false><<<dim3(16, 2, BATCH), 512, CSMEM>>>(
        pool, wt1, buf1, 128, p1, p2);
    finalize_kernel<<<256, 128>>>(p1, p2, dc_g1, dc_be1, An + 0, Bn + 0, 256, 64);
    bnprep_kernel<<<2048, 256>>>(buf1, buf1t, An + 0, Bn + 0, T4);
    conv_mma_kernel<false><<<dim3(16, 2, BATCH), 512, CSMEM>>>(
        buf1t, wt2, buf2, 256, p1, p2);
    finalize_kernel<<<256, 128>>>(p1, p2, dc_g2, dc_be2, An + 256, Bn + 256, 256, 64);
    bnprep_kernel<<<2048, 256>>>(buf2, buf2t, An + 256, Bn + 256, T4);

    // ASPP dilated branches (2,3,4) fused (read buf2t); 1x1 branch exact (raw buf2)
    conv_mma_kernel<true><<<dim3(8, 3, BATCH), 512, ASMEM>>>(
        buf2t, wtA, brb + (long)BATCH * 64 * NPIX, 256, p1, p2);
    for (int i = 0; i < 3; i++)
        finalize_kernel<<<64, 128>>>(p1 + i * 8192, p2 + i * 8192, ag[i + 1], ab[i + 1],
                                     An + (3 + i) * 256, Bn + (3 + i) * 256, 64, 32);
    conv1x1_bn_kernel<<<dim3(64, 1, BATCH), 256>>>(
        buf2, aw[0], brb, 256, An + 256, Bn + 256, p1 + 32768, p2 + 32768);
    finalize_kernel<<<64, 128>>>(p1 + 32768, p2 + 32768, ag[0], ab[0],
                                 An + 2 * 256, Bn + 2 * 256, 64, 256);

    // fused qkv -> q plain + K'/V fragment layouts; pos table
    qkv_kernel<<<dim3(64, 1, 16), 256>>>(brb, wq, bq, wk, bk, wv, bv,
                                         qb, kfb, vfb, An, Bn);
    pos_kernel<<<(64 * NPIX + 255) / 256, 256>>>(rel_h, rel_w);

    // fragment-direct flash attention -> concat output
    flash_mma_kernel<<<dim3(32, BATCH, 4), 256, FLASH3_SMEM>>>(
        qb, kfb, vfb, (float*)d_out);
}

// round 12
// speedup vs baseline: 2.4379x; 1.0821x over previous
#include <cuda_runtime.h>
#include <cuda_bf16.h>
#include <math_constants.h>
#include <stdint.h>

#define BATCH 4
#define NPIX 4096   // 64*64

// ---------------- scratch (device globals; no cudaMalloc allowed) ----------------
__device__ float g_buf1 [BATCH * 256 * NPIX];      // conv1 raw out (fp32)
__device__ float g_buf2 [BATCH * 256 * NPIX];      // conv2 raw out (fp32)
__device__ float g_xt0  [BATCH * 8  * 2 * NPIX * 8];   // conv1 input packed bf16 hi/lo
__device__ float g_xt1  [BATCH * 16 * 2 * NPIX * 8];   // conv2 input packed
__device__ float g_xt2  [BATCH * 16 * 2 * NPIX * 8];   // aspp  input packed
__device__ float g_br  [4 * BATCH * 64 * NPIX];
__device__ float g_q   [4 * BATCH * 64 * NPIX];    // plain q
__device__ float g_kf  [16 * 4096 * 128];          // K' fragment-paired tf32
__device__ float g_vf  [16 * 64 * 256 * 16];       // V  fragment-paired tf32
__device__ float g_pos [64 * NPIX];
__device__ float g_p1  [256 * 256];
__device__ float g_p2  [256 * 256];
__device__ float g_An  [6 * 256];
__device__ float g_Bn  [6 * 256];
__device__ float g_wt  [1327104];   // packed bf16 hi/lo conv weights

__device__ __forceinline__ uint32_t f2tf32(float f) {
    uint32_t u;
    asm("cvt.rna.tf32.f32 %0, %1;" : "=r"(u) : "f"(f));
    return u;
}
__device__ __forceinline__ float ex2f(float x) {
    float y;
    asm("ex2.approx.ftz.f32 %0, %1;" : "=f"(y) : "f"(x));
    return y;
}
__device__ __forceinline__ void mma8(float d[4], const uint32_t a[4],
                                     uint32_t b0, uint32_t b1) {
    asm volatile(
        "mma.sync.aligned.m16n8k8.row.col.f32.tf32.tf32.f32 "
        "{%0,%1,%2,%3},{%4,%5,%6,%7},{%8,%9},{%0,%1,%2,%3};"
        : "+f"(d[0]), "+f"(d[1]), "+f"(d[2]), "+f"(d[3])
        : "r"(a[0]), "r"(a[1]), "r"(a[2]), "r"(a[3]), "r"(b0), "r"(b1));
}
__device__ __forceinline__ void mma16(float d[4], const uint32_t a[4],
                                      uint32_t b0, uint32_t b1) {
    asm volatile(
        "mma.sync.aligned.m16n8k16.row.col.f32.bf16.bf16.f32 "
        "{%0,%1,%2,%3},{%4,%5,%6,%7},{%8,%9},{%0,%1,%2,%3};"
        : "+f"(d[0]), "+f"(d[1]), "+f"(d[2]), "+f"(d[3])
        : "r"(a[0]), "r"(a[1]), "r"(a[2]), "r"(a[3]), "r"(b0), "r"(b1));
}
__device__ __forceinline__ int ilv(int klo) { return (klo & 3) * 2 + (klo >> 2); }
__device__ __forceinline__ uint32_t pk2bf(float a, float b) {
    __nv_bfloat162 t = __floats2bfloat162_rn(a, b);
    return *reinterpret_cast<uint32_t*>(&t);
}
__device__ __forceinline__ float bfhi(float x) {
    return __bfloat162float(__float2bfloat16(x));
}

// ---------------- maxpool 2x2 -> packed bf16 hi/lo channel-pair layout ----------------
// xt layout: [b][chunk Cin/16][term hi/lo][pix 4096][8 words], word slot ilv(j) = ch (2j,2j+1)
__global__ void maxpool_xt_kernel(const float* __restrict__ x, float* __restrict__ xt) {
    int idx = blockIdx.x * blockDim.x + threadIdx.x;
    if (idx >= BATCH * 64 * NPIX) return;
    int pix = idx & 4095, rest = idx >> 12;
    int cp = rest & 63, b = rest >> 6;
    int y = pix >> 6, xx = pix & 63;
    float v[2];
#pragma unroll
    for (int e = 0; e < 2; e++) {
        const float* src = x + ((long)(b * 128 + 2 * cp + e) * 128 + 2 * y) * 128 + 2 * xx;
        v[e] = fmaxf(fmaxf(src[0], src[1]), fmaxf(src[128], src[129]));
    }
    float h0 = bfhi(v[0]), h1 = bfhi(v[1]);
    int chunk = cp >> 3, j = cp & 7;
    long base = (((long)(b * 8 + chunk) * 2) * 4096 + pix) * 8 + ilv(j);
    uint32_t* out = (uint32_t*)xt;
    out[base]         = pk2bf(h0, h1);
    out[base + 32768] = pk2bf(v[0] - h0, v[1] - h1);
}

// ---------------- bnprep: raw fp32 [c][pix] -> relu(BN) -> packed bf16 hi/lo ----------------
__global__ void bnprep_xt_kernel(const float* __restrict__ in, float* __restrict__ xt,
                                 const float* __restrict__ A, const float* __restrict__ B) {
    int idx = blockIdx.x * blockDim.x + threadIdx.x;
    if (idx >= BATCH * 128 * NPIX) return;
    int pix = idx & 4095, rest = idx >> 12;
    int cp = rest & 127, b = rest >> 7;
    int c0 = 2 * cp;
    float v0 = fmaxf(in[((long)(b * 256 + c0)) * NPIX + pix] * A[c0] + B[c0], 0.f);
    float v1 = fmaxf(in[((long)(b * 256 + c0 + 1)) * NPIX + pix] * A[c0 + 1] + B[c0 + 1], 0.f);
    float h0 = bfhi(v0), h1 = bfhi(v1);
    int chunk = cp >> 3, j = cp & 7;
    long base = (((long)(b * 16 + chunk) * 2) * 4096 + pix) * 8 + ilv(j);
    uint32_t* out = (uint32_t*)xt;
    out[base]         = pk2bf(h0, h1);
    out[base + 32768] = pk2bf(v0 - h0, v1 - h1);
}

// ---------------- weight prep: OIHW -> [ocg64][chunk16ic][hi/lo][tap][ocl][8 words] ----------------
__global__ void wprep_kernel(const float* __restrict__ W, float* __restrict__ dst,
                             int Cin, int Cout) {
    int idx = blockIdx.x * 256 + threadIdx.x;
    int cp = Cin >> 1;
    int total = Cout * cp * 9;
    if (idx >= total) return;
    int tap = idx % 9;
    int rem = idx / 9;
    int jp  = rem % cp;
    int oc  = rem / cp;
    float w0 = W[((long)oc * Cin + 2 * jp) * 9 + tap];
    float w1 = W[((long)oc * Cin + 2 * jp + 1) * 9 + tap];
    float h0 = bfhi(w0), h1 = bfhi(w1);
    int ocg = oc >> 6, ocl = oc & 63, chunk = jp >> 3, j = jp & 7;
    int nch = Cin >> 4;
    long base = (long)(ocg * nch + chunk) * 9216;
    uint32_t* d = (uint32_t*)dst;
    d[base +        (tap * 64 + ocl) * 8 + ilv(j)] = pk2bf(h0, h1);
    d[base + 4608 + (tap * 64 + ocl) * 8 + ilv(j)] = pk2bf(w0 - h0, w1 - h1);
}

// ======== bf16 3-term tensor-core 3x3 dilated conv, 2-stage cp.async pipeline ========
// 512 thr = 16 warps (mwarp 2 x yr 4 x nh 2). CTA tile: 64 oc x 256 px (4 y rows).
// warp m32 x n32. K-chunk = 16 ic (k16 MMA). terms: Ah*Bh + Ah*Bl + Al*Bh.
#define TSW   8448          // words per input term ([12 rows][88px][8w])
#define SINW  16896         // 2 terms
#define WW    9216          // weight words per chunk (hi+lo)
#define STAGEW 26112
#define CSM   ((2 * STAGEW + 1024) * 4)
template<bool AS>
__global__ void __launch_bounds__(512, 1) conv_mma_kernel(
    const float* __restrict__ in, const float* __restrict__ wtbase,
    float* __restrict__ outbase, int Cin,
    float* __restrict__ p1base, float* __restrict__ p2base)
{
    extern __shared__ float sm[];
    float* sRS = sm + 2 * STAGEW;
    float* sRQ = sRS + 512;

    const int ytile = blockIdx.x;          // 0..15
    const int b     = blockIdx.z;
    const int nchunk = Cin >> 4;
    int dil, ocg, Cout;
    const float* wt;
    float* out;
    float *p1, *p2;
    if (AS) {
        int br = blockIdx.y;               // 0..2 -> dil 3,6,9
        dil = 3 * (br + 1); ocg = 0; Cout = 64;
        wt  = wtbase + (long)br * 147456;
        out = outbase + ((long)br * BATCH + b) * 64 * NPIX;
        p1  = p1base + br * 8192;
        p2  = p2base + br * 8192;
    } else {
        dil = 1; ocg = blockIdx.y; Cout = gridDim.y * 64;
        wt  = wtbase + (long)ocg * nchunk * WW;
        out = outbase + (long)b * Cout * NPIX;
        p1  = p1base; p2 = p2base;
    }
    in += (long)b * nchunk * 65536;        // [chunk][term][4096][8w]

    const int t = threadIdx.x, lane = t & 31, w = t >> 5;
    const int g = lane >> 2, tq = lane & 3;
    const int mwarp = w >> 3;              // 0..1
    const int yr    = (w >> 1) & 3;        // 0..3
    const int nh    = w & 1;               // 0..1
    const int y0    = ytile * 4;

    const uint32_t smb = (uint32_t)__cvta_generic_to_shared(sm);

    // zero both input stages (halos persist); barrier before cp.async writes
    for (int i = t; i < SINW; i += 512) { sm[i] = 0.f; sm[STAGEW + i] = 0.f; }
    __syncthreads();

    auto issue = [&](int c, int s) {
        const uint32_t stb = smb + (uint32_t)(s * STAGEW * 4);
        // weights: 2304 float4
        const float4* ws = (const float4*)(wt + (long)c * WW);
        const uint32_t swu = stb + (uint32_t)(SINW * 4);
        for (int i = t; i < 2304; i += 512)
            asm volatile("cp.async.cg.shared.global [%0], [%1], 16;\n"
                         :: "r"(swu + i * 16), "l"(ws + i));
        // inputs: 2 terms x 12 rows x 128 x 16B, OOB rows zero-filled
#pragma unroll
        for (int e = t; e < 3072; e += 512) {
            int fx  = e & 127;
            int r   = e >> 7;              // 0..23
            int term = r / 12;
            int r2   = r - term * 12;
            int ky = r2 >> 2, yri = r2 & 3;
            int ry = y0 + yri + (ky - 1) * dil;
            int ok = (ry >= 0 && ry < 64);
            uint32_t dst = stb + (uint32_t)((term * TSW + (ky * 4 + yri) * 704 + 96) * 4 + fx * 16);
            const float4* src = (const float4*)(in + ((long)(c * 2 + term) * 4096 +
                                                      (ok ? ry : 0) * 64) * 8) + fx;
            int ssz = ok ? 16 : 0;
            asm volatile("cp.async.cg.shared.global [%0], [%1], 16, %2;\n"
                         :: "r"(dst), "l"(src), "r"(ssz));
        }
        asm volatile("cp.async.commit_group;\n");
    };

    float acc[2][4][4];
#pragma unroll
    for (int mf = 0; mf < 2; mf++)
#pragma unroll
        for (int nt = 0; nt < 4; nt++)
#pragma unroll
            for (int c = 0; c < 4; c++) acc[mf][nt][c] = 0.f;

    issue(0, 0);

    for (int chunk = 0; chunk < nchunk; chunk++) {
        const int s = chunk & 1;
        if (chunk + 1 < nchunk) {
            issue(chunk + 1, s ^ 1);
            asm volatile("cp.async.wait_group 1;\n" ::: "memory");
        } else {
            asm volatile("cp.async.wait_group 0;\n" ::: "memory");
        }
        __syncthreads();

        const uint32_t* sIn = (const uint32_t*)sm + s * STAGEW;
        const uint32_t* sW  = sIn + SINW;

#pragma unroll
        for (int tap = 0; tap < 9; tap++) {
            const int ky = tap / 3, kx = tap % 3;
            const uint32_t* wb = sW + (tap * 64 + mwarp * 32 + g) * 8 + 2 * tq;
            uint2 h0  = *(const uint2*)(wb);
            uint2 h0b = *(const uint2*)(wb + 64);
            uint2 h1  = *(const uint2*)(wb + 128);
            uint2 h1b = *(const uint2*)(wb + 192);
            uint2 l0  = *(const uint2*)(wb + 4608);
            uint2 l0b = *(const uint2*)(wb + 4672);
            uint2 l1  = *(const uint2*)(wb + 4736);
            uint2 l1b = *(const uint2*)(wb + 4800);
            uint32_t aH0[4] = {h0.x, h0b.x, h0.y, h0b.y};
            uint32_t aH1[4] = {h1.x, h1b.x, h1.y, h1b.y};
            uint32_t aL0[4] = {l0.x, l0b.x, l0.y, l0b.y};
            uint32_t aL1[4] = {l1.x, l1b.x, l1.y, l1b.y};
            const int rowoff = (ky * 4 + yr) * 704 +
                               (12 + nh * 32 + g + (kx - 1) * dil) * 8 + 2 * tq;
#pragma unroll
            for (int nt = 0; nt < 4; nt++) {
                uint2 bh = *(const uint2*)(sIn + rowoff + nt * 64);
                uint2 bl = *(const uint2*)(sIn + TSW + rowoff + nt * 64);
                mma16(acc[0][nt], aH0, bh.x, bh.y);
                mma16(acc[0][nt], aL0, bh.x, bh.y);
                mma16(acc[0][nt], aH0, bl.x, bl.y);
                mma16(acc[1][nt], aH1, bh.x, bh.y);
                mma16(acc[1][nt], aL1, bh.x, bh.y);
                mma16(acc[1][nt], aH1, bl.x, bl.y);
            }
        }
        __syncthreads();
    }

    // ---- epilogue: store + BN partials ----
    float s_[2][2] = {{0.f, 0.f}, {0.f, 0.f}};
    float q_[2][2] = {{0.f, 0.f}, {0.f, 0.f}};
    const int ocb = ocg * 64 + mwarp * 32;
#pragma unroll
    for (int mf = 0; mf < 2; mf++) {
        int oc = ocb + mf * 16 + g;
#pragma unroll
        for (int nt = 0; nt < 4; nt++) {
            int gx = (y0 + yr) * 64 + nh * 32 + nt * 8 + 2 * tq;
            float c0 = acc[mf][nt][0], c1 = acc[mf][nt][1];
            float c2 = acc[mf][nt][2], c3 = acc[mf][nt][3];
            out[(long)oc * NPIX + gx]           = c0;
            out[(long)oc * NPIX + gx + 1]       = c1;
            out[(long)(oc + 8) * NPIX + gx]     = c2;
            out[(long)(oc + 8) * NPIX + gx + 1] = c3;
            s_[mf][0] += c0 + c1; q_[mf][0] += c0 * c0 + c1 * c1;
            s_[mf][1] += c2 + c3; q_[mf][1] += c2 * c2 + c3 * c3;
        }
    }
#pragma unroll
    for (int mf = 0; mf < 2; mf++)
#pragma unroll
        for (int ro = 0; ro < 2; ro++) {
            float a = s_[mf][ro], qq = q_[mf][ro];
            a  += __shfl_xor_sync(0xffffffffu, a, 1);
            qq += __shfl_xor_sync(0xffffffffu, qq, 1);
            a  += __shfl_xor_sync(0xffffffffu, a, 2);
            qq += __shfl_xor_sync(0xffffffffu, qq, 2);
            if (tq == 0) {
                sRS[w * 32 + mf * 16 + ro * 8 + g] = a;
                sRQ[w * 32 + mf * 16 + ro * 8 + g] = qq;
            }
        }
    __syncthreads();
    if (t < 64) {
        int mw = t >> 5, cl = t & 31;
        float a = 0.f, qq = 0.f;
#pragma unroll
        for (int j = 0; j < 8; j++) {
            a  += sRS[(mw * 8 + j) * 32 + cl];
            qq += sRQ[(mw * 8 + j) * 32 + cl];
        }
        int slot = b * 16 + ytile;
        p1[slot * Cout + ocg * 64 + t] = a;
        p2[slot * Cout + ocg * 64 + t] = qq;
    }
}

// ---------------- BN finalize ----------------
__global__ void finalize_kernel(const float* __restrict__ p1, const float* __restrict__ p2,
                                const float* __restrict__ g, const float* __restrict__ be,
                                float* __restrict__ A, float* __restrict__ B,
                                int C, int nslots) {
    const int c = blockIdx.x, t = threadIdx.x;
    float s = 0.f, q = 0.f;
    for (int slot = t; slot < nslots; slot += 128) {
        s += p1[slot * C + c];
        q += p2[slot * C + c];
    }
    __shared__ float rs[4], rq[4];
#pragma unroll
    for (int off = 16; off; off >>= 1) {
        s += __shfl_down_sync(0xffffffffu, s, off);
        q += __shfl_down_sync(0xffffffffu, q, off);
    }
    int lane = t & 31, wp = t >> 5;
    if (!lane) { rs[wp] = s; rq[wp] = q; }
    __syncthreads();
    if (t == 0) {
        s = rs[0] + rs[1] + rs[2] + rs[3];
        q = rq[0] + rq[1] + rq[2] + rq[3];
        const float inv = 1.f / (float)(BATCH * NPIX);
        float mean = s * inv;
        float var  = q * inv - mean * mean;
        float a = g[c] * rsqrtf(var + 1e-5f);
        A[c] = a;
        B[c] = be[c] - mean * a;
    }
}

// ---------------- 1x1 conv Cout=64 with input-BN + stats (aspp1, exact fp32) ----------------
__global__ void __launch_bounds__(256) conv1x1_bn_kernel(
    const float* __restrict__ in, const float* __restrict__ w,
    float* __restrict__ out, int Cin,
    const float* __restrict__ Abn, const float* __restrict__ Bbn,
    float* __restrict__ p1, float* __restrict__ p2)
{
    const int p0 = blockIdx.x * 64;
    const int b  = blockIdx.z;
    in  += (long)b * Cin * NPIX;
    out += (long)b * 64  * NPIX;
    const int t = threadIdx.x, tx = t & 15, ty = t >> 4;

    __shared__ float sW [16 * 68];
    __shared__ float sIn[16 * 64];

    float acc[4][4];
#pragma unroll
    for (int r = 0; r < 4; r++)
#pragma unroll
        for (int c = 0; c < 4; c++) acc[r][c] = 0.f;

    for (int ic0 = 0; ic0 < Cin; ic0 += 16) {
        __syncthreads();
        for (int idx = t; idx < 1024; idx += 256) {
            int ic = idx & 15, oc = idx >> 4;
            sW[ic * 68 + oc] = w[(long)oc * Cin + ic0 + ic];
        }
        for (int idx = t; idx < 1024; idx += 256) {
            int ic = idx >> 6, px = idx & 63;
            int c = ic0 + ic;
            float v = in[c * NPIX + p0 + px];
            sIn[idx] = fmaxf(v * Abn[c] + Bbn[c], 0.f);
        }
        __syncthreads();
#pragma unroll
        for (int ic = 0; ic < 16; ic++) {
            float4 a  = *(const float4*)(sW  + ic * 68 + ty * 4);
            float4 xv = *(const float4*)(sIn + ic * 64 + tx * 4);
            float av[4] = {a.x, a.y, a.z, a.w};
            float xa[4] = {xv.x, xv.y, xv.z, xv.w};
#pragma unroll
            for (int r = 0; r < 4; r++)
#pragma unroll
                for (int c = 0; c < 4; c++) acc[r][c] += av[r] * xa[c];
        }
    }
    float sums[4], sqs[4];
#pragma unroll
    for (int r = 0; r < 4; r++) {
        float s = 0.f, q = 0.f;
        float* op = out + (long)(ty * 4 + r) * NPIX + p0 + tx * 4;
#pragma unroll
        for (int c = 0; c < 4; c++) {
            float v = acc[r][c];
            op[c] = v; s += v; q += v * v;
        }
        sums[r] = s; sqs[r] = q;
    }
#pragma unroll
    for (int r = 0; r < 4; r++) {
        float a = sums[r], q = sqs[r];
#pragma unroll
        for (int off = 1; off < 16; off <<= 1) {
            a += __shfl_xor_sync(0xffffffffu, a, off);
            q += __shfl_xor_sync(0xffffffffu, q, off);
        }
        if (tx == 0) {
            int c = ty * 4 + r;
            int slot = b * 64 + blockIdx.x;
            p1[slot * 64 + c] = a;
            p2[slot * 64 + c] = q;
        }
    }
}

// ---------------- fused q/k/v 1x1 projections -> q plain + K'/V fragment layouts ----------------
__global__ void __launch_bounds__(256) qkv_kernel(
    const float* __restrict__ brin,
    const float* __restrict__ wq, const float* __restrict__ bq,
    const float* __restrict__ wk, const float* __restrict__ bk,
    const float* __restrict__ wv, const float* __restrict__ bv,
    float* __restrict__ qo, float* __restrict__ kf, float* __restrict__ vf,
    const float* __restrict__ Abase, const float* __restrict__ Bbase)
{
    const int p0  = blockIdx.x * 64;
    const int img = blockIdx.z;
    const int br  = img >> 2;
    const long ib = (long)img * 64 * NPIX;
    const float* A  = Abase + (2 + br) * 256;
    const float* Bb = Bbase + (2 + br) * 256;
    const int t = threadIdx.x, tx = t & 15, ty = t >> 4;

    float* kfp = kf + (long)img * 524288;
    float* vfp = vf + (long)img * 262144;

    __shared__ float sW [3 * 16 * 64];
    __shared__ float sIn[16 * 64];

    float acc[3][4][4];
#pragma unroll
    for (int m = 0; m < 3; m++)
#pragma unroll
        for (int r = 0; r < 4; r++)
#pragma unroll
            for (int c = 0; c < 4; c++) acc[m][r][c] = 0.f;

    for (int ic0 = 0; ic0 < 64; ic0 += 16) {
        __syncthreads();
        for (int i = t; i < 1024; i += 256) {
            int ic = i >> 6, px = i & 63;
            int c = ic0 + ic;
            float v = brin[ib + (long)c * NPIX + p0 + px];
            sIn[i] = fmaxf(v * A[c] + Bb[c], 0.f);
        }
        for (int i = t; i < 3072; i += 256) {
            int m = i >> 10, r = i & 1023;
            int ic = r & 15, oc = r >> 4;
            const float* wm = (m == 0) ? wq : ((m == 1) ? wk : wv);
            sW[m * 1024 + ic * 64 + oc] = wm[oc * 64 + ic0 + ic];
        }
        __syncthreads();
#pragma unroll
        for (int ic = 0; ic < 16; ic++) {
            float4 xv = *(const float4*)(sIn + ic * 64 + tx * 4);
            float xa[4] = {xv.x, xv.y, xv.z, xv.w};
#pragma unroll
            for (int m = 0; m < 3; m++) {
                float4 a = *(const float4*)(sW + m * 1024 + ic * 64 + ty * 4);
                float av[4] = {a.x, a.y, a.z, a.w};
#pragma unroll
                for (int r = 0; r < 4; r++)
#pragma unroll
                    for (int c = 0; c < 4; c++) acc[m][r][c] += av[r] * xa[c];
            }
        }
    }
    const float* bs[3] = {bq, bk, bv};
#pragma unroll
    for (int m = 0; m < 3; m++) {
#pragma unroll
        for (int r = 0; r < 4; r++) {
            int oc = ty * 4 + r;
            float bb = bs[m][oc];
#pragma unroll
            for (int ci = 0; ci < 4; ci++) {
                int j = p0 + tx * 4 + ci;
                float val = acc[m][r][ci] + bb;
                if (m == 0) {
                    qo[ib + (long)oc * NPIX + j] = val;
                    int kk = 64 + oc, ks = kk >> 3, klo = kk & 7;
                    int slot = (ks >> 1) * 16 + (klo & 3) * 4 + (ks & 1) * 2 + (klo >> 2);
                    kfp[j * 128 + slot] = __uint_as_float(f2tf32(val));
                } else if (m == 1) {
                    int kk = oc, ks = kk >> 3, klo = kk & 7;
                    int slot = (ks >> 1) * 16 + (klo & 3) * 4 + (ks & 1) * 2 + (klo >> 2);
                    kfp[j * 128 + slot] = __uint_as_float(f2tf32(val));
                } else {
                    int ksv = j >> 3, jlo = j & 7;
                    int slot = (jlo & 3) * 4 + (ksv & 1) * 2 + (jlo >> 2);
                    vfp[(oc * 256 + (ksv >> 1)) * 16 + slot] = __uint_as_float(f2tf32(val));
                }
            }
        }
    }
}

// ---------------- pos table ----------------
__global__ void pos_kernel(const float* __restrict__ rh, const float* __restrict__ rw) {
    int idx = blockIdx.x * blockDim.x + threadIdx.x;
    if (idx >= 64 * NPIX) return;
    int d = idx >> 12, n = idx & 4095, a = n >> 6, bb = n & 63;
    g_pos[idx] = rh[d * 64 + bb] + rw[d * 64 + a];
}

// ================= fragment-direct tf32 flash attention (log2-domain scores) =================
#define FLASH3_SMEM (8192 * 4)
#define LOG2E 1.44269504088896f

__global__ void __launch_bounds__(256, 1) flash_mma_kernel(
    const float* __restrict__ qg, const float* __restrict__ kf,
    const float* __restrict__ vf, float* __restrict__ outg)
{
    extern __shared__ uint32_t smu[];
    uint32_t* sP = smu;

    const int i0 = blockIdx.x * 128;
    const int b  = blockIdx.y, br = blockIdx.z;
    const int img = br * BATCH + b;
    const float* q = qg + (long)img * 64 * NPIX;
    const uint4* KF = (const uint4*)(kf + (long)img * 524288);
    const uint4* VF = (const uint4*)(vf + (long)img * 262144);
    float* outp = outg + (long)(b * 256 + br * 64) * NPIX;

    const int t = threadIdx.x;
    const int lane = t & 31, w = t >> 5;
    const int g = lane >> 2, tq = lane & 3;

    uint32_t Qf[16][4];
    {
        int i_r = i0 + w * 16 + g;
#pragma unroll
        for (int ks = 0; ks < 16; ks++) {
            int kc = ks * 8 + tq;
            const float* s0 = (kc < 64)     ? (q + kc * NPIX)       : (g_pos + (kc - 64) * NPIX);
            const float* s1 = (kc + 4 < 64) ? (q + (kc + 4) * NPIX) : (g_pos + (kc - 60) * NPIX);
            Qf[ks][0] = f2tf32(s0[i_r] * LOG2E);
            Qf[ks][1] = f2tf32(s0[i_r + 8] * LOG2E);
            Qf[ks][2] = f2tf32(s1[i_r] * LOG2E);
            Qf[ks][3] = f2tf32(s1[i_r + 8] * LOG2E);
        }
    }

    float Oa[8][4];
#pragma unroll
    for (int nt = 0; nt < 8; nt++)
#pragma unroll
        for (int c = 0; c < 4; c++) Oa[nt][c] = 0.f;
    float m0 = -CUDART_INF_F, m1 = -CUDART_INF_F, l0 = 0.f, l1 = 0.f;

    const int p00 = ((2 * tq) & 3) * 2 + (tq >> 1);
    const int p01 = ((2 * tq + 1) & 3) * 2 + ((2 * tq + 1) >> 2);
    const int pb  = w * 1024 + g * 8;

    for (int j0 = 0; j0 < NPIX; j0 += 64) {
        float Sa[8][4];
#pragma unroll
        for (int nt = 0; nt < 8; nt++)
#pragma unroll
            for (int c = 0; c < 4; c++) Sa[nt][c] = 0.f;
#pragma unroll
        for (int kp = 0; kp < 8; kp++) {
#pragma unroll
            for (int nt = 0; nt < 8; nt++) {
                uint4 kb = KF[(j0 + nt * 8 + g) * 32 + kp * 4 + tq];
                mma8(Sa[nt], Qf[2 * kp],     kb.x, kb.y);
                mma8(Sa[nt], Qf[2 * kp + 1], kb.z, kb.w);
            }
        }

        float mx0 = -CUDART_INF_F, mx1 = -CUDART_INF_F;
#pragma unroll
        for (int nt = 0; nt < 8; nt++) {
            mx0 = fmaxf(mx0, fmaxf(Sa[nt][0], Sa[nt][1]));
            mx1 = fmaxf(mx1, fmaxf(Sa[nt][2], Sa[nt][3]));
        }
        mx0 = fmaxf(mx0, __shfl_xor_sync(0xffffffffu, mx0, 1));
        mx0 = fmaxf(mx0, __shfl_xor_sync(0xffffffffu, mx0, 2));
        mx1 = fmaxf(mx1, __shfl_xor_sync(0xffffffffu, mx1, 1));
        mx1 = fmaxf(mx1, __shfl_xor_sync(0xffffffffu, mx1, 2));
        float mn0 = fmaxf(m0, mx0), mn1 = fmaxf(m1, mx1);
        float al0 = ex2f(m0 - mn0), al1 = ex2f(m1 - mn1);

        float su0 = 0.f, su1 = 0.f;
#pragma unroll
        for (int nt = 0; nt < 8; nt++) {
            float e00 = ex2f(Sa[nt][0] - mn0);
            float e01 = ex2f(Sa[nt][1] - mn0);
            float e10 = ex2f(Sa[nt][2] - mn1);
            float e11 = ex2f(Sa[nt][3] - mn1);
            su0 += e00 + e01; su1 += e10 + e11;
            sP[pb + nt * 128 + p00]      = f2tf32(e00);
            sP[pb + nt * 128 + p01]      = f2tf32(e01);
            sP[pb + nt * 128 + 64 + p00] = f2tf32(e10);
            sP[pb + nt * 128 + 64 + p01] = f2tf32(e11);
        }
        su0 += __shfl_xor_sync(0xffffffffu, su0, 1);
        su0 += __shfl_xor_sync(0xffffffffu, su0, 2);
        su1 += __shfl_xor_sync(0xffffffffu, su1, 1);
        su1 += __shfl_xor_sync(0xffffffffu, su1, 2);
        l0 = l0 * al0 + su0; l1 = l1 * al1 + su1;
        m0 = mn0; m1 = mn1;
#pragma unroll
        for (int nt = 0; nt < 8; nt++) {
            Oa[nt][0] *= al0; Oa[nt][1] *= al0;
            Oa[nt][2] *= al1; Oa[nt][3] *= al1;
        }
        __syncwarp();

#pragma unroll
        for (int kpl = 0; kpl < 4; kpl++) {
            const uint32_t* ape = &sP[w * 1024 + (2 * kpl) * 128 + g * 8 + 2 * tq];
            uint2 e02 = *(const uint2*)ape;
            uint2 e13 = *(const uint2*)(ape + 64);
            uint2 o02 = *(const uint2*)(ape + 128);
            uint2 o13 = *(const uint2*)(ape + 192);
            uint32_t ae[4] = {e02.x, e13.x, e02.y, e13.y};
            uint32_t ao[4] = {o02.x, o13.x, o02.y, o13.y};
#pragma unroll
            for (int nt = 0; nt < 8; nt++) {
                uint4 vb = VF[((nt * 8 + g) * 256 + (j0 >> 4) + kpl) * 4 + tq];
                mma8(Oa[nt], ae, vb.x, vb.y);
                mma8(Oa[nt], ao, vb.z, vb.w);
            }
        }
        __syncwarp();
    }

    float inv0 = 1.f / l0, inv1 = 1.f / l1;
    int pix = i0 + w * 16 + g;
#pragma unroll
    for (int nt = 0; nt < 8; nt++) {
        int d0 = nt * 8 + 2 * tq;
        outp[(long)d0 * NPIX + pix]           = Oa[nt][0] * inv0;
        outp[(long)(d0 + 1) * NPIX + pix]     = Oa[nt][1] * inv0;
        outp[(long)d0 * NPIX + pix + 8]       = Oa[nt][2] * inv1;
        outp[(long)(d0 + 1) * NPIX + pix + 8] = Oa[nt][3] * inv1;
    }
}

// ---------------- host orchestration ----------------
extern "C" void kernel_launch(void* const* d_in, const int* in_sizes, int n_in,
                              void* d_out, int out_size) {
    const float* x      = (const float*)d_in[0];
    const float* dc_w1  = (const float*)d_in[1];
    const float* dc_g1  = (const float*)d_in[3];
    const float* dc_be1 = (const float*)d_in[4];
    const float* dc_w2  = (const float*)d_in[5];
    const float* dc_g2  = (const float*)d_in[7];
    const float* dc_be2 = (const float*)d_in[8];
    const float* aw[4]  = {(const float*)d_in[9],  (const float*)d_in[12],
                           (const float*)d_in[15], (const float*)d_in[18]};
    const float* ag[4]  = {(const float*)d_in[10], (const float*)d_in[13],
                           (const float*)d_in[16], (const float*)d_in[19]};
    const float* ab[4]  = {(const float*)d_in[11], (const float*)d_in[14],
                           (const float*)d_in[17], (const float*)d_in[20]};
    const float* wq = (const float*)d_in[21]; const float* bq = (const float*)d_in[22];
    const float* wk = (const float*)d_in[23]; const float* bk = (const float*)d_in[24];
    const float* wv = (const float*)d_in[25]; const float* bv = (const float*)d_in[26];
    const float* rel_h = (const float*)d_in[27];
    const float* rel_w = (const float*)d_in[28];

    float *buf1, *buf2, *xt0, *xt1, *xt2, *brb, *qb, *kfb, *vfb;
    float *p1, *p2, *An, *Bn, *wt;
    cudaGetSymbolAddress((void**)&buf1, g_buf1);
    cudaGetSymbolAddress((void**)&buf2, g_buf2);
    cudaGetSymbolAddress((void**)&xt0,  g_xt0);
    cudaGetSymbolAddress((void**)&xt1,  g_xt1);
    cudaGetSymbolAddress((void**)&xt2,  g_xt2);
    cudaGetSymbolAddress((void**)&brb,  g_br);
    cudaGetSymbolAddress((void**)&qb,   g_q);
    cudaGetSymbolAddress((void**)&kfb,  g_kf);
    cudaGetSymbolAddress((void**)&vfb,  g_vf);
    cudaGetSymbolAddress((void**)&p1,   g_p1);
    cudaGetSymbolAddress((void**)&p2,   g_p2);
    cudaGetSymbolAddress((void**)&An,   g_An);
    cudaGetSymbolAddress((void**)&Bn,   g_Bn);
    cudaGetSymbolAddress((void**)&wt,   g_wt);

    float* wt1 = wt;                  // conv1: 4 ocg x 8 ch x 9216 = 294912
    float* wt2 = wt + 294912;         // conv2: 4 x 16 x 9216 = 589824
    float* wtA = wt + 884736;         // aspp:  3 x (16 x 9216 = 147456)

    cudaFuncSetAttribute((const void*)conv_mma_kernel<false>,
                         cudaFuncAttributeMaxDynamicSharedMemorySize, CSM);
    cudaFuncSetAttribute((const void*)conv_mma_kernel<true>,
                         cudaFuncAttributeMaxDynamicSharedMemorySize, CSM);
    cudaFuncSetAttribute((const void*)flash_mma_kernel,
                         cudaFuncAttributeMaxDynamicSharedMemorySize, FLASH3_SMEM);

    // weight prep (bf16 hi/lo, fragment-packed)
    wprep_kernel<<<(256 * 64 * 9 + 255) / 256, 256>>>(dc_w1, wt1, 128, 256);
    wprep_kernel<<<(256 * 128 * 9 + 255) / 256, 256>>>(dc_w2, wt2, 256, 256);
    for (int i = 0; i < 3; i++)
        wprep_kernel<<<(64 * 128 * 9 + 255) / 256, 256>>>(
            aw[i + 1], wtA + (long)i * 147456, 256, 64);

    // mpconv: pool->xt0 -> conv1 -> fin1 -> bnprep->xt1 -> conv2 -> fin2 -> bnprep->xt2
    maxpool_xt_kernel<<<(BATCH * 64 * NPIX + 255) / 256, 256>>>(x, xt0);
    conv_mma_kernel<false><<<dim3(16, 4, BATCH), 512, CSM>>>(
        xt0, wt1, buf1, 128, p1, p2);
    finalize_kernel<<<256, 128>>>(p1, p2, dc_g1, dc_be1, An + 0, Bn + 0, 256, 64);
    bnprep_xt_kernel<<<(BATCH * 128 * NPIX + 255) / 256, 256>>>(buf1, xt1, An + 0, Bn + 0);
    conv_mma_kernel<false><<<dim3(16, 4, BATCH), 512, CSM>>>(
        xt1, wt2, buf2, 256, p1, p2);
    finalize_kernel<<<256, 128>>>(p1, p2, dc_g2, dc_be2, An + 256, Bn + 256, 256, 64);
    bnprep_xt_kernel<<<(BATCH * 128 * NPIX + 255) / 256, 256>>>(buf2, xt2, An + 256, Bn + 256);

    // ASPP dilated branches (2,3,4) fused (read xt2); 1x1 branch exact (raw buf2)
    conv_mma_kernel<true><<<dim3(16, 3, BATCH), 512, CSM>>>(
        xt2, wtA, brb + (long)BATCH * 64 * NPIX, 256, p1, p2);
    for (int i = 0; i < 3; i++)
        finalize_kernel<<<64, 128>>>(p1 + i * 8192, p2 + i * 8192, ag[i + 1], ab[i + 1],
                                     An + (3 + i) * 256, Bn + (3 + i) * 256, 64, 64);
    conv1x1_bn_kernel<<<dim3(64, 1, BATCH), 256>>>(
        buf2, aw[0], brb, 256, An + 256, Bn + 256, p1 + 32768, p2 + 32768);
    finalize_kernel<<<64, 128>>>(p1 + 32768, p2 + 32768, ag[0], ab[0],
                                 An + 2 * 256, Bn + 2 * 256, 64, 256);

    // fused qkv -> q plain + K'/V fragment layouts; pos table
    qkv_kernel<<<dim3(64, 1, 16), 256>>>(brb, wq, bq, wk, bk, wv, bv,
                                         qb, kfb, vfb, An, Bn);
    pos_kernel<<<(64 * NPIX + 255) / 256, 256>>>(rel_h, rel_w);

    // fragment-direct flash attention -> concat output
    flash_mma_kernel<<<dim3(32, BATCH, 4), 256, FLASH3_SMEM>>>(
        qb, kfb, vfb, (float*)d_out);
}